// round 1
// baseline (speedup 1.0000x reference)
#include <cuda_runtime.h>
#include <math.h>

// Problem constants
#define NTOK 16384      // B*S
#define BATCH 8
#define SEQ 2048
#define EMB 768
#define FFD 3072
#define NQD 128

// ---------------------------------------------------------------------------
// Scratch (device globals; no allocation allowed)
// ---------------------------------------------------------------------------
__device__ float g_qa[(size_t)NTOK * EMB];          // 50 MB
__device__ float g_scores[(size_t)BATCH * SEQ * SEQ]; // 134 MB
__device__ float g_x1[(size_t)NTOK * EMB];          // 50 MB
__device__ float g_tmp[(size_t)NTOK * EMB];         // 50 MB (attn_out, then ffn_out)
__device__ float g_h[(size_t)NTOK * FFD];           // 201 MB
__device__ float g_qf[(size_t)NTOK * NQD];          // 8 MB

// ---------------------------------------------------------------------------
// Epilogues: 0=none, 1=cos(v+bias), 2=v*scale, 3=relu(v+bias), 4=v+bias
// ---------------------------------------------------------------------------
template <int EPI>
__device__ __forceinline__ float epi_f(float v, const float* __restrict__ bias,
                                       int col, float scale) {
    if (EPI == 1) return cosf(v + bias[col]);
    if (EPI == 2) return v * scale;
    if (EPI == 3) return fmaxf(v + bias[col], 0.0f);
    if (EPI == 4) return v + bias[col];
    return v;
}

// ---------------------------------------------------------------------------
// Tiled SGEMM: C[m,n] = sum_k A[m,k] * (TRANSB ? B[n,k] : B[k,n])
// 128x128 tile, BK=8, 256 threads, 8x8 per-thread microtile.
// lda = K, ldb = (TRANSB ? K : N), ldc = N. M,N multiples of 128; K of 8.
// ---------------------------------------------------------------------------
template <bool TRANSB, int EPI>
__global__ void __launch_bounds__(256) sgemm_kernel(
    const float* __restrict__ A, const float* __restrict__ B,
    float* __restrict__ C, int M, int N, int K,
    size_t sA, size_t sB, size_t sC,
    const float* __restrict__ bias, float scale) {
    __shared__ float As[8][128];
    __shared__ float Bs[8][128];

    A += (size_t)blockIdx.z * sA;
    B += (size_t)blockIdx.z * sB;
    C += (size_t)blockIdx.z * sC;

    const int bm = blockIdx.y * 128;
    const int bn = blockIdx.x * 128;
    const int tid = threadIdx.x;
    const int tx = tid & 15;
    const int ty = tid >> 4;
    // loader mapping for K-contiguous operands: 128 rows x 2 float4 of k
    const int lr = tid >> 1;
    const int lc = (tid & 1) * 4;
    // loader mapping for NN B: 8 k-rows x 32 float4 of n
    const int nk = tid >> 5;
    const int nn = (tid & 31) * 4;

    float acc[8][8];
#pragma unroll
    for (int i = 0; i < 8; i++)
#pragma unroll
        for (int j = 0; j < 8; j++) acc[i][j] = 0.0f;

    for (int k0 = 0; k0 < K; k0 += 8) {
        float4 a = *(const float4*)(A + (size_t)(bm + lr) * K + k0 + lc);
        As[lc + 0][lr] = a.x;
        As[lc + 1][lr] = a.y;
        As[lc + 2][lr] = a.z;
        As[lc + 3][lr] = a.w;
        if (TRANSB) {
            float4 b = *(const float4*)(B + (size_t)(bn + lr) * K + k0 + lc);
            Bs[lc + 0][lr] = b.x;
            Bs[lc + 1][lr] = b.y;
            Bs[lc + 2][lr] = b.z;
            Bs[lc + 3][lr] = b.w;
        } else {
            float4 b = *(const float4*)(B + (size_t)(k0 + nk) * N + bn + nn);
            *(float4*)&Bs[nk][nn] = b;
        }
        __syncthreads();
#pragma unroll
        for (int kk = 0; kk < 8; kk++) {
            float4 a0 = *(const float4*)&As[kk][ty * 4];
            float4 a1 = *(const float4*)&As[kk][64 + ty * 4];
            float4 b0 = *(const float4*)&Bs[kk][tx * 4];
            float4 b1 = *(const float4*)&Bs[kk][64 + tx * 4];
            float ar[8] = {a0.x, a0.y, a0.z, a0.w, a1.x, a1.y, a1.z, a1.w};
            float br[8] = {b0.x, b0.y, b0.z, b0.w, b1.x, b1.y, b1.z, b1.w};
#pragma unroll
            for (int i = 0; i < 8; i++)
#pragma unroll
                for (int j = 0; j < 8; j++)
                    acc[i][j] = fmaf(ar[i], br[j], acc[i][j]);
        }
        __syncthreads();
    }

#pragma unroll
    for (int ig = 0; ig < 2; ig++)
#pragma unroll
        for (int i = 0; i < 4; i++) {
            int row = bm + ig * 64 + ty * 4 + i;
#pragma unroll
            for (int jg = 0; jg < 2; jg++) {
                int col = bn + jg * 64 + tx * 4;
                const float* ac = &acc[ig * 4 + i][jg * 4];
                float4 r;
                r.x = epi_f<EPI>(ac[0], bias, col + 0, scale);
                r.y = epi_f<EPI>(ac[1], bias, col + 1, scale);
                r.z = epi_f<EPI>(ac[2], bias, col + 2, scale);
                r.w = epi_f<EPI>(ac[3], bias, col + 3, scale);
                *(float4*)(C + (size_t)row * N + col) = r;
            }
        }
}

// ---------------------------------------------------------------------------
// Row softmax, row length 2048, one block (256 threads) per row.
// ---------------------------------------------------------------------------
__global__ void __launch_bounds__(256) softmax2048_kernel(float* __restrict__ S) {
    float* p = S + (size_t)blockIdx.x * SEQ;
    const int tid = threadIdx.x;
    __shared__ float sh[8];

    float v[8];
    float m = -1e30f;
#pragma unroll
    for (int i = 0; i < 8; i++) {
        v[i] = p[tid + i * 256];
        m = fmaxf(m, v[i]);
    }
#pragma unroll
    for (int o = 16; o > 0; o >>= 1) m = fmaxf(m, __shfl_xor_sync(~0u, m, o));
    if ((tid & 31) == 0) sh[tid >> 5] = m;
    __syncthreads();
    m = sh[0];
#pragma unroll
    for (int w = 1; w < 8; w++) m = fmaxf(m, sh[w]);

    float s = 0.0f;
#pragma unroll
    for (int i = 0; i < 8; i++) {
        v[i] = __expf(v[i] - m);
        s += v[i];
    }
    __syncthreads();
#pragma unroll
    for (int o = 16; o > 0; o >>= 1) s += __shfl_xor_sync(~0u, s, o);
    if ((tid & 31) == 0) sh[tid >> 5] = s;
    __syncthreads();
    s = 0.0f;
#pragma unroll
    for (int w = 0; w < 8; w++) s += sh[w];
    float inv = 1.0f / s;
#pragma unroll
    for (int i = 0; i < 8; i++) p[tid + i * 256] = v[i] * inv;
}

// ---------------------------------------------------------------------------
// out = LayerNorm(X + Y) * g + b, row length 768, one block per row.
// ---------------------------------------------------------------------------
__global__ void __launch_bounds__(256) add_ln_kernel(
    const float* __restrict__ X, const float* __restrict__ Y,
    const float* __restrict__ g, const float* __restrict__ b,
    float* __restrict__ out) {
    const size_t row = blockIdx.x;
    const float* xp = X + row * EMB;
    const float* yp = Y + row * EMB;
    float* op = out + row * EMB;
    const int tid = threadIdx.x;
    __shared__ float sh[8];

    float v[3];
    float s = 0.0f;
#pragma unroll
    for (int i = 0; i < 3; i++) {
        int c = tid + i * 256;
        v[i] = xp[c] + yp[c];
        s += v[i];
    }
#pragma unroll
    for (int o = 16; o > 0; o >>= 1) s += __shfl_xor_sync(~0u, s, o);
    if ((tid & 31) == 0) sh[tid >> 5] = s;
    __syncthreads();
    s = 0.0f;
#pragma unroll
    for (int w = 0; w < 8; w++) s += sh[w];
    const float mean = s * (1.0f / EMB);

    float q = 0.0f;
#pragma unroll
    for (int i = 0; i < 3; i++) {
        float d = v[i] - mean;
        q += d * d;
    }
    __syncthreads();
#pragma unroll
    for (int o = 16; o > 0; o >>= 1) q += __shfl_xor_sync(~0u, q, o);
    if ((tid & 31) == 0) sh[tid >> 5] = q;
    __syncthreads();
    q = 0.0f;
#pragma unroll
    for (int w = 0; w < 8; w++) q += sh[w];
    const float rs = rsqrtf(q * (1.0f / EMB) + 1e-5f);

#pragma unroll
    for (int i = 0; i < 3; i++) {
        int c = tid + i * 256;
        op[c] = (v[i] - mean) * rs * g[c] + b[c];
    }
}

// ---------------------------------------------------------------------------
// qf[m,q] = cos(x1[m, q] + theta_ry[q]), q < 128
// ---------------------------------------------------------------------------
__global__ void __launch_bounds__(256) qf_kernel(
    const float* __restrict__ x1, const float* __restrict__ th,
    float* __restrict__ qf) {
    int idx = blockIdx.x * 256 + threadIdx.x;
    int m = idx >> 7;
    int q = idx & 127;
    qf[idx] = cosf(x1[(size_t)m * EMB + q] + th[q]);
}

// ---------------------------------------------------------------------------
// Launch
// ---------------------------------------------------------------------------
extern "C" void kernel_launch(void* const* d_in, const int* in_sizes, int n_in,
                              void* d_out, int out_size) {
    const float* x     = (const float*)d_in[0];
    const float* Wp    = (const float*)d_in[1];
    const float* th_rx = (const float*)d_in[2];
    const float* th_ry = (const float*)d_in[3];
    const float* W1    = (const float*)d_in[4];
    const float* b1    = (const float*)d_in[5];
    const float* W2    = (const float*)d_in[6];
    const float* b2    = (const float*)d_in[7];
    const float* ln1g  = (const float*)d_in[8];
    const float* ln1b  = (const float*)d_in[9];
    const float* ln2g  = (const float*)d_in[10];
    const float* ln2b  = (const float*)d_in[11];
    float* out = (float*)d_out;

    float *qa, *sc, *x1, *tmp, *h, *qf;
    cudaGetSymbolAddress((void**)&qa, g_qa);
    cudaGetSymbolAddress((void**)&sc, g_scores);
    cudaGetSymbolAddress((void**)&x1, g_x1);
    cudaGetSymbolAddress((void**)&tmp, g_tmp);
    cudaGetSymbolAddress((void**)&h, g_h);
    cudaGetSymbolAddress((void**)&qf, g_qf);

    dim3 blk(256);

    // 1. proj + cos epilogue: qa = cos(x @ Wp^T + theta_rx)  [16384,768]
    sgemm_kernel<true, 1><<<dim3(EMB / 128, NTOK / 128, 1), blk>>>(
        x, Wp, qa, NTOK, EMB, EMB, 0, 0, 0, th_rx, 0.0f);

    // 2. scores = qa @ qa^T / sqrt(8), batched over 8
    sgemm_kernel<true, 2><<<dim3(SEQ / 128, SEQ / 128, BATCH), blk>>>(
        qa, qa, sc, SEQ, SEQ, EMB,
        (size_t)SEQ * EMB, (size_t)SEQ * EMB, (size_t)SEQ * SEQ,
        nullptr, 0.35355339059327373f);

    // 3. softmax rows
    softmax2048_kernel<<<NTOK, blk>>>(sc);

    // 4. attn_out = P @ qa (NN), batched
    sgemm_kernel<false, 0><<<dim3(EMB / 128, SEQ / 128, BATCH), blk>>>(
        sc, qa, tmp, SEQ, EMB, SEQ,
        (size_t)SEQ * SEQ, (size_t)SEQ * EMB, (size_t)SEQ * EMB,
        nullptr, 0.0f);

    // 5. x1 = LN(x + attn_out)
    add_ln_kernel<<<NTOK, blk>>>(x, tmp, ln1g, ln1b, x1);

    // 6. qf = cos(x1[:, :128] + theta_ry)
    qf_kernel<<<(NTOK * NQD) / 256, blk>>>(x1, th_ry, qf);

    // 7. h = relu(qf @ W1^T + b1)  [16384,3072], K=128
    sgemm_kernel<true, 3><<<dim3(FFD / 128, NTOK / 128, 1), blk>>>(
        qf, W1, h, NTOK, FFD, NQD, 0, 0, 0, b1, 0.0f);

    // 8. ffn_out = h @ W2^T + b2  [16384,768]
    sgemm_kernel<true, 4><<<dim3(EMB / 128, NTOK / 128, 1), blk>>>(
        h, W2, tmp, NTOK, EMB, FFD, 0, 0, 0, b2, 0.0f);

    // 9. out = LN(x1 + ffn_out)
    add_ln_kernel<<<NTOK, blk>>>(x1, tmp, ln2g, ln2b, out);
}

// round 2
// speedup vs baseline: 2.5811x; 2.5811x over previous
#include <cuda_runtime.h>
#include <math.h>

// Problem constants
#define NTOK 16384      // B*S
#define BATCH 8
#define SEQ 2048
#define EMB 768
#define FFD 3072
#define NQD 128

// ---------------------------------------------------------------------------
// Scratch (device globals; no allocation allowed)
// ---------------------------------------------------------------------------
__device__ float g_qa[(size_t)NTOK * EMB];            // 50 MB
__device__ float g_scores[(size_t)BATCH * SEQ * SEQ]; // 134 MB
__device__ float g_x1[(size_t)NTOK * EMB];            // 50 MB
__device__ float g_tmp[(size_t)NTOK * EMB];           // 50 MB
__device__ float g_h[(size_t)NTOK * FFD];             // 201 MB
__device__ float g_qf[(size_t)NTOK * NQD];            // 8 MB

// ---------------------------------------------------------------------------
// Helpers
// ---------------------------------------------------------------------------
__device__ __forceinline__ float tf32r(float f) {
    unsigned r;
    asm("cvt.rna.tf32.f32 %0, %1;" : "=r"(r) : "f"(f));
    return __uint_as_float(r);
}

__device__ __forceinline__ void mma8(float* c, const unsigned* a, const unsigned* b) {
    asm volatile(
        "mma.sync.aligned.m16n8k8.row.col.f32.tf32.tf32.f32 "
        "{%0,%1,%2,%3},{%4,%5,%6,%7},{%8,%9},{%0,%1,%2,%3};"
        : "+f"(c[0]), "+f"(c[1]), "+f"(c[2]), "+f"(c[3])
        : "r"(a[0]), "r"(a[1]), "r"(a[2]), "r"(a[3]), "r"(b[0]), "r"(b[1]));
}

// Epilogues: 0=none, 1=cos(v+bias), 2=v*scale, 3=relu(v+bias), 4=v+bias
template <int EPI>
__device__ __forceinline__ float epi_f(float v, const float* __restrict__ bias,
                                       int col, float scale) {
    if (EPI == 1) return cosf(v + bias[col]);
    if (EPI == 2) return v * scale;
    if (EPI == 3) return fmaxf(v + bias[col], 0.0f);
    if (EPI == 4) return v + bias[col];
    return v;
}

// ---------------------------------------------------------------------------
// TF32 tensor-core GEMM: C[m,n] = sum_k A[m,k] * (TRANSB ? B[n,k] : B[k,n])
// 128x128 CTA tile, BK=16, 256 threads (8 warps, 2x4), warp tile 64x32.
// Fragments are pre-shuffled into smem (mma m16n8k8 thread layout) so the
// consumer side is pure vector LDS. Double-buffered.
// ---------------------------------------------------------------------------
template <bool TRANSB, int EPI>
__global__ void __launch_bounds__(256) tgemm_kernel(
    const float* __restrict__ A, const float* __restrict__ B,
    float* __restrict__ C, int M, int N, int K,
    size_t sA, size_t sB, size_t sC,
    const float* __restrict__ bias, float scale) {
    __shared__ float As[2][2048];  // [buf][(ks*8+mt)*128 + chunk*4 + r]
    __shared__ float Bs[2][2048];  // [buf][(ks*16+nt)*64 + chunk*2 + r]

    A += (size_t)blockIdx.z * sA;
    B += (size_t)blockIdx.z * sB;
    C += (size_t)blockIdx.z * sC;

    const int bm = blockIdx.y * 128;
    const int bn = blockIdx.x * 128;
    const int tid = threadIdx.x;
    const int lane = tid & 31;
    const int wid = tid >> 5;
    const int wm = wid >> 2;  // 0..1
    const int wn = wid & 3;   // 0..3
    const int lda = K;
    const int ldb = TRANSB ? K : N;

    float acc[4][4][4] = {};
    float4 ra[2], rb[2];

    const int niter = K >> 4;

    auto ldgA = [&](int it) {
#pragma unroll
        for (int u = 0; u < 2; ++u) {
            int idx = u * 256 + tid;
            int row = idx >> 2, c = idx & 3;
            ra[u] = *(const float4*)(A + (size_t)(bm + row) * lda + it * 16 + c * 4);
        }
    };
    auto ldgB = [&](int it) {
#pragma unroll
        for (int u = 0; u < 2; ++u) {
            int idx = u * 256 + tid;
            if (TRANSB) {
                int row = idx >> 2, c = idx & 3;
                rb[u] = *(const float4*)(B + (size_t)(bn + row) * ldb + it * 16 + c * 4);
            } else {
                int kr = idx >> 5, nc = (idx & 31) * 4;
                rb[u] = *(const float4*)(B + (size_t)(it * 16 + kr) * ldb + bn + nc);
            }
        }
    };
    auto stsA = [&](int buf) {
#pragma unroll
        for (int u = 0; u < 2; ++u) {
            int idx = u * 256 + tid;
            int row = idx >> 2, c = idx & 3;
            int mt = row >> 4, rb3 = (row >> 3) & 1, r7 = row & 7;
            float v[4] = {ra[u].x, ra[u].y, ra[u].z, ra[u].w};
#pragma unroll
            for (int j = 0; j < 4; ++j) {
                int ks = c >> 1;
                int t = (r7 << 2) | j;
                int r = ((c & 1) << 1) | rb3;
                int off = ((ks * 8 + mt) * 32 + (t ^ (t >> 3))) * 4 + r;
                As[buf][off] = tf32r(v[j]);
            }
        }
    };
    auto stsB = [&](int buf) {
#pragma unroll
        for (int u = 0; u < 2; ++u) {
            int idx = u * 256 + tid;
            float v[4] = {rb[u].x, rb[u].y, rb[u].z, rb[u].w};
            if (TRANSB) {
                int row = idx >> 2, c = idx & 3;
                int nt = row >> 3, r7 = row & 7;
#pragma unroll
                for (int j = 0; j < 4; ++j) {
                    int ks = c >> 1;
                    int t = (r7 << 2) | j;
                    int r = c & 1;
                    int off = ((ks * 16 + nt) * 32 + (t ^ (t >> 3) ^ (nt & 3))) * 2 + r;
                    Bs[buf][off] = tf32r(v[j]);
                }
            } else {
                int kr = idx >> 5, nc = (idx & 31) * 4;
                int ks = kr >> 3, krm = kr & 7;
#pragma unroll
                for (int j = 0; j < 4; ++j) {
                    int n = nc + j;
                    int nt = n >> 3;
                    int t = ((n & 7) << 2) | (krm & 3);
                    int r = krm >> 2;
                    int off = ((ks * 16 + nt) * 32 + (t ^ (t >> 3) ^ (nt & 3))) * 2 + r;
                    Bs[buf][off] = tf32r(v[j]);
                }
            }
        }
    };
    auto compute = [&](int buf) {
        const int physA = lane ^ (lane >> 3);
#pragma unroll
        for (int ks = 0; ks < 2; ++ks) {
            unsigned af[4][4];
            unsigned bf[4][2];
#pragma unroll
            for (int mi = 0; mi < 4; ++mi) {
                int mtg = wm * 4 + mi;
                float4 t = *(const float4*)&As[buf][((ks * 8 + mtg) * 32 + physA) * 4];
                af[mi][0] = __float_as_uint(t.x);
                af[mi][1] = __float_as_uint(t.y);
                af[mi][2] = __float_as_uint(t.z);
                af[mi][3] = __float_as_uint(t.w);
            }
#pragma unroll
            for (int ni = 0; ni < 4; ++ni) {
                int ntg = wn * 4 + ni;
                int physB = lane ^ (lane >> 3) ^ (ntg & 3);
                float2 t = *(const float2*)&Bs[buf][((ks * 16 + ntg) * 32 + physB) * 2];
                bf[ni][0] = __float_as_uint(t.x);
                bf[ni][1] = __float_as_uint(t.y);
            }
#pragma unroll
            for (int mi = 0; mi < 4; ++mi)
#pragma unroll
                for (int ni = 0; ni < 4; ++ni)
                    mma8(acc[mi][ni], af[mi], bf[ni]);
        }
    };

    ldgA(0);
    ldgB(0);
    stsA(0);
    stsB(0);
    __syncthreads();

    for (int it = 0; it < niter; ++it) {
        int cur = it & 1;
        bool more = (it + 1) < niter;
        if (more) {
            ldgA(it + 1);
            ldgB(it + 1);
        }
        compute(cur);
        if (more) {
            stsA(cur ^ 1);
            stsB(cur ^ 1);
        }
        __syncthreads();
    }

    // Epilogue: c0,c1 -> (row, col..col+1); c2,c3 -> (row+8, col..col+1)
    const int g = lane >> 2;
    const int tg = lane & 3;
#pragma unroll
    for (int mi = 0; mi < 4; ++mi) {
        int row = bm + wm * 64 + mi * 16 + g;
#pragma unroll
        for (int ni = 0; ni < 4; ++ni) {
            int col = bn + wn * 32 + ni * 8 + tg * 2;
            const float* a = acc[mi][ni];
            float2 lo, hi;
            lo.x = epi_f<EPI>(a[0], bias, col + 0, scale);
            lo.y = epi_f<EPI>(a[1], bias, col + 1, scale);
            hi.x = epi_f<EPI>(a[2], bias, col + 0, scale);
            hi.y = epi_f<EPI>(a[3], bias, col + 1, scale);
            *(float2*)(C + (size_t)row * N + col) = lo;
            *(float2*)(C + (size_t)(row + 8) * N + col) = hi;
        }
    }
}

// ---------------------------------------------------------------------------
// Row softmax, row length 2048, one block (256 threads) per row.
// ---------------------------------------------------------------------------
__global__ void __launch_bounds__(256) softmax2048_kernel(float* __restrict__ S) {
    float* p = S + (size_t)blockIdx.x * SEQ;
    const int tid = threadIdx.x;
    __shared__ float sh[8];

    float v[8];
    float m = -1e30f;
#pragma unroll
    for (int i = 0; i < 8; i++) {
        v[i] = p[tid + i * 256];
        m = fmaxf(m, v[i]);
    }
#pragma unroll
    for (int o = 16; o > 0; o >>= 1) m = fmaxf(m, __shfl_xor_sync(~0u, m, o));
    if ((tid & 31) == 0) sh[tid >> 5] = m;
    __syncthreads();
    m = sh[0];
#pragma unroll
    for (int w = 1; w < 8; w++) m = fmaxf(m, sh[w]);

    float s = 0.0f;
#pragma unroll
    for (int i = 0; i < 8; i++) {
        v[i] = __expf(v[i] - m);
        s += v[i];
    }
    __syncthreads();
#pragma unroll
    for (int o = 16; o > 0; o >>= 1) s += __shfl_xor_sync(~0u, s, o);
    if ((tid & 31) == 0) sh[tid >> 5] = s;
    __syncthreads();
    s = 0.0f;
#pragma unroll
    for (int w = 0; w < 8; w++) s += sh[w];
    float inv = 1.0f / s;
#pragma unroll
    for (int i = 0; i < 8; i++) p[tid + i * 256] = v[i] * inv;
}

// ---------------------------------------------------------------------------
// out = LayerNorm(X + Y) * g + b, row length 768, one block per row.
// ---------------------------------------------------------------------------
__global__ void __launch_bounds__(256) add_ln_kernel(
    const float* __restrict__ X, const float* __restrict__ Y,
    const float* __restrict__ g, const float* __restrict__ b,
    float* __restrict__ out) {
    const size_t row = blockIdx.x;
    const float* xp = X + row * EMB;
    const float* yp = Y + row * EMB;
    float* op = out + row * EMB;
    const int tid = threadIdx.x;
    __shared__ float sh[8];

    float v[3];
    float s = 0.0f;
#pragma unroll
    for (int i = 0; i < 3; i++) {
        int c = tid + i * 256;
        v[i] = xp[c] + yp[c];
        s += v[i];
    }
#pragma unroll
    for (int o = 16; o > 0; o >>= 1) s += __shfl_xor_sync(~0u, s, o);
    if ((tid & 31) == 0) sh[tid >> 5] = s;
    __syncthreads();
    s = 0.0f;
#pragma unroll
    for (int w = 0; w < 8; w++) s += sh[w];
    const float mean = s * (1.0f / EMB);

    float q = 0.0f;
#pragma unroll
    for (int i = 0; i < 3; i++) {
        float d = v[i] - mean;
        q += d * d;
    }
    __syncthreads();
#pragma unroll
    for (int o = 16; o > 0; o >>= 1) q += __shfl_xor_sync(~0u, q, o);
    if ((tid & 31) == 0) sh[tid >> 5] = q;
    __syncthreads();
    q = 0.0f;
#pragma unroll
    for (int w = 0; w < 8; w++) q += sh[w];
    const float rs = rsqrtf(q * (1.0f / EMB) + 1e-5f);

#pragma unroll
    for (int i = 0; i < 3; i++) {
        int c = tid + i * 256;
        op[c] = (v[i] - mean) * rs * g[c] + b[c];
    }
}

// ---------------------------------------------------------------------------
// qf[m,q] = cos(x1[m, q] + theta_ry[q]), q < 128
// ---------------------------------------------------------------------------
__global__ void __launch_bounds__(256) qf_kernel(
    const float* __restrict__ x1, const float* __restrict__ th,
    float* __restrict__ qf) {
    int idx = blockIdx.x * 256 + threadIdx.x;
    int m = idx >> 7;
    int q = idx & 127;
    qf[idx] = cosf(x1[(size_t)m * EMB + q] + th[q]);
}

// ---------------------------------------------------------------------------
// Launch
// ---------------------------------------------------------------------------
extern "C" void kernel_launch(void* const* d_in, const int* in_sizes, int n_in,
                              void* d_out, int out_size) {
    const float* x     = (const float*)d_in[0];
    const float* Wp    = (const float*)d_in[1];
    const float* th_rx = (const float*)d_in[2];
    const float* th_ry = (const float*)d_in[3];
    const float* W1    = (const float*)d_in[4];
    const float* b1    = (const float*)d_in[5];
    const float* W2    = (const float*)d_in[6];
    const float* b2    = (const float*)d_in[7];
    const float* ln1g  = (const float*)d_in[8];
    const float* ln1b  = (const float*)d_in[9];
    const float* ln2g  = (const float*)d_in[10];
    const float* ln2b  = (const float*)d_in[11];
    float* out = (float*)d_out;

    float *qa, *sc, *x1, *tmp, *h, *qf;
    cudaGetSymbolAddress((void**)&qa, g_qa);
    cudaGetSymbolAddress((void**)&sc, g_scores);
    cudaGetSymbolAddress((void**)&x1, g_x1);
    cudaGetSymbolAddress((void**)&tmp, g_tmp);
    cudaGetSymbolAddress((void**)&h, g_h);
    cudaGetSymbolAddress((void**)&qf, g_qf);

    dim3 blk(256);

    // 1. qa = cos(x @ Wp^T + theta_rx)  [16384,768]
    tgemm_kernel<true, 1><<<dim3(EMB / 128, NTOK / 128, 1), blk>>>(
        x, Wp, qa, NTOK, EMB, EMB, 0, 0, 0, th_rx, 0.0f);

    // 2. scores = qa @ qa^T / sqrt(8), batched over 8
    tgemm_kernel<true, 2><<<dim3(SEQ / 128, SEQ / 128, BATCH), blk>>>(
        qa, qa, sc, SEQ, SEQ, EMB,
        (size_t)SEQ * EMB, (size_t)SEQ * EMB, (size_t)SEQ * SEQ,
        nullptr, 0.35355339059327373f);

    // 3. softmax rows
    softmax2048_kernel<<<NTOK, blk>>>(sc);

    // 4. attn_out = P @ qa (NN), batched
    tgemm_kernel<false, 0><<<dim3(EMB / 128, SEQ / 128, BATCH), blk>>>(
        sc, qa, tmp, SEQ, EMB, SEQ,
        (size_t)SEQ * SEQ, (size_t)SEQ * EMB, (size_t)SEQ * EMB,
        nullptr, 0.0f);

    // 5. x1 = LN(x + attn_out)
    add_ln_kernel<<<NTOK, blk>>>(x, tmp, ln1g, ln1b, x1);

    // 6. qf = cos(x1[:, :128] + theta_ry)
    qf_kernel<<<(NTOK * NQD) / 256, blk>>>(x1, th_ry, qf);

    // 7. h = relu(qf @ W1^T + b1)  [16384,3072], K=128
    tgemm_kernel<true, 3><<<dim3(FFD / 128, NTOK / 128, 1), blk>>>(
        qf, W1, h, NTOK, FFD, NQD, 0, 0, 0, b1, 0.0f);

    // 8. ffn_out = h @ W2^T + b2  [16384,768]
    tgemm_kernel<true, 4><<<dim3(EMB / 128, NTOK / 128, 1), blk>>>(
        h, W2, tmp, NTOK, EMB, FFD, 0, 0, 0, b2, 0.0f);

    // 9. out = LN(x1 + ffn_out)
    add_ln_kernel<<<NTOK, blk>>>(x1, tmp, ln2g, ln2b, out);
}

// round 4
// speedup vs baseline: 3.1349x; 1.2145x over previous
#include <cuda_runtime.h>
#include <cstdint>
#include <math.h>

// Problem constants
#define NTOK 16384      // B*S
#define BATCH 8
#define SEQ 2048
#define EMB 768
#define FFD 3072
#define NQD 128

// ---------------------------------------------------------------------------
// Scratch (device globals; no allocation allowed)
// ---------------------------------------------------------------------------
__device__ float g_qa[(size_t)NTOK * EMB];
__device__ float g_qaT[(size_t)NTOK * EMB];           // per-batch transposed qa
__device__ float g_scores[(size_t)BATCH * SEQ * SEQ];
__device__ float g_x1[(size_t)NTOK * EMB];
__device__ float g_tmp[(size_t)NTOK * EMB];
__device__ float g_h[(size_t)NTOK * FFD];
__device__ float g_qf[(size_t)NTOK * NQD];

// ---------------------------------------------------------------------------
// Helpers
// ---------------------------------------------------------------------------
__device__ __forceinline__ float tf32r(float f) {
    unsigned r;
    asm("cvt.rna.tf32.f32 %0, %1;" : "=r"(r) : "f"(f));
    return __uint_as_float(r);
}

__device__ __forceinline__ void mma8(float* c, const unsigned* a, const unsigned* b) {
    asm volatile(
        "mma.sync.aligned.m16n8k8.row.col.f32.tf32.tf32.f32 "
        "{%0,%1,%2,%3},{%4,%5,%6,%7},{%8,%9},{%0,%1,%2,%3};"
        : "+f"(c[0]), "+f"(c[1]), "+f"(c[2]), "+f"(c[3])
        : "r"(a[0]), "r"(a[1]), "r"(a[2]), "r"(a[3]), "r"(b[0]), "r"(b[1]));
}

// Epilogues: 0=none, 1=cos(v+bias), 2=v*scale, 3=relu(v+bias), 4=v+bias
template <int EPI>
__device__ __forceinline__ float epi_f(float v, const float* __restrict__ bias,
                                       int col, float scale) {
    if (EPI == 1) return __cosf(v + bias[col]);
    if (EPI == 2) return v * scale;
    if (EPI == 3) return fmaxf(v + bias[col], 0.0f);
    if (EPI == 4) return v + bias[col];
    return v;
}

// ---------------------------------------------------------------------------
// TF32 tensor-core GEMM: C[m,n] = sum_k A[m,k] * B[n,k]  (both K-major)
// CTA tile 128x256, BK=16, 256 threads (8 warps, 2x4), warp tile 64x64.
// Fragments pre-shuffled into smem (mma m16n8k8 thread layout); consumer is
// pure vector LDS. Double-buffered.
// ---------------------------------------------------------------------------
template <int EPI>
__global__ void __launch_bounds__(256, 1) tgemm_kernel(
    const float* __restrict__ A, const float* __restrict__ B,
    float* __restrict__ C, int M, int N, int K,
    size_t sA, size_t sB, size_t sC,
    const float* __restrict__ bias, float scale) {
    __shared__ float As[2][2048];  // [buf][((ks*8+mt)*32 + lane_swz)*4 + r]
    __shared__ float Bs[2][4096];  // [buf][((ks*32+nt)*32 + lane_swz)*2 + r]

    A += (size_t)blockIdx.z * sA;
    B += (size_t)blockIdx.z * sB;
    C += (size_t)blockIdx.z * sC;

    const int bm = blockIdx.y * 128;
    const int bn = blockIdx.x * 256;
    const int tid = threadIdx.x;
    const int lane = tid & 31;
    const int wid = tid >> 5;
    const int wm = wid >> 2;  // 0..1 (64 rows each)
    const int wn = wid & 3;   // 0..3 (64 cols each)

    float acc[4][8][4] = {};
    float4 ra[2], rb[4];

    const int niter = K >> 4;

    auto ldgA = [&](int it) {
#pragma unroll
        for (int u = 0; u < 2; ++u) {
            int idx = u * 256 + tid;
            int row = idx >> 2, c = idx & 3;
            ra[u] = *(const float4*)(A + (size_t)(bm + row) * K + it * 16 + c * 4);
        }
    };
    auto ldgB = [&](int it) {
#pragma unroll
        for (int u = 0; u < 4; ++u) {
            int idx = u * 256 + tid;
            int row = idx >> 2, c = idx & 3;
            rb[u] = *(const float4*)(B + (size_t)(bn + row) * K + it * 16 + c * 4);
        }
    };
    auto stsA = [&](int buf) {
#pragma unroll
        for (int u = 0; u < 2; ++u) {
            int idx = u * 256 + tid;
            int row = idx >> 2, c = idx & 3;
            int mt = row >> 4, rb3 = (row >> 3) & 1, r7 = row & 7;
            float v[4] = {ra[u].x, ra[u].y, ra[u].z, ra[u].w};
#pragma unroll
            for (int j = 0; j < 4; ++j) {
                int ks = c >> 1;
                int t = (r7 << 2) | j;
                int r = ((c & 1) << 1) | rb3;
                int off = ((ks * 8 + mt) * 32 + (t ^ (t >> 3))) * 4 + r;
                As[buf][off] = tf32r(v[j]);
            }
        }
    };
    auto stsB = [&](int buf) {
#pragma unroll
        for (int u = 0; u < 4; ++u) {
            int idx = u * 256 + tid;
            int row = idx >> 2, c = idx & 3;
            int nt = row >> 3, r7 = row & 7;
            float v[4] = {rb[u].x, rb[u].y, rb[u].z, rb[u].w};
#pragma unroll
            for (int j = 0; j < 4; ++j) {
                int ks = c >> 1;
                int t = (r7 << 2) | j;
                int r = c & 1;
                int off = ((ks * 32 + nt) * 32 + (t ^ (t >> 3) ^ (nt & 3))) * 2 + r;
                Bs[buf][off] = tf32r(v[j]);
            }
        }
    };
    auto compute = [&](int buf) {
        const int physA = lane ^ (lane >> 3);
#pragma unroll
        for (int ks = 0; ks < 2; ++ks) {
            unsigned af[4][4];
            unsigned bf[8][2];
#pragma unroll
            for (int mi = 0; mi < 4; ++mi) {
                int mtg = wm * 4 + mi;
                float4 t = *(const float4*)&As[buf][((ks * 8 + mtg) * 32 + physA) * 4];
                af[mi][0] = __float_as_uint(t.x);
                af[mi][1] = __float_as_uint(t.y);
                af[mi][2] = __float_as_uint(t.z);
                af[mi][3] = __float_as_uint(t.w);
            }
#pragma unroll
            for (int ni = 0; ni < 8; ++ni) {
                int ntg = wn * 8 + ni;
                int physB = lane ^ (lane >> 3) ^ (ntg & 3);
                float2 t = *(const float2*)&Bs[buf][((ks * 32 + ntg) * 32 + physB) * 2];
                bf[ni][0] = __float_as_uint(t.x);
                bf[ni][1] = __float_as_uint(t.y);
            }
#pragma unroll
            for (int mi = 0; mi < 4; ++mi)
#pragma unroll
                for (int ni = 0; ni < 8; ++ni)
                    mma8(acc[mi][ni], af[mi], bf[ni]);
        }
    };

    ldgA(0);
    ldgB(0);
    stsA(0);
    stsB(0);
    __syncthreads();

    for (int it = 0; it < niter; ++it) {
        int cur = it & 1;
        bool more = (it + 1) < niter;
        if (more) {
            ldgA(it + 1);
            ldgB(it + 1);
        }
        compute(cur);
        if (more) {
            stsA(cur ^ 1);
            stsB(cur ^ 1);
        }
        __syncthreads();
    }

    // Epilogue: c0,c1 -> (row, col..col+1); c2,c3 -> (row+8, col..col+1)
    const int g = lane >> 2;
    const int tg = lane & 3;
#pragma unroll
    for (int mi = 0; mi < 4; ++mi) {
        int row = bm + wm * 64 + mi * 16 + g;
#pragma unroll
        for (int ni = 0; ni < 8; ++ni) {
            int col = bn + wn * 64 + ni * 8 + tg * 2;
            const float* a = acc[mi][ni];
            float2 lo, hi;
            lo.x = epi_f<EPI>(a[0], bias, col + 0, scale);
            lo.y = epi_f<EPI>(a[1], bias, col + 1, scale);
            hi.x = epi_f<EPI>(a[2], bias, col + 0, scale);
            hi.y = epi_f<EPI>(a[3], bias, col + 1, scale);
            *(float2*)(C + (size_t)row * N + col) = lo;
            *(float2*)(C + (size_t)(row + 8) * N + col) = hi;
        }
    }
}

// ---------------------------------------------------------------------------
// 32x32 tiled transpose per batch: out[b][e][t] = in[b][t][e]
// ---------------------------------------------------------------------------
__global__ void __launch_bounds__(256) transpose_kernel(
    const float* __restrict__ in, float* __restrict__ out) {
    __shared__ float t[32][33];
    const int b = blockIdx.z;
    const int t0 = blockIdx.x * 32;
    const int e0 = blockIdx.y * 32;
    const int lx = threadIdx.x & 31, ly = threadIdx.x >> 5;
#pragma unroll
    for (int r = 0; r < 32; r += 8)
        t[ly + r][lx] = in[((size_t)b * SEQ + t0 + ly + r) * EMB + e0 + lx];
    __syncthreads();
#pragma unroll
    for (int r = 0; r < 32; r += 8)
        out[((size_t)b * EMB + e0 + ly + r) * SEQ + t0 + lx] = t[lx][ly + r];
}

// ---------------------------------------------------------------------------
// Row softmax, row length 2048, one block (256 threads) per row.
// ---------------------------------------------------------------------------
__global__ void __launch_bounds__(256) softmax2048_kernel(float* __restrict__ S) {
    float* p = S + (size_t)blockIdx.x * SEQ;
    const int tid = threadIdx.x;
    __shared__ float sh[8];

    float v[8];
    float m = -1e30f;
#pragma unroll
    for (int i = 0; i < 8; i++) {
        v[i] = p[tid + i * 256];
        m = fmaxf(m, v[i]);
    }
#pragma unroll
    for (int o = 16; o > 0; o >>= 1) m = fmaxf(m, __shfl_xor_sync(~0u, m, o));
    if ((tid & 31) == 0) sh[tid >> 5] = m;
    __syncthreads();
    m = sh[0];
#pragma unroll
    for (int w = 1; w < 8; w++) m = fmaxf(m, sh[w]);

    float s = 0.0f;
#pragma unroll
    for (int i = 0; i < 8; i++) {
        v[i] = __expf(v[i] - m);
        s += v[i];
    }
    __syncthreads();
#pragma unroll
    for (int o = 16; o > 0; o >>= 1) s += __shfl_xor_sync(~0u, s, o);
    if ((tid & 31) == 0) sh[tid >> 5] = s;
    __syncthreads();
    s = 0.0f;
#pragma unroll
    for (int w = 0; w < 8; w++) s += sh[w];
    float inv = 1.0f / s;
#pragma unroll
    for (int i = 0; i < 8; i++) p[tid + i * 256] = v[i] * inv;
}

// ---------------------------------------------------------------------------
// out = LayerNorm(X + Y) * g + b, row length 768, one block per row.
// ---------------------------------------------------------------------------
__global__ void __launch_bounds__(256) add_ln_kernel(
    const float* __restrict__ X, const float* __restrict__ Y,
    const float* __restrict__ g, const float* __restrict__ b,
    float* __restrict__ out) {
    const size_t row = blockIdx.x;
    const float* xp = X + row * EMB;
    const float* yp = Y + row * EMB;
    float* op = out + row * EMB;
    const int tid = threadIdx.x;
    __shared__ float sh[8];

    float v[3];
    float s = 0.0f;
#pragma unroll
    for (int i = 0; i < 3; i++) {
        int c = tid + i * 256;
        v[i] = xp[c] + yp[c];
        s += v[i];
    }
#pragma unroll
    for (int o = 16; o > 0; o >>= 1) s += __shfl_xor_sync(~0u, s, o);
    if ((tid & 31) == 0) sh[tid >> 5] = s;
    __syncthreads();
    s = 0.0f;
#pragma unroll
    for (int w = 0; w < 8; w++) s += sh[w];
    const float mean = s * (1.0f / EMB);

    float q = 0.0f;
#pragma unroll
    for (int i = 0; i < 3; i++) {
        float d = v[i] - mean;
        q += d * d;
    }
    __syncthreads();
#pragma unroll
    for (int o = 16; o > 0; o >>= 1) q += __shfl_xor_sync(~0u, q, o);
    if ((tid & 31) == 0) sh[tid >> 5] = q;
    __syncthreads();
    q = 0.0f;
#pragma unroll
    for (int w = 0; w < 8; w++) q += sh[w];
    const float rs = rsqrtf(q * (1.0f / EMB) + 1e-5f);

#pragma unroll
    for (int i = 0; i < 3; i++) {
        int c = tid + i * 256;
        op[c] = (v[i] - mean) * rs * g[c] + b[c];
    }
}

// ---------------------------------------------------------------------------
// qf[m,q] = cos(x1[m, q] + theta_ry[q]), q < 128
// ---------------------------------------------------------------------------
__global__ void __launch_bounds__(256) qf_kernel(
    const float* __restrict__ x1, const float* __restrict__ th,
    float* __restrict__ qf) {
    int idx = blockIdx.x * 256 + threadIdx.x;
    int m = idx >> 7;
    int q = idx & 127;
    qf[idx] = __cosf(x1[(size_t)m * EMB + q] + th[q]);
}

// ---------------------------------------------------------------------------
// Launch
// ---------------------------------------------------------------------------
extern "C" void kernel_launch(void* const* d_in, const int* in_sizes, int n_in,
                              void* d_out, int out_size) {
    const float* x     = (const float*)d_in[0];
    const float* Wp    = (const float*)d_in[1];
    const float* th_rx = (const float*)d_in[2];
    const float* th_ry = (const float*)d_in[3];
    const float* W1    = (const float*)d_in[4];
    const float* b1    = (const float*)d_in[5];
    const float* W2    = (const float*)d_in[6];
    const float* b2    = (const float*)d_in[7];
    const float* ln1g  = (const float*)d_in[8];
    const float* ln1b  = (const float*)d_in[9];
    const float* ln2g  = (const float*)d_in[10];
    const float* ln2b  = (const float*)d_in[11];
    float* out = (float*)d_out;

    float *qa, *qaT, *sc, *x1, *tmp, *h, *qf;
    cudaGetSymbolAddress((void**)&qa, g_qa);
    cudaGetSymbolAddress((void**)&qaT, g_qaT);
    cudaGetSymbolAddress((void**)&sc, g_scores);
    cudaGetSymbolAddress((void**)&x1, g_x1);
    cudaGetSymbolAddress((void**)&tmp, g_tmp);
    cudaGetSymbolAddress((void**)&h, g_h);
    cudaGetSymbolAddress((void**)&qf, g_qf);

    dim3 blk(256);

    // 1. qa = cos(x @ Wp^T + theta_rx)  [16384,768]
    tgemm_kernel<1><<<dim3(EMB / 256, NTOK / 128, 1), blk>>>(
        x, Wp, qa, NTOK, EMB, EMB, 0, 0, 0, th_rx, 0.0f);

    // 1b. qaT[b][e][t] = qa[b][t][e]
    transpose_kernel<<<dim3(SEQ / 32, EMB / 32, BATCH), blk>>>(qa, qaT);

    // 2. scores = qa @ qa^T / sqrt(8), batched over 8
    tgemm_kernel<2><<<dim3(SEQ / 256, SEQ / 128, BATCH), blk>>>(
        qa, qa, sc, SEQ, SEQ, EMB,
        (size_t)SEQ * EMB, (size_t)SEQ * EMB, (size_t)SEQ * SEQ,
        nullptr, 0.35355339059327373f);

    // 3. softmax rows
    softmax2048_kernel<<<NTOK, blk>>>(sc);

    // 4. attn_out = P @ qa == P @ (qaT)^T, batched
    tgemm_kernel<0><<<dim3(EMB / 256, SEQ / 128, BATCH), blk>>>(
        sc, qaT, tmp, SEQ, EMB, SEQ,
        (size_t)SEQ * SEQ, (size_t)EMB * SEQ, (size_t)SEQ * EMB,
        nullptr, 0.0f);

    // 5. x1 = LN(x + attn_out)
    add_ln_kernel<<<NTOK, blk>>>(x, tmp, ln1g, ln1b, x1);

    // 6. qf = cos(x1[:, :128] + theta_ry)
    qf_kernel<<<(NTOK * NQD) / 256, blk>>>(x1, th_ry, qf);

    // 7. h = relu(qf @ W1^T + b1)  [16384,3072], K=128
    tgemm_kernel<3><<<dim3(FFD / 256, NTOK / 128, 1), blk>>>(
        qf, W1, h, NTOK, FFD, NQD, 0, 0, 0, b1, 0.0f);

    // 8. ffn_out = h @ W2^T + b2  [16384,768]
    tgemm_kernel<4><<<dim3(EMB / 256, NTOK / 128, 1), blk>>>(
        h, W2, tmp, NTOK, EMB, FFD, 0, 0, 0, b2, 0.0f);

    // 9. out = LN(x1 + ffn_out)
    add_ln_kernel<<<NTOK, blk>>>(x1, tmp, ln2g, ln2b, out);
}

// round 5
// speedup vs baseline: 3.4244x; 1.0923x over previous
#include <cuda_runtime.h>
#include <cuda_bf16.h>
#include <cstdint>
#include <math.h>

// Problem constants
#define NTOK 16384      // B*S
#define BATCH 8
#define SEQ 2048
#define EMB 768
#define FFD 3072
#define NQD 128

// ---------------------------------------------------------------------------
// Scratch (device globals; no allocation allowed)
// ---------------------------------------------------------------------------
__device__ float g_qa[(size_t)NTOK * EMB];
__device__ float g_qaT[(size_t)NTOK * EMB];           // per-batch transposed qa
__device__ float g_scores[(size_t)BATCH * SEQ * SEQ];
__device__ float g_x1[(size_t)NTOK * EMB];
__device__ float g_tmp[(size_t)NTOK * EMB];
__device__ float g_h[(size_t)NTOK * FFD];
__device__ float g_qf[(size_t)NTOK * NQD];

// ---------------------------------------------------------------------------
// Helpers
// ---------------------------------------------------------------------------
__device__ __forceinline__ float tf32r(float f) {
    unsigned r;
    asm("cvt.rna.tf32.f32 %0, %1;" : "=r"(r) : "f"(f));
    return __uint_as_float(r);
}

__device__ __forceinline__ unsigned bf2(float x, float y) {
    __nv_bfloat162 t = __float22bfloat162_rn(make_float2(x, y));
    return *(unsigned*)&t;
}

__device__ __forceinline__ void mma8(float* c, const unsigned* a, const unsigned* b) {
    asm volatile(
        "mma.sync.aligned.m16n8k8.row.col.f32.tf32.tf32.f32 "
        "{%0,%1,%2,%3},{%4,%5,%6,%7},{%8,%9},{%0,%1,%2,%3};"
        : "+f"(c[0]), "+f"(c[1]), "+f"(c[2]), "+f"(c[3])
        : "r"(a[0]), "r"(a[1]), "r"(a[2]), "r"(a[3]), "r"(b[0]), "r"(b[1]));
}

__device__ __forceinline__ void mma16(float* c, const unsigned* a, const unsigned* b) {
    asm volatile(
        "mma.sync.aligned.m16n8k16.row.col.f32.bf16.bf16.f32 "
        "{%0,%1,%2,%3},{%4,%5,%6,%7},{%8,%9},{%0,%1,%2,%3};"
        : "+f"(c[0]), "+f"(c[1]), "+f"(c[2]), "+f"(c[3])
        : "r"(a[0]), "r"(a[1]), "r"(a[2]), "r"(a[3]), "r"(b[0]), "r"(b[1]));
}

// Epilogues: 0=none, 1=cos(v+bias), 2=v*scale, 3=relu(v+bias), 4=v+bias
template <int EPI>
__device__ __forceinline__ float epi_f(float v, const float* __restrict__ bias,
                                       int col, float scale) {
    if (EPI == 1) return __cosf(v + bias[col]);
    if (EPI == 2) return v * scale;
    if (EPI == 3) return fmaxf(v + bias[col], 0.0f);
    if (EPI == 4) return v + bias[col];
    return v;
}

// ---------------------------------------------------------------------------
// TF32 tensor-core GEMM: C[m,n] = sum_k A[m,k] * B[n,k]  (both K-major)
// CTA tile 128x256, BK=16, 256 threads (8 warps, 2x4), warp tile 64x64.
// ---------------------------------------------------------------------------
template <int EPI>
__global__ void __launch_bounds__(256, 1) tgemm_kernel(
    const float* __restrict__ A, const float* __restrict__ B,
    float* __restrict__ C, int M, int N, int K,
    size_t sA, size_t sB, size_t sC,
    const float* __restrict__ bias, float scale) {
    __shared__ float As[2][2048];
    __shared__ float Bs[2][4096];

    A += (size_t)blockIdx.z * sA;
    B += (size_t)blockIdx.z * sB;
    C += (size_t)blockIdx.z * sC;

    const int bm = blockIdx.y * 128;
    const int bn = blockIdx.x * 256;
    const int tid = threadIdx.x;
    const int lane = tid & 31;
    const int wid = tid >> 5;
    const int wm = wid >> 2;
    const int wn = wid & 3;

    float acc[4][8][4] = {};
    float4 ra[2], rb[4];

    const int niter = K >> 4;

    auto ldgA = [&](int it) {
#pragma unroll
        for (int u = 0; u < 2; ++u) {
            int idx = u * 256 + tid;
            int row = idx >> 2, c = idx & 3;
            ra[u] = *(const float4*)(A + (size_t)(bm + row) * K + it * 16 + c * 4);
        }
    };
    auto ldgB = [&](int it) {
#pragma unroll
        for (int u = 0; u < 4; ++u) {
            int idx = u * 256 + tid;
            int row = idx >> 2, c = idx & 3;
            rb[u] = *(const float4*)(B + (size_t)(bn + row) * K + it * 16 + c * 4);
        }
    };
    auto stsA = [&](int buf) {
#pragma unroll
        for (int u = 0; u < 2; ++u) {
            int idx = u * 256 + tid;
            int row = idx >> 2, c = idx & 3;
            int mt = row >> 4, rb3 = (row >> 3) & 1, r7 = row & 7;
            float v[4] = {ra[u].x, ra[u].y, ra[u].z, ra[u].w};
#pragma unroll
            for (int j = 0; j < 4; ++j) {
                int ks = c >> 1;
                int t = (r7 << 2) | j;
                int r = ((c & 1) << 1) | rb3;
                int off = ((ks * 8 + mt) * 32 + (t ^ (t >> 3))) * 4 + r;
                As[buf][off] = tf32r(v[j]);
            }
        }
    };
    auto stsB = [&](int buf) {
#pragma unroll
        for (int u = 0; u < 4; ++u) {
            int idx = u * 256 + tid;
            int row = idx >> 2, c = idx & 3;
            int nt = row >> 3, r7 = row & 7;
            float v[4] = {rb[u].x, rb[u].y, rb[u].z, rb[u].w};
#pragma unroll
            for (int j = 0; j < 4; ++j) {
                int ks = c >> 1;
                int t = (r7 << 2) | j;
                int r = c & 1;
                int off = ((ks * 32 + nt) * 32 + (t ^ (t >> 3) ^ (nt & 3))) * 2 + r;
                Bs[buf][off] = tf32r(v[j]);
            }
        }
    };
    auto compute = [&](int buf) {
        const int physA = lane ^ (lane >> 3);
#pragma unroll
        for (int ks = 0; ks < 2; ++ks) {
            unsigned af[4][4];
            unsigned bf[8][2];
#pragma unroll
            for (int mi = 0; mi < 4; ++mi) {
                int mtg = wm * 4 + mi;
                float4 t = *(const float4*)&As[buf][((ks * 8 + mtg) * 32 + physA) * 4];
                af[mi][0] = __float_as_uint(t.x);
                af[mi][1] = __float_as_uint(t.y);
                af[mi][2] = __float_as_uint(t.z);
                af[mi][3] = __float_as_uint(t.w);
            }
#pragma unroll
            for (int ni = 0; ni < 8; ++ni) {
                int ntg = wn * 8 + ni;
                int physB = lane ^ (lane >> 3) ^ (ntg & 3);
                float2 t = *(const float2*)&Bs[buf][((ks * 32 + ntg) * 32 + physB) * 2];
                bf[ni][0] = __float_as_uint(t.x);
                bf[ni][1] = __float_as_uint(t.y);
            }
#pragma unroll
            for (int mi = 0; mi < 4; ++mi)
#pragma unroll
                for (int ni = 0; ni < 8; ++ni)
                    mma8(acc[mi][ni], af[mi], bf[ni]);
        }
    };

    ldgA(0);
    ldgB(0);
    stsA(0);
    stsB(0);
    __syncthreads();

    for (int it = 0; it < niter; ++it) {
        int cur = it & 1;
        bool more = (it + 1) < niter;
        if (more) {
            ldgA(it + 1);
            ldgB(it + 1);
        }
        compute(cur);
        if (more) {
            stsA(cur ^ 1);
            stsB(cur ^ 1);
        }
        __syncthreads();
    }

    const int g = lane >> 2;
    const int tg = lane & 3;
#pragma unroll
    for (int mi = 0; mi < 4; ++mi) {
        int row = bm + wm * 64 + mi * 16 + g;
#pragma unroll
        for (int ni = 0; ni < 8; ++ni) {
            int col = bn + wn * 64 + ni * 8 + tg * 2;
            const float* a = acc[mi][ni];
            float2 lo, hi;
            lo.x = epi_f<EPI>(a[0], bias, col + 0, scale);
            lo.y = epi_f<EPI>(a[1], bias, col + 1, scale);
            hi.x = epi_f<EPI>(a[2], bias, col + 0, scale);
            hi.y = epi_f<EPI>(a[3], bias, col + 1, scale);
            *(float2*)(C + (size_t)row * N + col) = lo;
            *(float2*)(C + (size_t)(row + 8) * N + col) = hi;
        }
    }
}

// ---------------------------------------------------------------------------
// BF16 tensor-core GEMM (m16n8k16): same tiling as tgemm, fp32 in/out with
// on-the-fly bf16 conversion at STS. Half the smem traffic, half the HMMAs.
// As u32[2][1024]: [(mt*32+phys)*4 + reg]  (reg: a0..a3 of m16n8k16)
// Bs u32[2][2048]: [(nt*32+phys)*2 + reg]  (reg: b0,b1)
// ---------------------------------------------------------------------------
template <int EPI>
__global__ void __launch_bounds__(256, 1) bgemm_kernel(
    const float* __restrict__ A, const float* __restrict__ B,
    float* __restrict__ C, int M, int N, int K,
    size_t sA, size_t sB, size_t sC,
    const float* __restrict__ bias, float scale) {
    __shared__ unsigned As[2][1024];
    __shared__ unsigned Bs[2][2048];

    A += (size_t)blockIdx.z * sA;
    B += (size_t)blockIdx.z * sB;
    C += (size_t)blockIdx.z * sC;

    const int bm = blockIdx.y * 128;
    const int bn = blockIdx.x * 256;
    const int tid = threadIdx.x;
    const int lane = tid & 31;
    const int wid = tid >> 5;
    const int wm = wid >> 2;
    const int wn = wid & 3;

    float acc[4][8][4] = {};
    float4 ra[2], rb[4];

    const int niter = K >> 4;

    auto ldgA = [&](int it) {
#pragma unroll
        for (int u = 0; u < 2; ++u) {
            int idx = u * 256 + tid;
            int row = idx >> 2, c = idx & 3;
            ra[u] = *(const float4*)(A + (size_t)(bm + row) * K + it * 16 + c * 4);
        }
    };
    auto ldgB = [&](int it) {
#pragma unroll
        for (int u = 0; u < 4; ++u) {
            int idx = u * 256 + tid;
            int row = idx >> 2, c = idx & 3;
            rb[u] = *(const float4*)(B + (size_t)(bn + row) * K + it * 16 + c * 4);
        }
    };
    // A element (row, k-pair p): reg = (p>=4?2:0) + ((row&15)>=8?1:0),
    // thread t = ((row&7)<<2)|(p&3), phys = t^(t>>3)
    auto stsA = [&](int buf) {
#pragma unroll
        for (int u = 0; u < 2; ++u) {
            int idx = u * 256 + tid;
            int row = idx >> 2, c = idx & 3;
            int mt = row >> 4, rhi = (row >> 3) & 1, r7 = row & 7;
            unsigned lo = bf2(ra[u].x, ra[u].y);   // pair p = 2c
            unsigned hi = bf2(ra[u].z, ra[u].w);   // pair p = 2c+1
            int regbase = (c >= 2 ? 2 : 0) + rhi;  // note: p>=4 <=> c>=2
#pragma unroll
            for (int j = 0; j < 2; ++j) {
                int p = 2 * c + j;
                int t = (r7 << 2) | (p & 3);
                int off = (mt * 32 + (t ^ (t >> 3))) * 4 + regbase;
                // regbase already includes (p>=4?2:0) since both j share c>=2
                As[buf][off] = j ? hi : lo;
            }
        }
    };
    // B element (n, k-pair p): reg = (p>=4?1:0), t = ((n&7)<<2)|(p&3),
    // phys = t^(t>>3)^(nt&3)
    auto stsB = [&](int buf) {
#pragma unroll
        for (int u = 0; u < 4; ++u) {
            int idx = u * 256 + tid;
            int row = idx >> 2, c = idx & 3;
            int nt = row >> 3, r7 = row & 7;
            unsigned lo = bf2(rb[u].x, rb[u].y);
            unsigned hi = bf2(rb[u].z, rb[u].w);
            int reg = (c >= 2) ? 1 : 0;
#pragma unroll
            for (int j = 0; j < 2; ++j) {
                int p = 2 * c + j;
                int t = (r7 << 2) | (p & 3);
                int off = (nt * 32 + (t ^ (t >> 3) ^ (nt & 3))) * 2 + reg;
                Bs[buf][off] = j ? hi : lo;
            }
        }
    };
    auto compute = [&](int buf) {
        const int physA = lane ^ (lane >> 3);
        unsigned af[4][4];
        unsigned bf[8][2];
#pragma unroll
        for (int mi = 0; mi < 4; ++mi) {
            int mtg = wm * 4 + mi;
            uint4 t = *(const uint4*)&As[buf][(mtg * 32 + physA) * 4];
            af[mi][0] = t.x;
            af[mi][1] = t.y;
            af[mi][2] = t.z;
            af[mi][3] = t.w;
        }
#pragma unroll
        for (int ni = 0; ni < 8; ++ni) {
            int ntg = wn * 8 + ni;
            int physB = lane ^ (lane >> 3) ^ (ntg & 3);
            uint2 t = *(const uint2*)&Bs[buf][(ntg * 32 + physB) * 2];
            bf[ni][0] = t.x;
            bf[ni][1] = t.y;
        }
#pragma unroll
        for (int mi = 0; mi < 4; ++mi)
#pragma unroll
            for (int ni = 0; ni < 8; ++ni)
                mma16(acc[mi][ni], af[mi], bf[ni]);
    };

    ldgA(0);
    ldgB(0);
    stsA(0);
    stsB(0);
    __syncthreads();

    for (int it = 0; it < niter; ++it) {
        int cur = it & 1;
        bool more = (it + 1) < niter;
        if (more) {
            ldgA(it + 1);
            ldgB(it + 1);
        }
        compute(cur);
        if (more) {
            stsA(cur ^ 1);
            stsB(cur ^ 1);
        }
        __syncthreads();
    }

    const int g = lane >> 2;
    const int tg = lane & 3;
#pragma unroll
    for (int mi = 0; mi < 4; ++mi) {
        int row = bm + wm * 64 + mi * 16 + g;
#pragma unroll
        for (int ni = 0; ni < 8; ++ni) {
            int col = bn + wn * 64 + ni * 8 + tg * 2;
            const float* a = acc[mi][ni];
            float2 lo, hi;
            lo.x = epi_f<EPI>(a[0], bias, col + 0, scale);
            lo.y = epi_f<EPI>(a[1], bias, col + 1, scale);
            hi.x = epi_f<EPI>(a[2], bias, col + 0, scale);
            hi.y = epi_f<EPI>(a[3], bias, col + 1, scale);
            *(float2*)(C + (size_t)row * N + col) = lo;
            *(float2*)(C + (size_t)(row + 8) * N + col) = hi;
        }
    }
}

// ---------------------------------------------------------------------------
// 32x32 tiled transpose per batch: out[b][e][t] = in[b][t][e]
// ---------------------------------------------------------------------------
__global__ void __launch_bounds__(256) transpose_kernel(
    const float* __restrict__ in, float* __restrict__ out) {
    __shared__ float t[32][33];
    const int b = blockIdx.z;
    const int t0 = blockIdx.x * 32;
    const int e0 = blockIdx.y * 32;
    const int lx = threadIdx.x & 31, ly = threadIdx.x >> 5;
#pragma unroll
    for (int r = 0; r < 32; r += 8)
        t[ly + r][lx] = in[((size_t)b * SEQ + t0 + ly + r) * EMB + e0 + lx];
    __syncthreads();
#pragma unroll
    for (int r = 0; r < 32; r += 8)
        out[((size_t)b * EMB + e0 + ly + r) * SEQ + t0 + lx] = t[lx][ly + r];
}

// ---------------------------------------------------------------------------
// Row softmax, row length 2048, one block (256 threads) per row.
// ---------------------------------------------------------------------------
__global__ void __launch_bounds__(256) softmax2048_kernel(float* __restrict__ S) {
    float* p = S + (size_t)blockIdx.x * SEQ;
    const int tid = threadIdx.x;
    __shared__ float sh[8];

    float v[8];
    float m = -1e30f;
#pragma unroll
    for (int i = 0; i < 8; i++) {
        v[i] = p[tid + i * 256];
        m = fmaxf(m, v[i]);
    }
#pragma unroll
    for (int o = 16; o > 0; o >>= 1) m = fmaxf(m, __shfl_xor_sync(~0u, m, o));
    if ((tid & 31) == 0) sh[tid >> 5] = m;
    __syncthreads();
    m = sh[0];
#pragma unroll
    for (int w = 1; w < 8; w++) m = fmaxf(m, sh[w]);

    float s = 0.0f;
#pragma unroll
    for (int i = 0; i < 8; i++) {
        v[i] = __expf(v[i] - m);
        s += v[i];
    }
    __syncthreads();
#pragma unroll
    for (int o = 16; o > 0; o >>= 1) s += __shfl_xor_sync(~0u, s, o);
    if ((tid & 31) == 0) sh[tid >> 5] = s;
    __syncthreads();
    s = 0.0f;
#pragma unroll
    for (int w = 0; w < 8; w++) s += sh[w];
    float inv = 1.0f / s;
#pragma unroll
    for (int i = 0; i < 8; i++) p[tid + i * 256] = v[i] * inv;
}

// ---------------------------------------------------------------------------
// out = LayerNorm(X + Y) * g + b, row length 768, one block per row.
// ---------------------------------------------------------------------------
__global__ void __launch_bounds__(256) add_ln_kernel(
    const float* __restrict__ X, const float* __restrict__ Y,
    const float* __restrict__ g, const float* __restrict__ b,
    float* __restrict__ out) {
    const size_t row = blockIdx.x;
    const float* xp = X + row * EMB;
    const float* yp = Y + row * EMB;
    float* op = out + row * EMB;
    const int tid = threadIdx.x;
    __shared__ float sh[8];

    float v[3];
    float s = 0.0f;
#pragma unroll
    for (int i = 0; i < 3; i++) {
        int c = tid + i * 256;
        v[i] = xp[c] + yp[c];
        s += v[i];
    }
#pragma unroll
    for (int o = 16; o > 0; o >>= 1) s += __shfl_xor_sync(~0u, s, o);
    if ((tid & 31) == 0) sh[tid >> 5] = s;
    __syncthreads();
    s = 0.0f;
#pragma unroll
    for (int w = 0; w < 8; w++) s += sh[w];
    const float mean = s * (1.0f / EMB);

    float q = 0.0f;
#pragma unroll
    for (int i = 0; i < 3; i++) {
        float d = v[i] - mean;
        q += d * d;
    }
    __syncthreads();
#pragma unroll
    for (int o = 16; o > 0; o >>= 1) q += __shfl_xor_sync(~0u, q, o);
    if ((tid & 31) == 0) sh[tid >> 5] = q;
    __syncthreads();
    q = 0.0f;
#pragma unroll
    for (int w = 0; w < 8; w++) q += sh[w];
    const float rs = rsqrtf(q * (1.0f / EMB) + 1e-5f);

#pragma unroll
    for (int i = 0; i < 3; i++) {
        int c = tid + i * 256;
        op[c] = (v[i] - mean) * rs * g[c] + b[c];
    }
}

// ---------------------------------------------------------------------------
// qf[m,q] = cos(x1[m, q] + theta_ry[q]), q < 128
// ---------------------------------------------------------------------------
__global__ void __launch_bounds__(256) qf_kernel(
    const float* __restrict__ x1, const float* __restrict__ th,
    float* __restrict__ qf) {
    int idx = blockIdx.x * 256 + threadIdx.x;
    int m = idx >> 7;
    int q = idx & 127;
    qf[idx] = __cosf(x1[(size_t)m * EMB + q] + th[q]);
}

// ---------------------------------------------------------------------------
// Launch
// ---------------------------------------------------------------------------
extern "C" void kernel_launch(void* const* d_in, const int* in_sizes, int n_in,
                              void* d_out, int out_size) {
    const float* x     = (const float*)d_in[0];
    const float* Wp    = (const float*)d_in[1];
    const float* th_rx = (const float*)d_in[2];
    const float* th_ry = (const float*)d_in[3];
    const float* W1    = (const float*)d_in[4];
    const float* b1    = (const float*)d_in[5];
    const float* W2    = (const float*)d_in[6];
    const float* b2    = (const float*)d_in[7];
    const float* ln1g  = (const float*)d_in[8];
    const float* ln1b  = (const float*)d_in[9];
    const float* ln2g  = (const float*)d_in[10];
    const float* ln2b  = (const float*)d_in[11];
    float* out = (float*)d_out;

    float *qa, *qaT, *sc, *x1, *tmp, *h, *qf;
    cudaGetSymbolAddress((void**)&qa, g_qa);
    cudaGetSymbolAddress((void**)&qaT, g_qaT);
    cudaGetSymbolAddress((void**)&sc, g_scores);
    cudaGetSymbolAddress((void**)&x1, g_x1);
    cudaGetSymbolAddress((void**)&tmp, g_tmp);
    cudaGetSymbolAddress((void**)&h, g_h);
    cudaGetSymbolAddress((void**)&qf, g_qf);

    dim3 blk(256);

    // 1. qa = cos(x @ Wp^T + theta_rx)  [16384,768]  (TF32: feeds scores)
    tgemm_kernel<1><<<dim3(EMB / 256, NTOK / 128, 1), blk>>>(
        x, Wp, qa, NTOK, EMB, EMB, 0, 0, 0, th_rx, 0.0f);

    // 1b. qaT[b][e][t] = qa[b][t][e]
    transpose_kernel<<<dim3(SEQ / 32, EMB / 32, BATCH), blk>>>(qa, qaT);

    // 2. scores = qa @ qa^T / sqrt(8), batched (TF32: softmax-sensitive)
    tgemm_kernel<2><<<dim3(SEQ / 256, SEQ / 128, BATCH), blk>>>(
        qa, qa, sc, SEQ, SEQ, EMB,
        (size_t)SEQ * EMB, (size_t)SEQ * EMB, (size_t)SEQ * SEQ,
        nullptr, 0.35355339059327373f);

    // 3. softmax rows
    softmax2048_kernel<<<NTOK, blk>>>(sc);

    // 4. attn_out = P @ qa == P @ (qaT)^T, batched (BF16)
    bgemm_kernel<0><<<dim3(EMB / 256, SEQ / 128, BATCH), blk>>>(
        sc, qaT, tmp, SEQ, EMB, SEQ,
        (size_t)SEQ * SEQ, (size_t)EMB * SEQ, (size_t)SEQ * EMB,
        nullptr, 0.0f);

    // 5. x1 = LN(x + attn_out)
    add_ln_kernel<<<NTOK, blk>>>(x, tmp, ln1g, ln1b, x1);

    // 6. qf = cos(x1[:, :128] + theta_ry)
    qf_kernel<<<(NTOK * NQD) / 256, blk>>>(x1, th_ry, qf);

    // 7. h = relu(qf @ W1^T + b1)  [16384,3072], K=128 (BF16)
    bgemm_kernel<3><<<dim3(FFD / 256, NTOK / 128, 1), blk>>>(
        qf, W1, h, NTOK, FFD, NQD, 0, 0, 0, b1, 0.0f);

    // 8. ffn_out = h @ W2^T + b2  [16384,768] (BF16)
    bgemm_kernel<4><<<dim3(EMB / 256, NTOK / 128, 1), blk>>>(
        h, W2, tmp, NTOK, EMB, FFD, 0, 0, 0, b2, 0.0f);

    // 9. out = LN(x1 + ffn_out)
    add_ln_kernel<<<NTOK, blk>>>(x1, tmp, ln2g, ln2b, out);
}

// round 7
// speedup vs baseline: 4.9163x; 1.4357x over previous
#include <cuda_runtime.h>
#include <cuda_bf16.h>
#include <cstdint>
#include <math.h>

// Problem constants
#define NTOK 16384      // B*S
#define BATCH 8
#define SEQ 2048
#define EMB 768
#define FFD 3072
#define NQD 128

// ---------------------------------------------------------------------------
// Scratch (device globals; no allocation allowed)
// ---------------------------------------------------------------------------
__device__ float g_qa[(size_t)NTOK * EMB];
__device__ float g_scores[(size_t)BATCH * SEQ * SEQ];
__device__ float g_x1[(size_t)NTOK * EMB];
__device__ float g_tmp[(size_t)NTOK * EMB];
__device__ __nv_bfloat16 g_Pb[(size_t)BATCH * SEQ * SEQ];
__device__ __nv_bfloat16 g_qaTb[(size_t)NTOK * EMB];
__device__ __nv_bfloat16 g_qfb[(size_t)NTOK * NQD];
__device__ __nv_bfloat16 g_hb[(size_t)NTOK * FFD];
__device__ __nv_bfloat16 g_W1b[(size_t)FFD * NQD];
__device__ __nv_bfloat16 g_W2b[(size_t)EMB * FFD];

// ---------------------------------------------------------------------------
// Helpers
// ---------------------------------------------------------------------------
__device__ __forceinline__ uint32_t smem_u32(const void* p) {
    uint32_t a;
    asm("{ .reg .u64 t; cvta.to.shared.u64 t, %1; cvt.u32.u64 %0, t; }"
        : "=r"(a) : "l"(p));
    return a;
}

__device__ __forceinline__ float tf32r(float f) {
    unsigned r;
    asm("cvt.rna.tf32.f32 %0, %1;" : "=r"(r) : "f"(f));
    return __uint_as_float(r);
}

__device__ __forceinline__ void mma8(float* c, const unsigned* a, const unsigned* b) {
    asm volatile(
        "mma.sync.aligned.m16n8k8.row.col.f32.tf32.tf32.f32 "
        "{%0,%1,%2,%3},{%4,%5,%6,%7},{%8,%9},{%0,%1,%2,%3};"
        : "+f"(c[0]), "+f"(c[1]), "+f"(c[2]), "+f"(c[3])
        : "r"(a[0]), "r"(a[1]), "r"(a[2]), "r"(a[3]), "r"(b[0]), "r"(b[1]));
}

__device__ __forceinline__ void mma16(float* c, const unsigned* a, const unsigned* b) {
    asm volatile(
        "mma.sync.aligned.m16n8k16.row.col.f32.bf16.bf16.f32 "
        "{%0,%1,%2,%3},{%4,%5,%6,%7},{%8,%9},{%0,%1,%2,%3};"
        : "+f"(c[0]), "+f"(c[1]), "+f"(c[2]), "+f"(c[3])
        : "r"(a[0]), "r"(a[1]), "r"(a[2]), "r"(a[3]), "r"(b[0]), "r"(b[1]));
}

__device__ __forceinline__ void cp16(uint32_t dst, const void* src) {
    asm volatile("cp.async.cg.shared.global [%0], [%1], 16;" :: "r"(dst), "l"(src));
}
#define CP_COMMIT() asm volatile("cp.async.commit_group;" ::: "memory")

#define LDMX4(r, a) \
    asm volatile("ldmatrix.sync.aligned.m8n8.x4.shared.b16 {%0,%1,%2,%3}, [%4];" \
                 : "=r"((r)[0]), "=r"((r)[1]), "=r"((r)[2]), "=r"((r)[3]) : "r"(a))

// Epilogues: 0=none, 1=cos(v+bias), 2=v*scale, 3=relu(v+bias), 4=v+bias
template <int EPI>
__device__ __forceinline__ float epi_f(float v, const float* __restrict__ bias,
                                       int col, float scale) {
    if (EPI == 1) return __cosf(v + bias[col]);
    if (EPI == 2) return v * scale;
    if (EPI == 3) return fmaxf(v + bias[col], 0.0f);
    if (EPI == 4) return v + bias[col];
    return v;
}

// ---------------------------------------------------------------------------
// TF32 tensor-core GEMM: C = A @ B^T, K-major both.
// CTA 128x256, BK=16, 8 warps 2x4, warp tile 64x64, fragment pre-shuffle smem.
// ---------------------------------------------------------------------------
template <int EPI>
__global__ void __launch_bounds__(256, 1) tgemm_kernel(
    const float* __restrict__ A, const float* __restrict__ B,
    float* __restrict__ C, int M, int N, int K,
    size_t sA, size_t sB, size_t sC,
    const float* __restrict__ bias, float scale) {
    __shared__ float As[2][2048];
    __shared__ float Bs[2][4096];

    A += (size_t)blockIdx.z * sA;
    B += (size_t)blockIdx.z * sB;
    C += (size_t)blockIdx.z * sC;

    const int bm = blockIdx.y * 128;
    const int bn = blockIdx.x * 256;
    const int tid = threadIdx.x;
    const int lane = tid & 31;
    const int wid = tid >> 5;
    const int wm = wid >> 2;
    const int wn = wid & 3;

    float acc[4][8][4] = {};
    float4 ra[2], rb[4];

    const int niter = K >> 4;

    auto ldgA = [&](int it) {
#pragma unroll
        for (int u = 0; u < 2; ++u) {
            int idx = u * 256 + tid;
            int row = idx >> 2, c = idx & 3;
            ra[u] = *(const float4*)(A + (size_t)(bm + row) * K + it * 16 + c * 4);
        }
    };
    auto ldgB = [&](int it) {
#pragma unroll
        for (int u = 0; u < 4; ++u) {
            int idx = u * 256 + tid;
            int row = idx >> 2, c = idx & 3;
            rb[u] = *(const float4*)(B + (size_t)(bn + row) * K + it * 16 + c * 4);
        }
    };
    auto stsA = [&](int buf) {
#pragma unroll
        for (int u = 0; u < 2; ++u) {
            int idx = u * 256 + tid;
            int row = idx >> 2, c = idx & 3;
            int mt = row >> 4, rb3 = (row >> 3) & 1, r7 = row & 7;
            float v[4] = {ra[u].x, ra[u].y, ra[u].z, ra[u].w};
#pragma unroll
            for (int j = 0; j < 4; ++j) {
                int ks = c >> 1;
                int t = (r7 << 2) | j;
                int r = ((c & 1) << 1) | rb3;
                int off = ((ks * 8 + mt) * 32 + (t ^ (t >> 3))) * 4 + r;
                As[buf][off] = tf32r(v[j]);
            }
        }
    };
    auto stsB = [&](int buf) {
#pragma unroll
        for (int u = 0; u < 4; ++u) {
            int idx = u * 256 + tid;
            int row = idx >> 2, c = idx & 3;
            int nt = row >> 3, r7 = row & 7;
            float v[4] = {rb[u].x, rb[u].y, rb[u].z, rb[u].w};
#pragma unroll
            for (int j = 0; j < 4; ++j) {
                int ks = c >> 1;
                int t = (r7 << 2) | j;
                int r = c & 1;
                int off = ((ks * 32 + nt) * 32 + (t ^ (t >> 3) ^ (nt & 3))) * 2 + r;
                Bs[buf][off] = tf32r(v[j]);
            }
        }
    };
    auto compute = [&](int buf) {
        const int physA = lane ^ (lane >> 3);
#pragma unroll
        for (int ks = 0; ks < 2; ++ks) {
            unsigned af[4][4];
            unsigned bf[8][2];
#pragma unroll
            for (int mi = 0; mi < 4; ++mi) {
                int mtg = wm * 4 + mi;
                float4 t = *(const float4*)&As[buf][((ks * 8 + mtg) * 32 + physA) * 4];
                af[mi][0] = __float_as_uint(t.x);
                af[mi][1] = __float_as_uint(t.y);
                af[mi][2] = __float_as_uint(t.z);
                af[mi][3] = __float_as_uint(t.w);
            }
#pragma unroll
            for (int ni = 0; ni < 8; ++ni) {
                int ntg = wn * 8 + ni;
                int physB = lane ^ (lane >> 3) ^ (ntg & 3);
                float2 t = *(const float2*)&Bs[buf][((ks * 32 + ntg) * 32 + physB) * 2];
                bf[ni][0] = __float_as_uint(t.x);
                bf[ni][1] = __float_as_uint(t.y);
            }
#pragma unroll
            for (int mi = 0; mi < 4; ++mi)
#pragma unroll
                for (int ni = 0; ni < 8; ++ni)
                    mma8(acc[mi][ni], af[mi], bf[ni]);
        }
    };

    ldgA(0);
    ldgB(0);
    stsA(0);
    stsB(0);
    __syncthreads();

    for (int it = 0; it < niter; ++it) {
        int cur = it & 1;
        bool more = (it + 1) < niter;
        if (more) {
            ldgA(it + 1);
            ldgB(it + 1);
        }
        compute(cur);
        if (more) {
            stsA(cur ^ 1);
            stsB(cur ^ 1);
        }
        __syncthreads();
    }

    const int g = lane >> 2;
    const int tg = lane & 3;
#pragma unroll
    for (int mi = 0; mi < 4; ++mi) {
        int row = bm + wm * 64 + mi * 16 + g;
#pragma unroll
        for (int ni = 0; ni < 8; ++ni) {
            int col = bn + wn * 64 + ni * 8 + tg * 2;
            const float* a = acc[mi][ni];
            float2 lo, hi;
            lo.x = epi_f<EPI>(a[0], bias, col + 0, scale);
            lo.y = epi_f<EPI>(a[1], bias, col + 1, scale);
            hi.x = epi_f<EPI>(a[2], bias, col + 0, scale);
            hi.y = epi_f<EPI>(a[3], bias, col + 1, scale);
            *(float2*)(C + (size_t)row * N + col) = lo;
            *(float2*)(C + (size_t)(row + 8) * N + col) = hi;
        }
    }
}

// ---------------------------------------------------------------------------
// BF16 GEMM v2: cp.async + ldmatrix, bf16 gmem operands (K-major both).
// CTA 128x256, BK=32, 3-stage pipeline, 8 warps 2x4, warp tile 64x64.
// ---------------------------------------------------------------------------
#define BG_STAGE 24576
#define BG_SMEM  (3 * BG_STAGE)

__device__ __forceinline__ uint32_t swz_off(int r, int c) {
    return (uint32_t)(r * 64 + ((c ^ ((r ^ (r >> 1)) & 3)) << 4));
}

template <int EPI, bool OUTBF>
__global__ void __launch_bounds__(256, 1) bgemm2_kernel(
    const __nv_bfloat16* __restrict__ A, const __nv_bfloat16* __restrict__ B,
    void* __restrict__ Cv, int M, int N, int K,
    size_t sA, size_t sB, size_t sC,
    const float* __restrict__ bias, float scale) {
    extern __shared__ char smem[];
    const uint32_t sb = smem_u32(smem);

    A += (size_t)blockIdx.z * sA;
    B += (size_t)blockIdx.z * sB;

    const int bm = blockIdx.y * 128;
    const int bn = blockIdx.x * 256;
    const int tid = threadIdx.x;
    const int lane = tid & 31;
    const int wid = tid >> 5;
    const int wm = wid >> 2;
    const int wn = wid & 3;
    const int niter = K >> 5;

    float acc[4][8][4] = {};

    auto load_stage = [&](int it, int st) {
        uint32_t base = sb + st * BG_STAGE;
        const __nv_bfloat16* Ag = A + (size_t)bm * K + it * 32;
#pragma unroll
        for (int u = 0; u < 2; u++) {
            int q = u * 256 + tid;
            int r = q >> 2, c = q & 3;
            cp16(base + swz_off(r, c), Ag + (size_t)r * K + c * 8);
        }
        const __nv_bfloat16* Bg = B + (size_t)bn * K + it * 32;
#pragma unroll
        for (int u = 0; u < 4; u++) {
            int q = u * 256 + tid;
            int r = q >> 2, c = q & 3;
            cp16(base + 8192 + swz_off(r, c), Bg + (size_t)r * K + c * 8);
        }
        CP_COMMIT();
    };

    auto compute = [&](int st) {
        uint32_t Ab = sb + st * BG_STAGE;
        uint32_t Bb = Ab + 8192;
#pragma unroll
        for (int s = 0; s < 2; s++) {
            unsigned af[4][4], bf[8][2];
#pragma unroll
            for (int mi = 0; mi < 4; mi++) {
                int row = wm * 64 + mi * 16 + ((lane >> 3) & 1) * 8 + (lane & 7);
                int c = s * 2 + (lane >> 4);
                LDMX4(af[mi], Ab + swz_off(row, c));
            }
#pragma unroll
            for (int p = 0; p < 4; p++) {
                int row = wn * 64 + p * 16 + ((lane >> 4) << 3) + (lane & 7);
                int c = s * 2 + ((lane >> 3) & 1);
                unsigned t[4];
                LDMX4(t, Bb + swz_off(row, c));
                bf[2 * p][0] = t[0];
                bf[2 * p][1] = t[1];
                bf[2 * p + 1][0] = t[2];
                bf[2 * p + 1][1] = t[3];
            }
#pragma unroll
            for (int mi = 0; mi < 4; mi++)
#pragma unroll
                for (int ni = 0; ni < 8; ni++)
                    mma16(acc[mi][ni], af[mi], bf[ni]);
        }
    };

    load_stage(0, 0);
    if (niter > 1) load_stage(1, 1);
    else CP_COMMIT();

    int cur = 0;
    for (int it = 0; it < niter; it++) {
        asm volatile("cp.async.wait_group 1;" ::: "memory");
        __syncthreads();
        compute(cur);
        if (it + 2 < niter) {
            int nst = cur - 1;
            if (nst < 0) nst = 2;
            load_stage(it + 2, nst);
        } else {
            CP_COMMIT();
        }
        cur = (cur == 2) ? 0 : cur + 1;
    }

    const int g = lane >> 2;
    const int tg = lane & 3;
#pragma unroll
    for (int mi = 0; mi < 4; ++mi) {
        int row = bm + wm * 64 + mi * 16 + g;
#pragma unroll
        for (int ni = 0; ni < 8; ++ni) {
            int col = bn + wn * 64 + ni * 8 + tg * 2;
            const float* a = acc[mi][ni];
            float e0 = epi_f<EPI>(a[0], bias, col + 0, scale);
            float e1 = epi_f<EPI>(a[1], bias, col + 1, scale);
            float e2 = epi_f<EPI>(a[2], bias, col + 0, scale);
            float e3 = epi_f<EPI>(a[3], bias, col + 1, scale);
            if (OUTBF) {
                __nv_bfloat16* C = (__nv_bfloat16*)Cv + (size_t)blockIdx.z * sC;
                *(__nv_bfloat162*)(C + (size_t)row * N + col) =
                    __float22bfloat162_rn(make_float2(e0, e1));
                *(__nv_bfloat162*)(C + (size_t)(row + 8) * N + col) =
                    __float22bfloat162_rn(make_float2(e2, e3));
            } else {
                float* C = (float*)Cv + (size_t)blockIdx.z * sC;
                *(float2*)(C + (size_t)row * N + col) = make_float2(e0, e1);
                *(float2*)(C + (size_t)(row + 8) * N + col) = make_float2(e2, e3);
            }
        }
    }
}

// ---------------------------------------------------------------------------
// 32x32 tiled transpose per batch, bf16 out: out[b][e][t] = bf16(in[b][t][e])
// ---------------------------------------------------------------------------
__global__ void __launch_bounds__(256) transpose_kernel(
    const float* __restrict__ in, __nv_bfloat16* __restrict__ out) {
    __shared__ float t[32][33];
    const int b = blockIdx.z;
    const int t0 = blockIdx.x * 32;
    const int e0 = blockIdx.y * 32;
    const int lx = threadIdx.x & 31, ly = threadIdx.x >> 5;
#pragma unroll
    for (int r = 0; r < 32; r += 8)
        t[ly + r][lx] = in[((size_t)b * SEQ + t0 + ly + r) * EMB + e0 + lx];
    __syncthreads();
#pragma unroll
    for (int r = 0; r < 32; r += 8)
        out[((size_t)b * EMB + e0 + ly + r) * SEQ + t0 + lx] =
            __float2bfloat16(t[lx][ly + r]);
}

// ---------------------------------------------------------------------------
// Row softmax (reads fp32 scores, writes bf16 P), row length 2048.
// ---------------------------------------------------------------------------
__global__ void __launch_bounds__(256) softmax2048_kernel(
    const float* __restrict__ S, __nv_bfloat16* __restrict__ P) {
    const float* p = S + (size_t)blockIdx.x * SEQ;
    __nv_bfloat16* o = P + (size_t)blockIdx.x * SEQ;
    const int tid = threadIdx.x;
    __shared__ float sh[8];

    float v[8];
    float m = -1e30f;
#pragma unroll
    for (int i = 0; i < 8; i++) {
        v[i] = p[tid + i * 256];
        m = fmaxf(m, v[i]);
    }
#pragma unroll
    for (int o2 = 16; o2 > 0; o2 >>= 1) m = fmaxf(m, __shfl_xor_sync(~0u, m, o2));
    if ((tid & 31) == 0) sh[tid >> 5] = m;
    __syncthreads();
    m = sh[0];
#pragma unroll
    for (int w = 1; w < 8; w++) m = fmaxf(m, sh[w]);

    float s = 0.0f;
#pragma unroll
    for (int i = 0; i < 8; i++) {
        v[i] = __expf(v[i] - m);
        s += v[i];
    }
    __syncthreads();
#pragma unroll
    for (int o2 = 16; o2 > 0; o2 >>= 1) s += __shfl_xor_sync(~0u, s, o2);
    if ((tid & 31) == 0) sh[tid >> 5] = s;
    __syncthreads();
    s = 0.0f;
#pragma unroll
    for (int w = 0; w < 8; w++) s += sh[w];
    float inv = 1.0f / s;
#pragma unroll
    for (int i = 0; i < 8; i++) o[tid + i * 256] = __float2bfloat16(v[i] * inv);
}

// ---------------------------------------------------------------------------
// out = LayerNorm(X + Y) * g + b, row length 768, one block per row.
// ---------------------------------------------------------------------------
__global__ void __launch_bounds__(256) add_ln_kernel(
    const float* __restrict__ X, const float* __restrict__ Y,
    const float* __restrict__ g, const float* __restrict__ b,
    float* __restrict__ out) {
    const size_t row = blockIdx.x;
    const float* xp = X + row * EMB;
    const float* yp = Y + row * EMB;
    float* op = out + row * EMB;
    const int tid = threadIdx.x;
    __shared__ float sh[8];

    float v[3];
    float s = 0.0f;
#pragma unroll
    for (int i = 0; i < 3; i++) {
        int c = tid + i * 256;
        v[i] = xp[c] + yp[c];
        s += v[i];
    }
#pragma unroll
    for (int o = 16; o > 0; o >>= 1) s += __shfl_xor_sync(~0u, s, o);
    if ((tid & 31) == 0) sh[tid >> 5] = s;
    __syncthreads();
    s = 0.0f;
#pragma unroll
    for (int w = 0; w < 8; w++) s += sh[w];
    const float mean = s * (1.0f / EMB);

    float q = 0.0f;
#pragma unroll
    for (int i = 0; i < 3; i++) {
        float d = v[i] - mean;
        q += d * d;
    }
    __syncthreads();
#pragma unroll
    for (int o = 16; o > 0; o >>= 1) q += __shfl_xor_sync(~0u, q, o);
    if ((tid & 31) == 0) sh[tid >> 5] = q;
    __syncthreads();
    q = 0.0f;
#pragma unroll
    for (int w = 0; w < 8; w++) q += sh[w];
    const float rs = rsqrtf(q * (1.0f / EMB) + 1e-5f);

#pragma unroll
    for (int i = 0; i < 3; i++) {
        int c = tid + i * 256;
        op[c] = (v[i] - mean) * rs * g[c] + b[c];
    }
}

// ---------------------------------------------------------------------------
// qf[m,q] = bf16(cos(x1[m, q] + theta_ry[q])), q < 128
// ---------------------------------------------------------------------------
__global__ void __launch_bounds__(256) qf_kernel(
    const float* __restrict__ x1, const float* __restrict__ th,
    __nv_bfloat16* __restrict__ qf) {
    int idx = blockIdx.x * 256 + threadIdx.x;
    int m = idx >> 7;
    int q = idx & 127;
    qf[idx] = __float2bfloat16(__cosf(x1[(size_t)m * EMB + q] + th[q]));
}

// ---------------------------------------------------------------------------
// fp32 -> bf16 convert (n multiple of 1024)
// ---------------------------------------------------------------------------
__global__ void __launch_bounds__(256) cvt_kernel(
    const float* __restrict__ in, __nv_bfloat16* __restrict__ out) {
    int i = blockIdx.x * 256 + threadIdx.x;
    float4 v = *(const float4*)(in + (size_t)i * 4);
    *(__nv_bfloat162*)(out + (size_t)i * 4) =
        __float22bfloat162_rn(make_float2(v.x, v.y));
    *(__nv_bfloat162*)(out + (size_t)i * 4 + 2) =
        __float22bfloat162_rn(make_float2(v.z, v.w));
}

// ---------------------------------------------------------------------------
// Launch
// ---------------------------------------------------------------------------
extern "C" void kernel_launch(void* const* d_in, const int* in_sizes, int n_in,
                              void* d_out, int out_size) {
    const float* x     = (const float*)d_in[0];
    const float* Wp    = (const float*)d_in[1];
    const float* th_rx = (const float*)d_in[2];
    const float* th_ry = (const float*)d_in[3];
    const float* W1    = (const float*)d_in[4];
    const float* b1    = (const float*)d_in[5];
    const float* W2    = (const float*)d_in[6];
    const float* b2    = (const float*)d_in[7];
    const float* ln1g  = (const float*)d_in[8];
    const float* ln1b  = (const float*)d_in[9];
    const float* ln2g  = (const float*)d_in[10];
    const float* ln2b  = (const float*)d_in[11];
    float* out = (float*)d_out;

    float *qa, *sc, *x1, *tmp;
    __nv_bfloat16 *Pb, *qaTb, *qfb, *hb, *W1b, *W2b;
    cudaGetSymbolAddress((void**)&qa, g_qa);
    cudaGetSymbolAddress((void**)&sc, g_scores);
    cudaGetSymbolAddress((void**)&x1, g_x1);
    cudaGetSymbolAddress((void**)&tmp, g_tmp);
    cudaGetSymbolAddress((void**)&Pb, g_Pb);
    cudaGetSymbolAddress((void**)&qaTb, g_qaTb);
    cudaGetSymbolAddress((void**)&qfb, g_qfb);
    cudaGetSymbolAddress((void**)&hb, g_hb);
    cudaGetSymbolAddress((void**)&W1b, g_W1b);
    cudaGetSymbolAddress((void**)&W2b, g_W2b);

    cudaFuncSetAttribute(bgemm2_kernel<0, false>,
                         cudaFuncAttributeMaxDynamicSharedMemorySize, BG_SMEM);
    cudaFuncSetAttribute(bgemm2_kernel<3, true>,
                         cudaFuncAttributeMaxDynamicSharedMemorySize, BG_SMEM);
    cudaFuncSetAttribute(bgemm2_kernel<4, false>,
                         cudaFuncAttributeMaxDynamicSharedMemorySize, BG_SMEM);

    dim3 blk(256);

    // 0. weight conversions (bf16)
    cvt_kernel<<<(FFD * NQD) / 1024, blk>>>(W1, W1b);
    cvt_kernel<<<(EMB * FFD) / 1024, blk>>>(W2, W2b);

    // 1. qa = cos(x @ Wp^T + theta_rx)  [16384,768]  (TF32)
    tgemm_kernel<1><<<dim3(EMB / 256, NTOK / 128, 1), blk>>>(
        x, Wp, qa, NTOK, EMB, EMB, 0, 0, 0, th_rx, 0.0f);

    // 1b. qaTb[b][e][t] = bf16(qa[b][t][e])
    transpose_kernel<<<dim3(SEQ / 32, EMB / 32, BATCH), blk>>>(qa, qaTb);

    // 2. scores = qa @ qa^T / sqrt(8), batched (TF32)
    tgemm_kernel<2><<<dim3(SEQ / 256, SEQ / 128, BATCH), blk>>>(
        qa, qa, sc, SEQ, SEQ, EMB,
        (size_t)SEQ * EMB, (size_t)SEQ * EMB, (size_t)SEQ * SEQ,
        nullptr, 0.35355339059327373f);

    // 3. softmax rows -> bf16 P
    softmax2048_kernel<<<NTOK, blk>>>(sc, Pb);

    // 4. attn_out = P @ qa (bf16 pipeline), batched
    bgemm2_kernel<0, false><<<dim3(EMB / 256, SEQ / 128, BATCH), blk, BG_SMEM>>>(
        Pb, qaTb, tmp, SEQ, EMB, SEQ,
        (size_t)SEQ * SEQ, (size_t)EMB * SEQ, (size_t)SEQ * EMB,
        nullptr, 0.0f);

    // 5. x1 = LN(x + attn_out)
    add_ln_kernel<<<NTOK, blk>>>(x, tmp, ln1g, ln1b, x1);

    // 6. qf = bf16(cos(x1[:, :128] + theta_ry))
    qf_kernel<<<(NTOK * NQD) / 256, blk>>>(x1, th_ry, qfb);

    // 7. h = relu(qf @ W1^T + b1) -> bf16  [16384,3072], K=128
    bgemm2_kernel<3, true><<<dim3(FFD / 256, NTOK / 128, 1), blk, BG_SMEM>>>(
        qfb, W1b, hb, NTOK, FFD, NQD, 0, 0, 0, b1, 0.0f);

    // 8. ffn_out = h @ W2^T + b2  [16384,768], K=3072
    bgemm2_kernel<4, false><<<dim3(EMB / 256, NTOK / 128, 1), blk, BG_SMEM>>>(
        hb, W2b, tmp, NTOK, EMB, FFD, 0, 0, 0, b2, 0.0f);

    // 9. out = LN(x1 + ffn_out)
    add_ln_kernel<<<NTOK, blk>>>(x1, tmp, ln2g, ln2b, out);
}

// round 10
// speedup vs baseline: 5.1814x; 1.0539x over previous
#include <cuda_runtime.h>
#include <cuda_bf16.h>
#include <cstdint>
#include <math.h>

// Problem constants
#define NTOK 16384      // B*S
#define BATCH 8
#define SEQ 2048
#define EMB 768
#define FFD 3072
#define NQD 128

// ---------------------------------------------------------------------------
// Scratch (device globals; no allocation allowed)
// ---------------------------------------------------------------------------
__device__ float g_qa[(size_t)NTOK * EMB];
__device__ float g_scores[(size_t)BATCH * SEQ * SEQ];
__device__ float g_x1[(size_t)NTOK * EMB];
__device__ float g_tmp[(size_t)NTOK * EMB];
__device__ float g_xr[(size_t)NTOK * EMB];            // tf32-rounded x
__device__ float g_Wpr[(size_t)EMB * EMB];            // tf32-rounded Wp
__device__ __nv_bfloat16 g_Pb[(size_t)BATCH * SEQ * SEQ];
__device__ __nv_bfloat16 g_qaTb[(size_t)NTOK * EMB];
__device__ __nv_bfloat16 g_qfb[(size_t)NTOK * NQD];
__device__ __nv_bfloat16 g_hb[(size_t)NTOK * FFD];
__device__ __nv_bfloat16 g_W1b[(size_t)FFD * NQD];
__device__ __nv_bfloat16 g_W2b[(size_t)EMB * FFD];

// ---------------------------------------------------------------------------
// Helpers
// ---------------------------------------------------------------------------
__device__ __forceinline__ uint32_t smem_u32(const void* p) {
    uint32_t a;
    asm("{ .reg .u64 t; cvta.to.shared.u64 t, %1; cvt.u32.u64 %0, t; }"
        : "=r"(a) : "l"(p));
    return a;
}

__device__ __forceinline__ float tf32r(float f) {
    unsigned r;
    asm("cvt.rna.tf32.f32 %0, %1;" : "=r"(r) : "f"(f));
    return __uint_as_float(r);
}

__device__ __forceinline__ void mma8(float* c, const unsigned* a, const unsigned* b) {
    asm volatile(
        "mma.sync.aligned.m16n8k8.row.col.f32.tf32.tf32.f32 "
        "{%0,%1,%2,%3},{%4,%5,%6,%7},{%8,%9},{%0,%1,%2,%3};"
        : "+f"(c[0]), "+f"(c[1]), "+f"(c[2]), "+f"(c[3])
        : "r"(a[0]), "r"(a[1]), "r"(a[2]), "r"(a[3]), "r"(b[0]), "r"(b[1]));
}

__device__ __forceinline__ void mma16(float* c, const unsigned* a, const unsigned* b) {
    asm volatile(
        "mma.sync.aligned.m16n8k16.row.col.f32.bf16.bf16.f32 "
        "{%0,%1,%2,%3},{%4,%5,%6,%7},{%8,%9},{%0,%1,%2,%3};"
        : "+f"(c[0]), "+f"(c[1]), "+f"(c[2]), "+f"(c[3])
        : "r"(a[0]), "r"(a[1]), "r"(a[2]), "r"(a[3]), "r"(b[0]), "r"(b[1]));
}

__device__ __forceinline__ void cp16(uint32_t dst, const void* src) {
    asm volatile("cp.async.cg.shared.global [%0], [%1], 16;" :: "r"(dst), "l"(src));
}
#define CP_COMMIT() asm volatile("cp.async.commit_group;" ::: "memory")

#define LDMX4(r, a) \
    asm volatile("ldmatrix.sync.aligned.m8n8.x4.shared.b16 {%0,%1,%2,%3}, [%4];" \
                 : "=r"((r)[0]), "=r"((r)[1]), "=r"((r)[2]), "=r"((r)[3]) : "r"(a))

// Epilogues: 0=none, 1=tf32r(cos(v+bias)), 2=v*scale, 3=relu(v+bias), 4=v+bias
template <int EPI>
__device__ __forceinline__ float epi_f(float v, const float* __restrict__ bias,
                                       int col, float scale) {
    if (EPI == 1) return tf32r(__cosf(v + bias[col]));
    if (EPI == 2) return v * scale;
    if (EPI == 3) return fmaxf(v + bias[col], 0.0f);
    if (EPI == 4) return v + bias[col];
    return v;
}

// Shared swizzle: 64B rows of 4x16B chunks, gray-code chunk rotation.
__device__ __forceinline__ uint32_t swz_off(int r, int c) {
    return (uint32_t)(r * 64 + ((c ^ ((r ^ (r >> 1)) & 3)) << 4));
}

#define BG_STAGE 24576
#define BG_SMEM  (3 * BG_STAGE)

// ---------------------------------------------------------------------------
// TF32 GEMM v2: cp.async + ldmatrix(b16 view), fp32 K-major operands.
// C = A @ B^T. CTA 128x256, BK=16, 3-stage, 8 warps 2x4, warp tile 64x64.
// NOTE: operands MUST be pre-rounded to tf32 (mma truncates raw fp32).
// ---------------------------------------------------------------------------
template <int EPI>
__global__ void __launch_bounds__(256, 1) tgemm2_kernel(
    const float* __restrict__ A, const float* __restrict__ B,
    float* __restrict__ C, int M, int N, int K,
    size_t sA, size_t sB, size_t sC,
    const float* __restrict__ bias, float scale) {
    extern __shared__ char smem[];
    const uint32_t sb = smem_u32(smem);

    A += (size_t)blockIdx.z * sA;
    B += (size_t)blockIdx.z * sB;
    C += (size_t)blockIdx.z * sC;

    const int bm = blockIdx.y * 128;
    const int bn = blockIdx.x * 256;
    const int tid = threadIdx.x;
    const int lane = tid & 31;
    const int wid = tid >> 5;
    const int wm = wid >> 2;
    const int wn = wid & 3;
    const int niter = K >> 4;

    float acc[4][8][4] = {};

    auto load_stage = [&](int it, int st) {
        uint32_t base = sb + st * BG_STAGE;
        const float* Ag = A + (size_t)bm * K + it * 16;
#pragma unroll
        for (int u = 0; u < 2; u++) {
            int q = u * 256 + tid;
            int r = q >> 2, c = q & 3;
            cp16(base + swz_off(r, c), Ag + (size_t)r * K + c * 4);
        }
        const float* Bg = B + (size_t)bn * K + it * 16;
#pragma unroll
        for (int u = 0; u < 4; u++) {
            int q = u * 256 + tid;
            int r = q >> 2, c = q & 3;
            cp16(base + 8192 + swz_off(r, c), Bg + (size_t)r * K + c * 4);
        }
        CP_COMMIT();
    };

    auto compute = [&](int st) {
        uint32_t Ab = sb + st * BG_STAGE;
        uint32_t Bb = Ab + 8192;
#pragma unroll
        for (int s = 0; s < 2; s++) {  // two k8 blocks per BK=16
            unsigned af[4][4], bf[8][2];
#pragma unroll
            for (int mi = 0; mi < 4; mi++) {
                int row = wm * 64 + mi * 16 + ((lane >> 3) & 1) * 8 + (lane & 7);
                int c = s * 2 + (lane >> 4);
                LDMX4(af[mi], Ab + swz_off(row, c));
            }
#pragma unroll
            for (int p = 0; p < 4; p++) {
                int row = wn * 64 + p * 16 + ((lane >> 4) << 3) + (lane & 7);
                int c = s * 2 + ((lane >> 3) & 1);
                unsigned t[4];
                LDMX4(t, Bb + swz_off(row, c));
                bf[2 * p][0] = t[0];
                bf[2 * p][1] = t[1];
                bf[2 * p + 1][0] = t[2];
                bf[2 * p + 1][1] = t[3];
            }
#pragma unroll
            for (int mi = 0; mi < 4; mi++)
#pragma unroll
                for (int ni = 0; ni < 8; ni++)
                    mma8(acc[mi][ni], af[mi], bf[ni]);
        }
    };

    load_stage(0, 0);
    if (niter > 1) load_stage(1, 1);
    else CP_COMMIT();

    int cur = 0;
    for (int it = 0; it < niter; it++) {
        asm volatile("cp.async.wait_group 1;" ::: "memory");
        __syncthreads();
        compute(cur);
        if (it + 2 < niter) {
            int nst = cur - 1;
            if (nst < 0) nst = 2;
            load_stage(it + 2, nst);
        } else {
            CP_COMMIT();
        }
        cur = (cur == 2) ? 0 : cur + 1;
    }

    const int g = lane >> 2;
    const int tg = lane & 3;
#pragma unroll
    for (int mi = 0; mi < 4; ++mi) {
        int row = bm + wm * 64 + mi * 16 + g;
#pragma unroll
        for (int ni = 0; ni < 8; ++ni) {
            int col = bn + wn * 64 + ni * 8 + tg * 2;
            const float* a = acc[mi][ni];
            float2 lo, hi;
            lo.x = epi_f<EPI>(a[0], bias, col + 0, scale);
            lo.y = epi_f<EPI>(a[1], bias, col + 1, scale);
            hi.x = epi_f<EPI>(a[2], bias, col + 0, scale);
            hi.y = epi_f<EPI>(a[3], bias, col + 1, scale);
            *(float2*)(C + (size_t)row * N + col) = lo;
            *(float2*)(C + (size_t)(row + 8) * N + col) = hi;
        }
    }
}

// ---------------------------------------------------------------------------
// BF16 GEMM v2: cp.async + ldmatrix, bf16 gmem operands (K-major both).
// CTA 128x256, BK=32, 3-stage pipeline, 8 warps 2x4, warp tile 64x64.
// ---------------------------------------------------------------------------
template <int EPI, bool OUTBF>
__global__ void __launch_bounds__(256, 1) bgemm2_kernel(
    const __nv_bfloat16* __restrict__ A, const __nv_bfloat16* __restrict__ B,
    void* __restrict__ Cv, int M, int N, int K,
    size_t sA, size_t sB, size_t sC,
    const float* __restrict__ bias, float scale) {
    extern __shared__ char smem[];
    const uint32_t sb = smem_u32(smem);

    A += (size_t)blockIdx.z * sA;
    B += (size_t)blockIdx.z * sB;

    const int bm = blockIdx.y * 128;
    const int bn = blockIdx.x * 256;
    const int tid = threadIdx.x;
    const int lane = tid & 31;
    const int wid = tid >> 5;
    const int wm = wid >> 2;
    const int wn = wid & 3;
    const int niter = K >> 5;

    float acc[4][8][4] = {};

    auto load_stage = [&](int it, int st) {
        uint32_t base = sb + st * BG_STAGE;
        const __nv_bfloat16* Ag = A + (size_t)bm * K + it * 32;
#pragma unroll
        for (int u = 0; u < 2; u++) {
            int q = u * 256 + tid;
            int r = q >> 2, c = q & 3;
            cp16(base + swz_off(r, c), Ag + (size_t)r * K + c * 8);
        }
        const __nv_bfloat16* Bg = B + (size_t)bn * K + it * 32;
#pragma unroll
        for (int u = 0; u < 4; u++) {
            int q = u * 256 + tid;
            int r = q >> 2, c = q & 3;
            cp16(base + 8192 + swz_off(r, c), Bg + (size_t)r * K + c * 8);
        }
        CP_COMMIT();
    };

    auto compute = [&](int st) {
        uint32_t Ab = sb + st * BG_STAGE;
        uint32_t Bb = Ab + 8192;
#pragma unroll
        for (int s = 0; s < 2; s++) {
            unsigned af[4][4], bf[8][2];
#pragma unroll
            for (int mi = 0; mi < 4; mi++) {
                int row = wm * 64 + mi * 16 + ((lane >> 3) & 1) * 8 + (lane & 7);
                int c = s * 2 + (lane >> 4);
                LDMX4(af[mi], Ab + swz_off(row, c));
            }
#pragma unroll
            for (int p = 0; p < 4; p++) {
                int row = wn * 64 + p * 16 + ((lane >> 4) << 3) + (lane & 7);
                int c = s * 2 + ((lane >> 3) & 1);
                unsigned t[4];
                LDMX4(t, Bb + swz_off(row, c));
                bf[2 * p][0] = t[0];
                bf[2 * p][1] = t[1];
                bf[2 * p + 1][0] = t[2];
                bf[2 * p + 1][1] = t[3];
            }
#pragma unroll
            for (int mi = 0; mi < 4; mi++)
#pragma unroll
                for (int ni = 0; ni < 8; ni++)
                    mma16(acc[mi][ni], af[mi], bf[ni]);
        }
    };

    load_stage(0, 0);
    if (niter > 1) load_stage(1, 1);
    else CP_COMMIT();

    int cur = 0;
    for (int it = 0; it < niter; it++) {
        asm volatile("cp.async.wait_group 1;" ::: "memory");
        __syncthreads();
        compute(cur);
        if (it + 2 < niter) {
            int nst = cur - 1;
            if (nst < 0) nst = 2;
            load_stage(it + 2, nst);
        } else {
            CP_COMMIT();
        }
        cur = (cur == 2) ? 0 : cur + 1;
    }

    const int g = lane >> 2;
    const int tg = lane & 3;
#pragma unroll
    for (int mi = 0; mi < 4; ++mi) {
        int row = bm + wm * 64 + mi * 16 + g;
#pragma unroll
        for (int ni = 0; ni < 8; ++ni) {
            int col = bn + wn * 64 + ni * 8 + tg * 2;
            const float* a = acc[mi][ni];
            float e0 = epi_f<EPI>(a[0], bias, col + 0, scale);
            float e1 = epi_f<EPI>(a[1], bias, col + 1, scale);
            float e2 = epi_f<EPI>(a[2], bias, col + 0, scale);
            float e3 = epi_f<EPI>(a[3], bias, col + 1, scale);
            if (OUTBF) {
                __nv_bfloat16* C = (__nv_bfloat16*)Cv + (size_t)blockIdx.z * sC;
                *(__nv_bfloat162*)(C + (size_t)row * N + col) =
                    __float22bfloat162_rn(make_float2(e0, e1));
                *(__nv_bfloat162*)(C + (size_t)(row + 8) * N + col) =
                    __float22bfloat162_rn(make_float2(e2, e3));
            } else {
                float* C = (float*)Cv + (size_t)blockIdx.z * sC;
                *(float2*)(C + (size_t)row * N + col) = make_float2(e0, e1);
                *(float2*)(C + (size_t)(row + 8) * N + col) = make_float2(e2, e3);
            }
        }
    }
}

// ---------------------------------------------------------------------------
// 32x32 tiled transpose per batch, bf16 out: out[b][e][t] = bf16(in[b][t][e])
// ---------------------------------------------------------------------------
__global__ void __launch_bounds__(256) transpose_kernel(
    const float* __restrict__ in, __nv_bfloat16* __restrict__ out) {
    __shared__ float t[32][33];
    const int b = blockIdx.z;
    const int t0 = blockIdx.x * 32;
    const int e0 = blockIdx.y * 32;
    const int lx = threadIdx.x & 31, ly = threadIdx.x >> 5;
#pragma unroll
    for (int r = 0; r < 32; r += 8)
        t[ly + r][lx] = in[((size_t)b * SEQ + t0 + ly + r) * EMB + e0 + lx];
    __syncthreads();
#pragma unroll
    for (int r = 0; r < 32; r += 8)
        out[((size_t)b * EMB + e0 + ly + r) * SEQ + t0 + lx] =
            __float2bfloat16(t[lx][ly + r]);
}

// ---------------------------------------------------------------------------
// Row softmax (reads fp32 scores, writes bf16 P), row length 2048.
// ---------------------------------------------------------------------------
__global__ void __launch_bounds__(256) softmax2048_kernel(
    const float* __restrict__ S, __nv_bfloat16* __restrict__ P) {
    const float* p = S + (size_t)blockIdx.x * SEQ;
    __nv_bfloat16* o = P + (size_t)blockIdx.x * SEQ;
    const int tid = threadIdx.x;
    __shared__ float sh[8];

    float v[8];
    float m = -1e30f;
#pragma unroll
    for (int i = 0; i < 8; i++) {
        v[i] = p[tid + i * 256];
        m = fmaxf(m, v[i]);
    }
#pragma unroll
    for (int o2 = 16; o2 > 0; o2 >>= 1) m = fmaxf(m, __shfl_xor_sync(~0u, m, o2));
    if ((tid & 31) == 0) sh[tid >> 5] = m;
    __syncthreads();
    m = sh[0];
#pragma unroll
    for (int w = 1; w < 8; w++) m = fmaxf(m, sh[w]);

    float s = 0.0f;
#pragma unroll
    for (int i = 0; i < 8; i++) {
        v[i] = __expf(v[i] - m);
        s += v[i];
    }
    __syncthreads();
#pragma unroll
    for (int o2 = 16; o2 > 0; o2 >>= 1) s += __shfl_xor_sync(~0u, s, o2);
    if ((tid & 31) == 0) sh[tid >> 5] = s;
    __syncthreads();
    s = 0.0f;
#pragma unroll
    for (int w = 0; w < 8; w++) s += sh[w];
    float inv = 1.0f / s;
#pragma unroll
    for (int i = 0; i < 8; i++) o[tid + i * 256] = __float2bfloat16(v[i] * inv);
}

// ---------------------------------------------------------------------------
// out = LayerNorm(X + Y) * g + b, row length 768; optionally fused qf output:
// qf[row, c] = bf16(cos(out[c] + th[c])) for c < 128.
// ---------------------------------------------------------------------------
template <bool QF>
__global__ void __launch_bounds__(256) add_ln_kernel(
    const float* __restrict__ X, const float* __restrict__ Y,
    const float* __restrict__ g, const float* __restrict__ b,
    float* __restrict__ out, const float* __restrict__ th,
    __nv_bfloat16* __restrict__ qf) {
    const size_t row = blockIdx.x;
    const float* xp = X + row * EMB;
    const float* yp = Y + row * EMB;
    float* op = out + row * EMB;
    const int tid = threadIdx.x;
    __shared__ float sh[8];

    float v[3];
    float s = 0.0f;
#pragma unroll
    for (int i = 0; i < 3; i++) {
        int c = tid + i * 256;
        v[i] = xp[c] + yp[c];
        s += v[i];
    }
#pragma unroll
    for (int o = 16; o > 0; o >>= 1) s += __shfl_xor_sync(~0u, s, o);
    if ((tid & 31) == 0) sh[tid >> 5] = s;
    __syncthreads();
    s = 0.0f;
#pragma unroll
    for (int w = 0; w < 8; w++) s += sh[w];
    const float mean = s * (1.0f / EMB);

    float q = 0.0f;
#pragma unroll
    for (int i = 0; i < 3; i++) {
        float d = v[i] - mean;
        q += d * d;
    }
    __syncthreads();
#pragma unroll
    for (int o = 16; o > 0; o >>= 1) q += __shfl_xor_sync(~0u, q, o);
    if ((tid & 31) == 0) sh[tid >> 5] = q;
    __syncthreads();
    q = 0.0f;
#pragma unroll
    for (int w = 0; w < 8; w++) q += sh[w];
    const float rs = rsqrtf(q * (1.0f / EMB) + 1e-5f);

#pragma unroll
    for (int i = 0; i < 3; i++) {
        int c = tid + i * 256;
        float r = (v[i] - mean) * rs * g[c] + b[c];
        op[c] = r;
        if (QF && i == 0 && c < NQD)
            qf[row * NQD + c] = __float2bfloat16(__cosf(r + th[c]));
    }
}

// ---------------------------------------------------------------------------
// fp32 -> bf16 convert (n multiple of 1024)
// ---------------------------------------------------------------------------
__global__ void __launch_bounds__(256) cvt_kernel(
    const float* __restrict__ in, __nv_bfloat16* __restrict__ out) {
    int i = blockIdx.x * 256 + threadIdx.x;
    float4 v = *(const float4*)(in + (size_t)i * 4);
    *(__nv_bfloat162*)(out + (size_t)i * 4) =
        __float22bfloat162_rn(make_float2(v.x, v.y));
    *(__nv_bfloat162*)(out + (size_t)i * 4 + 2) =
        __float22bfloat162_rn(make_float2(v.z, v.w));
}

// ---------------------------------------------------------------------------
// fp32 -> tf32(rna)-in-fp32 convert (n multiple of 1024)
// ---------------------------------------------------------------------------
__global__ void __launch_bounds__(256) cvt_tf32_kernel(
    const float* __restrict__ in, float* __restrict__ out) {
    int i = blockIdx.x * 256 + threadIdx.x;
    float4 v = *(const float4*)(in + (size_t)i * 4);
    v.x = tf32r(v.x);
    v.y = tf32r(v.y);
    v.z = tf32r(v.z);
    v.w = tf32r(v.w);
    *(float4*)(out + (size_t)i * 4) = v;
}

// ---------------------------------------------------------------------------
// Launch
// ---------------------------------------------------------------------------
extern "C" void kernel_launch(void* const* d_in, const int* in_sizes, int n_in,
                              void* d_out, int out_size) {
    const float* x     = (const float*)d_in[0];
    const float* Wp    = (const float*)d_in[1];
    const float* th_rx = (const float*)d_in[2];
    const float* th_ry = (const float*)d_in[3];
    const float* W1    = (const float*)d_in[4];
    const float* b1    = (const float*)d_in[5];
    const float* W2    = (const float*)d_in[6];
    const float* b2    = (const float*)d_in[7];
    const float* ln1g  = (const float*)d_in[8];
    const float* ln1b  = (const float*)d_in[9];
    const float* ln2g  = (const float*)d_in[10];
    const float* ln2b  = (const float*)d_in[11];
    float* out = (float*)d_out;

    float *qa, *sc, *x1, *tmp, *xr, *Wpr;
    __nv_bfloat16 *Pb, *qaTb, *qfb, *hb, *W1b, *W2b;
    cudaGetSymbolAddress((void**)&qa, g_qa);
    cudaGetSymbolAddress((void**)&sc, g_scores);
    cudaGetSymbolAddress((void**)&x1, g_x1);
    cudaGetSymbolAddress((void**)&tmp, g_tmp);
    cudaGetSymbolAddress((void**)&xr, g_xr);
    cudaGetSymbolAddress((void**)&Wpr, g_Wpr);
    cudaGetSymbolAddress((void**)&Pb, g_Pb);
    cudaGetSymbolAddress((void**)&qaTb, g_qaTb);
    cudaGetSymbolAddress((void**)&qfb, g_qfb);
    cudaGetSymbolAddress((void**)&hb, g_hb);
    cudaGetSymbolAddress((void**)&W1b, g_W1b);
    cudaGetSymbolAddress((void**)&W2b, g_W2b);

    cudaFuncSetAttribute(tgemm2_kernel<1>,
                         cudaFuncAttributeMaxDynamicSharedMemorySize, BG_SMEM);
    cudaFuncSetAttribute(tgemm2_kernel<2>,
                         cudaFuncAttributeMaxDynamicSharedMemorySize, BG_SMEM);
    cudaFuncSetAttribute(bgemm2_kernel<0, false>,
                         cudaFuncAttributeMaxDynamicSharedMemorySize, BG_SMEM);
    cudaFuncSetAttribute(bgemm2_kernel<3, true>,
                         cudaFuncAttributeMaxDynamicSharedMemorySize, BG_SMEM);
    cudaFuncSetAttribute(bgemm2_kernel<4, false>,
                         cudaFuncAttributeMaxDynamicSharedMemorySize, BG_SMEM);

    dim3 blk(256);

    // 0. operand conversions
    cvt_kernel<<<(FFD * NQD) / 1024, blk>>>(W1, W1b);
    cvt_kernel<<<(EMB * FFD) / 1024, blk>>>(W2, W2b);
    cvt_tf32_kernel<<<(NTOK * EMB) / 1024, blk>>>(x, xr);
    cvt_tf32_kernel<<<(EMB * EMB) / 1024, blk>>>(Wp, Wpr);

    // 1. qa = tf32r(cos(xr @ Wpr^T + theta_rx))  [16384,768]  (TF32 v2)
    tgemm2_kernel<1><<<dim3(EMB / 256, NTOK / 128, 1), blk, BG_SMEM>>>(
        xr, Wpr, qa, NTOK, EMB, EMB, 0, 0, 0, th_rx, 0.0f);

    // 1b. qaTb[b][e][t] = bf16(qa[b][t][e])
    transpose_kernel<<<dim3(SEQ / 32, EMB / 32, BATCH), blk>>>(qa, qaTb);

    // 2. scores = qa @ qa^T / sqrt(8), batched (TF32 v2; qa pre-rounded)
    tgemm2_kernel<2><<<dim3(SEQ / 256, SEQ / 128, BATCH), blk, BG_SMEM>>>(
        qa, qa, sc, SEQ, SEQ, EMB,
        (size_t)SEQ * EMB, (size_t)SEQ * EMB, (size_t)SEQ * SEQ,
        nullptr, 0.35355339059327373f);

    // 3. softmax rows -> bf16 P
    softmax2048_kernel<<<NTOK, blk>>>(sc, Pb);

    // 4. attn_out = P @ qa (bf16 pipeline), batched
    bgemm2_kernel<0, false><<<dim3(EMB / 256, SEQ / 128, BATCH), blk, BG_SMEM>>>(
        Pb, qaTb, tmp, SEQ, EMB, SEQ,
        (size_t)SEQ * SEQ, (size_t)EMB * SEQ, (size_t)SEQ * EMB,
        nullptr, 0.0f);

    // 5. x1 = LN(x + attn_out), fused qf = bf16(cos(x1[:, :128] + theta_ry))
    add_ln_kernel<true><<<NTOK, blk>>>(x, tmp, ln1g, ln1b, x1, th_ry, qfb);

    // 7. h = relu(qf @ W1^T + b1) -> bf16  [16384,3072], K=128
    bgemm2_kernel<3, true><<<dim3(FFD / 256, NTOK / 128, 1), blk, BG_SMEM>>>(
        qfb, W1b, hb, NTOK, FFD, NQD, 0, 0, 0, b1, 0.0f);

    // 8. ffn_out = h @ W2^T + b2  [16384,768], K=3072
    bgemm2_kernel<4, false><<<dim3(EMB / 256, NTOK / 128, 1), blk, BG_SMEM>>>(
        hb, W2b, tmp, NTOK, EMB, FFD, 0, 0, 0, b2, 0.0f);

    // 9. out = LN(x1 + ffn_out)
    add_ln_kernel<false><<<NTOK, blk>>>(x1, tmp, ln2g, ln2b, out, nullptr, nullptr);
}

// round 11
// speedup vs baseline: 5.8091x; 1.1211x over previous
#include <cuda_runtime.h>
#include <cuda_bf16.h>
#include <cstdint>
#include <math.h>

// Problem constants
#define NTOK 16384      // B*S
#define BATCH 8
#define SEQ 2048
#define EMB 768
#define FFD 3072
#define NQD 128

// ---------------------------------------------------------------------------
// Scratch (device globals; no allocation allowed)
// ---------------------------------------------------------------------------
__device__ float g_qa[(size_t)NTOK * EMB];
__device__ float g_scores[(size_t)BATCH * SEQ * SEQ];
__device__ float g_x1[(size_t)NTOK * EMB];
__device__ float g_tmp[(size_t)NTOK * EMB];
__device__ float g_xr[(size_t)NTOK * EMB];            // tf32-rounded x
__device__ float g_Wpr[(size_t)EMB * EMB];            // tf32-rounded Wp
__device__ __nv_bfloat16 g_Pb[(size_t)BATCH * SEQ * SEQ];
__device__ __nv_bfloat16 g_qaTb[(size_t)NTOK * EMB];
__device__ __nv_bfloat16 g_qfb[(size_t)NTOK * NQD];
__device__ __nv_bfloat16 g_hb[(size_t)NTOK * FFD];
__device__ __nv_bfloat16 g_W1b[(size_t)FFD * NQD];
__device__ __nv_bfloat16 g_W2b[(size_t)EMB * FFD];

// ---------------------------------------------------------------------------
// Helpers
// ---------------------------------------------------------------------------
__device__ __forceinline__ uint32_t smem_u32(const void* p) {
    uint32_t a;
    asm("{ .reg .u64 t; cvta.to.shared.u64 t, %1; cvt.u32.u64 %0, t; }"
        : "=r"(a) : "l"(p));
    return a;
}

__device__ __forceinline__ float tf32r(float f) {
    unsigned r;
    asm("cvt.rna.tf32.f32 %0, %1;" : "=r"(r) : "f"(f));
    return __uint_as_float(r);
}

__device__ __forceinline__ void mma8(float* c, const unsigned* a, const unsigned* b) {
    asm volatile(
        "mma.sync.aligned.m16n8k8.row.col.f32.tf32.tf32.f32 "
        "{%0,%1,%2,%3},{%4,%5,%6,%7},{%8,%9},{%0,%1,%2,%3};"
        : "+f"(c[0]), "+f"(c[1]), "+f"(c[2]), "+f"(c[3])
        : "r"(a[0]), "r"(a[1]), "r"(a[2]), "r"(a[3]), "r"(b[0]), "r"(b[1]));
}

__device__ __forceinline__ void mma16(float* c, const unsigned* a, const unsigned* b) {
    asm volatile(
        "mma.sync.aligned.m16n8k16.row.col.f32.bf16.bf16.f32 "
        "{%0,%1,%2,%3},{%4,%5,%6,%7},{%8,%9},{%0,%1,%2,%3};"
        : "+f"(c[0]), "+f"(c[1]), "+f"(c[2]), "+f"(c[3])
        : "r"(a[0]), "r"(a[1]), "r"(a[2]), "r"(a[3]), "r"(b[0]), "r"(b[1]));
}

__device__ __forceinline__ void cp16(uint32_t dst, const void* src) {
    asm volatile("cp.async.cg.shared.global [%0], [%1], 16;" :: "r"(dst), "l"(src));
}
#define CP_COMMIT() asm volatile("cp.async.commit_group;" ::: "memory")
#define CP_WAIT2()  asm volatile("cp.async.wait_group 2;" ::: "memory")

#define LDMX4(r, a) \
    asm volatile("ldmatrix.sync.aligned.m8n8.x4.shared.b16 {%0,%1,%2,%3}, [%4];" \
                 : "=r"((r)[0]), "=r"((r)[1]), "=r"((r)[2]), "=r"((r)[3]) : "r"(a))

// Epilogues: 0=none, 1=tf32r(cos(v+bias)), 2=v*scale, 3=relu(v+bias), 4=v+bias
template <int EPI>
__device__ __forceinline__ float epi_f(float v, const float* __restrict__ bias,
                                       int col, float scale) {
    if (EPI == 1) return tf32r(__cosf(v + bias[col]));
    if (EPI == 2) return v * scale;
    if (EPI == 3) return fmaxf(v + bias[col], 0.0f);
    if (EPI == 4) return v + bias[col];
    return v;
}

// Shared swizzle: 64B rows of 4x16B chunks, gray-code chunk rotation.
__device__ __forceinline__ uint32_t swz_off(int r, int c) {
    return (uint32_t)(r * 64 + ((c ^ ((r ^ (r >> 1)) & 3)) << 4));
}

#define BG_STAGE 24576
#define NSTAGE 4
#define BG_SMEM  (NSTAGE * BG_STAGE)

// ---------------------------------------------------------------------------
// TF32 GEMM v2: cp.async + ldmatrix(b16 view), fp32 K-major operands.
// C = A @ B^T. CTA 128x256, BK=16, 4-stage, 8 warps 2x4, warp tile 64x64.
// Operands MUST be pre-rounded to tf32 (mma truncates raw fp32).
// SYM: C is symmetric (A==B); blockIdx.x enumerates 72 lower tiles/batch,
// below-diagonal tiles also scatter their transpose (exact cover proof in
// round-10 notes: my>=2nx direct + my>=2nx+2 mirrors tile the full matrix).
// ---------------------------------------------------------------------------
template <int EPI, bool SYM>
__global__ void __launch_bounds__(256, 1) tgemm2_kernel(
    const float* __restrict__ A, const float* __restrict__ B,
    float* __restrict__ C, int M, int N, int K,
    size_t sA, size_t sB, size_t sC,
    const float* __restrict__ bias, float scale) {
    extern __shared__ char smem[];
    const uint32_t sb = smem_u32(smem);

    A += (size_t)blockIdx.z * sA;
    B += (size_t)blockIdx.z * sB;
    C += (size_t)blockIdx.z * sC;

    int bm, bn, tt = 0;
    if (SYM) {
        int t = blockIdx.x, nx = 0;
        while (t >= 16 - 2 * nx) { t -= 16 - 2 * nx; nx++; }
        tt = t;                      // my = 2nx + t
        bm = (2 * nx + t) * 128;
        bn = nx * 256;
    } else {
        bm = blockIdx.y * 128;
        bn = blockIdx.x * 256;
    }

    const int tid = threadIdx.x;
    const int lane = tid & 31;
    const int wid = tid >> 5;
    const int wm = wid >> 2;
    const int wn = wid & 3;
    const int niter = K >> 4;

    float acc[4][8][4] = {};

    auto load_stage = [&](int it, int st) {
        uint32_t base = sb + st * BG_STAGE;
        const float* Ag = A + (size_t)bm * K + it * 16;
#pragma unroll
        for (int u = 0; u < 2; u++) {
            int q = u * 256 + tid;
            int r = q >> 2, c = q & 3;
            cp16(base + swz_off(r, c), Ag + (size_t)r * K + c * 4);
        }
        const float* Bg = B + (size_t)bn * K + it * 16;
#pragma unroll
        for (int u = 0; u < 4; u++) {
            int q = u * 256 + tid;
            int r = q >> 2, c = q & 3;
            cp16(base + 8192 + swz_off(r, c), Bg + (size_t)r * K + c * 4);
        }
        CP_COMMIT();
    };

    auto compute = [&](int st) {
        uint32_t Ab = sb + st * BG_STAGE;
        uint32_t Bb = Ab + 8192;
#pragma unroll
        for (int s = 0; s < 2; s++) {  // two k8 blocks per BK=16
            unsigned af[4][4], bf[8][2];
#pragma unroll
            for (int mi = 0; mi < 4; mi++) {
                int row = wm * 64 + mi * 16 + ((lane >> 3) & 1) * 8 + (lane & 7);
                int c = s * 2 + (lane >> 4);
                LDMX4(af[mi], Ab + swz_off(row, c));
            }
#pragma unroll
            for (int p = 0; p < 4; p++) {
                int row = wn * 64 + p * 16 + ((lane >> 4) << 3) + (lane & 7);
                int c = s * 2 + ((lane >> 3) & 1);
                unsigned t[4];
                LDMX4(t, Bb + swz_off(row, c));
                bf[2 * p][0] = t[0];
                bf[2 * p][1] = t[1];
                bf[2 * p + 1][0] = t[2];
                bf[2 * p + 1][1] = t[3];
            }
#pragma unroll
            for (int mi = 0; mi < 4; mi++)
#pragma unroll
                for (int ni = 0; ni < 8; ni++)
                    mma8(acc[mi][ni], af[mi], bf[ni]);
        }
    };

#pragma unroll
    for (int i = 0; i < NSTAGE - 1; i++) {
        if (i < niter) load_stage(i, i);
        else CP_COMMIT();
    }

    int cur = 0;
    for (int it = 0; it < niter; it++) {
        CP_WAIT2();
        __syncthreads();
        compute(cur);
        if (it + NSTAGE - 1 < niter) {
            int nst = cur + NSTAGE - 1;
            if (nst >= NSTAGE) nst -= NSTAGE;
            load_stage(it + NSTAGE - 1, nst);
        } else {
            CP_COMMIT();
        }
        cur = (cur == NSTAGE - 1) ? 0 : cur + 1;
    }

    const int g = lane >> 2;
    const int tg = lane & 3;
#pragma unroll
    for (int mi = 0; mi < 4; ++mi) {
        int row = bm + wm * 64 + mi * 16 + g;
#pragma unroll
        for (int ni = 0; ni < 8; ++ni) {
            int col = bn + wn * 64 + ni * 8 + tg * 2;
            const float* a = acc[mi][ni];
            float e0 = epi_f<EPI>(a[0], bias, col + 0, scale);
            float e1 = epi_f<EPI>(a[1], bias, col + 1, scale);
            float e2 = epi_f<EPI>(a[2], bias, col + 0, scale);
            float e3 = epi_f<EPI>(a[3], bias, col + 1, scale);
            *(float2*)(C + (size_t)row * N + col) = make_float2(e0, e1);
            *(float2*)(C + (size_t)(row + 8) * N + col) = make_float2(e2, e3);
            if (SYM && tt >= 2) {  // strictly below diagonal: mirror transpose
                C[(size_t)(col + 0) * N + row] = e0;
                C[(size_t)(col + 1) * N + row] = e1;
                C[(size_t)(col + 0) * N + row + 8] = e2;
                C[(size_t)(col + 1) * N + row + 8] = e3;
            }
        }
    }
}

// ---------------------------------------------------------------------------
// BF16 GEMM v2: cp.async + ldmatrix, bf16 gmem operands (K-major both).
// CTA 128x256, BK=32, 4-stage pipeline, 8 warps 2x4, warp tile 64x64.
// ---------------------------------------------------------------------------
template <int EPI, bool OUTBF>
__global__ void __launch_bounds__(256, 1) bgemm2_kernel(
    const __nv_bfloat16* __restrict__ A, const __nv_bfloat16* __restrict__ B,
    void* __restrict__ Cv, int M, int N, int K,
    size_t sA, size_t sB, size_t sC,
    const float* __restrict__ bias, float scale) {
    extern __shared__ char smem[];
    const uint32_t sb = smem_u32(smem);

    A += (size_t)blockIdx.z * sA;
    B += (size_t)blockIdx.z * sB;

    const int bm = blockIdx.y * 128;
    const int bn = blockIdx.x * 256;
    const int tid = threadIdx.x;
    const int lane = tid & 31;
    const int wid = tid >> 5;
    const int wm = wid >> 2;
    const int wn = wid & 3;
    const int niter = K >> 5;

    float acc[4][8][4] = {};

    auto load_stage = [&](int it, int st) {
        uint32_t base = sb + st * BG_STAGE;
        const __nv_bfloat16* Ag = A + (size_t)bm * K + it * 32;
#pragma unroll
        for (int u = 0; u < 2; u++) {
            int q = u * 256 + tid;
            int r = q >> 2, c = q & 3;
            cp16(base + swz_off(r, c), Ag + (size_t)r * K + c * 8);
        }
        const __nv_bfloat16* Bg = B + (size_t)bn * K + it * 32;
#pragma unroll
        for (int u = 0; u < 4; u++) {
            int q = u * 256 + tid;
            int r = q >> 2, c = q & 3;
            cp16(base + 8192 + swz_off(r, c), Bg + (size_t)r * K + c * 8);
        }
        CP_COMMIT();
    };

    auto compute = [&](int st) {
        uint32_t Ab = sb + st * BG_STAGE;
        uint32_t Bb = Ab + 8192;
#pragma unroll
        for (int s = 0; s < 2; s++) {
            unsigned af[4][4], bf[8][2];
#pragma unroll
            for (int mi = 0; mi < 4; mi++) {
                int row = wm * 64 + mi * 16 + ((lane >> 3) & 1) * 8 + (lane & 7);
                int c = s * 2 + (lane >> 4);
                LDMX4(af[mi], Ab + swz_off(row, c));
            }
#pragma unroll
            for (int p = 0; p < 4; p++) {
                int row = wn * 64 + p * 16 + ((lane >> 4) << 3) + (lane & 7);
                int c = s * 2 + ((lane >> 3) & 1);
                unsigned t[4];
                LDMX4(t, Bb + swz_off(row, c));
                bf[2 * p][0] = t[0];
                bf[2 * p][1] = t[1];
                bf[2 * p + 1][0] = t[2];
                bf[2 * p + 1][1] = t[3];
            }
#pragma unroll
            for (int mi = 0; mi < 4; mi++)
#pragma unroll
                for (int ni = 0; ni < 8; ni++)
                    mma16(acc[mi][ni], af[mi], bf[ni]);
        }
    };

#pragma unroll
    for (int i = 0; i < NSTAGE - 1; i++) {
        if (i < niter) load_stage(i, i);
        else CP_COMMIT();
    }

    int cur = 0;
    for (int it = 0; it < niter; it++) {
        CP_WAIT2();
        __syncthreads();
        compute(cur);
        if (it + NSTAGE - 1 < niter) {
            int nst = cur + NSTAGE - 1;
            if (nst >= NSTAGE) nst -= NSTAGE;
            load_stage(it + NSTAGE - 1, nst);
        } else {
            CP_COMMIT();
        }
        cur = (cur == NSTAGE - 1) ? 0 : cur + 1;
    }

    const int g = lane >> 2;
    const int tg = lane & 3;
#pragma unroll
    for (int mi = 0; mi < 4; ++mi) {
        int row = bm + wm * 64 + mi * 16 + g;
#pragma unroll
        for (int ni = 0; ni < 8; ++ni) {
            int col = bn + wn * 64 + ni * 8 + tg * 2;
            const float* a = acc[mi][ni];
            float e0 = epi_f<EPI>(a[0], bias, col + 0, scale);
            float e1 = epi_f<EPI>(a[1], bias, col + 1, scale);
            float e2 = epi_f<EPI>(a[2], bias, col + 0, scale);
            float e3 = epi_f<EPI>(a[3], bias, col + 1, scale);
            if (OUTBF) {
                __nv_bfloat16* C = (__nv_bfloat16*)Cv + (size_t)blockIdx.z * sC;
                *(__nv_bfloat162*)(C + (size_t)row * N + col) =
                    __float22bfloat162_rn(make_float2(e0, e1));
                *(__nv_bfloat162*)(C + (size_t)(row + 8) * N + col) =
                    __float22bfloat162_rn(make_float2(e2, e3));
            } else {
                float* C = (float*)Cv + (size_t)blockIdx.z * sC;
                *(float2*)(C + (size_t)row * N + col) = make_float2(e0, e1);
                *(float2*)(C + (size_t)(row + 8) * N + col) = make_float2(e2, e3);
            }
        }
    }
}

// ---------------------------------------------------------------------------
// 32x32 tiled transpose per batch, bf16 out: out[b][e][t] = bf16(in[b][t][e])
// ---------------------------------------------------------------------------
__global__ void __launch_bounds__(256) transpose_kernel(
    const float* __restrict__ in, __nv_bfloat16* __restrict__ out) {
    __shared__ float t[32][33];
    const int b = blockIdx.z;
    const int t0 = blockIdx.x * 32;
    const int e0 = blockIdx.y * 32;
    const int lx = threadIdx.x & 31, ly = threadIdx.x >> 5;
#pragma unroll
    for (int r = 0; r < 32; r += 8)
        t[ly + r][lx] = in[((size_t)b * SEQ + t0 + ly + r) * EMB + e0 + lx];
    __syncthreads();
#pragma unroll
    for (int r = 0; r < 32; r += 8)
        out[((size_t)b * EMB + e0 + ly + r) * SEQ + t0 + lx] =
            __float2bfloat16(t[lx][ly + r]);
}

// ---------------------------------------------------------------------------
// Row softmax (reads fp32 scores, writes bf16 P), row length 2048.
// ---------------------------------------------------------------------------
__global__ void __launch_bounds__(256) softmax2048_kernel(
    const float* __restrict__ S, __nv_bfloat16* __restrict__ P) {
    const float* p = S + (size_t)blockIdx.x * SEQ;
    __nv_bfloat16* o = P + (size_t)blockIdx.x * SEQ;
    const int tid = threadIdx.x;
    __shared__ float sh[8];

    float v[8];
    float m = -1e30f;
#pragma unroll
    for (int i = 0; i < 8; i++) {
        v[i] = p[tid + i * 256];
        m = fmaxf(m, v[i]);
    }
#pragma unroll
    for (int o2 = 16; o2 > 0; o2 >>= 1) m = fmaxf(m, __shfl_xor_sync(~0u, m, o2));
    if ((tid & 31) == 0) sh[tid >> 5] = m;
    __syncthreads();
    m = sh[0];
#pragma unroll
    for (int w = 1; w < 8; w++) m = fmaxf(m, sh[w]);

    float s = 0.0f;
#pragma unroll
    for (int i = 0; i < 8; i++) {
        v[i] = __expf(v[i] - m);
        s += v[i];
    }
    __syncthreads();
#pragma unroll
    for (int o2 = 16; o2 > 0; o2 >>= 1) s += __shfl_xor_sync(~0u, s, o2);
    if ((tid & 31) == 0) sh[tid >> 5] = s;
    __syncthreads();
    s = 0.0f;
#pragma unroll
    for (int w = 0; w < 8; w++) s += sh[w];
    float inv = 1.0f / s;
#pragma unroll
    for (int i = 0; i < 8; i++) o[tid + i * 256] = __float2bfloat16(v[i] * inv);
}

// ---------------------------------------------------------------------------
// out = LayerNorm(X + Y) * g + b, row length 768; optionally fused qf output:
// qf[row, c] = bf16(cos(out[c] + th[c])) for c < 128.
// ---------------------------------------------------------------------------
template <bool QF>
__global__ void __launch_bounds__(256) add_ln_kernel(
    const float* __restrict__ X, const float* __restrict__ Y,
    const float* __restrict__ g, const float* __restrict__ b,
    float* __restrict__ out, const float* __restrict__ th,
    __nv_bfloat16* __restrict__ qf) {
    const size_t row = blockIdx.x;
    const float* xp = X + row * EMB;
    const float* yp = Y + row * EMB;
    float* op = out + row * EMB;
    const int tid = threadIdx.x;
    __shared__ float sh[8];

    float v[3];
    float s = 0.0f;
#pragma unroll
    for (int i = 0; i < 3; i++) {
        int c = tid + i * 256;
        v[i] = xp[c] + yp[c];
        s += v[i];
    }
#pragma unroll
    for (int o = 16; o > 0; o >>= 1) s += __shfl_xor_sync(~0u, s, o);
    if ((tid & 31) == 0) sh[tid >> 5] = s;
    __syncthreads();
    s = 0.0f;
#pragma unroll
    for (int w = 0; w < 8; w++) s += sh[w];
    const float mean = s * (1.0f / EMB);

    float q = 0.0f;
#pragma unroll
    for (int i = 0; i < 3; i++) {
        float d = v[i] - mean;
        q += d * d;
    }
    __syncthreads();
#pragma unroll
    for (int o = 16; o > 0; o >>= 1) q += __shfl_xor_sync(~0u, q, o);
    if ((tid & 31) == 0) sh[tid >> 5] = q;
    __syncthreads();
    q = 0.0f;
#pragma unroll
    for (int w = 0; w < 8; w++) q += sh[w];
    const float rs = rsqrtf(q * (1.0f / EMB) + 1e-5f);

#pragma unroll
    for (int i = 0; i < 3; i++) {
        int c = tid + i * 256;
        float r = (v[i] - mean) * rs * g[c] + b[c];
        op[c] = r;
        if (QF && i == 0 && c < NQD)
            qf[row * NQD + c] = __float2bfloat16(__cosf(r + th[c]));
    }
}

// ---------------------------------------------------------------------------
// fp32 -> bf16 convert (n multiple of 1024)
// ---------------------------------------------------------------------------
__global__ void __launch_bounds__(256) cvt_kernel(
    const float* __restrict__ in, __nv_bfloat16* __restrict__ out) {
    int i = blockIdx.x * 256 + threadIdx.x;
    float4 v = *(const float4*)(in + (size_t)i * 4);
    *(__nv_bfloat162*)(out + (size_t)i * 4) =
        __float22bfloat162_rn(make_float2(v.x, v.y));
    *(__nv_bfloat162*)(out + (size_t)i * 4 + 2) =
        __float22bfloat162_rn(make_float2(v.z, v.w));
}

// ---------------------------------------------------------------------------
// fp32 -> tf32(rna)-in-fp32 convert (n multiple of 1024)
// ---------------------------------------------------------------------------
__global__ void __launch_bounds__(256) cvt_tf32_kernel(
    const float* __restrict__ in, float* __restrict__ out) {
    int i = blockIdx.x * 256 + threadIdx.x;
    float4 v = *(const float4*)(in + (size_t)i * 4);
    v.x = tf32r(v.x);
    v.y = tf32r(v.y);
    v.z = tf32r(v.z);
    v.w = tf32r(v.w);
    *(float4*)(out + (size_t)i * 4) = v;
}

// ---------------------------------------------------------------------------
// Launch
// ---------------------------------------------------------------------------
extern "C" void kernel_launch(void* const* d_in, const int* in_sizes, int n_in,
                              void* d_out, int out_size) {
    const float* x     = (const float*)d_in[0];
    const float* Wp    = (const float*)d_in[1];
    const float* th_rx = (const float*)d_in[2];
    const float* th_ry = (const float*)d_in[3];
    const float* W1    = (const float*)d_in[4];
    const float* b1    = (const float*)d_in[5];
    const float* W2    = (const float*)d_in[6];
    const float* b2    = (const float*)d_in[7];
    const float* ln1g  = (const float*)d_in[8];
    const float* ln1b  = (const float*)d_in[9];
    const float* ln2g  = (const float*)d_in[10];
    const float* ln2b  = (const float*)d_in[11];
    float* out = (float*)d_out;

    float *qa, *sc, *x1, *tmp, *xr, *Wpr;
    __nv_bfloat16 *Pb, *qaTb, *qfb, *hb, *W1b, *W2b;
    cudaGetSymbolAddress((void**)&qa, g_qa);
    cudaGetSymbolAddress((void**)&sc, g_scores);
    cudaGetSymbolAddress((void**)&x1, g_x1);
    cudaGetSymbolAddress((void**)&tmp, g_tmp);
    cudaGetSymbolAddress((void**)&xr, g_xr);
    cudaGetSymbolAddress((void**)&Wpr, g_Wpr);
    cudaGetSymbolAddress((void**)&Pb, g_Pb);
    cudaGetSymbolAddress((void**)&qaTb, g_qaTb);
    cudaGetSymbolAddress((void**)&qfb, g_qfb);
    cudaGetSymbolAddress((void**)&hb, g_hb);
    cudaGetSymbolAddress((void**)&W1b, g_W1b);
    cudaGetSymbolAddress((void**)&W2b, g_W2b);

    cudaFuncSetAttribute(tgemm2_kernel<1, false>,
                         cudaFuncAttributeMaxDynamicSharedMemorySize, BG_SMEM);
    cudaFuncSetAttribute(tgemm2_kernel<2, true>,
                         cudaFuncAttributeMaxDynamicSharedMemorySize, BG_SMEM);
    cudaFuncSetAttribute(bgemm2_kernel<0, false>,
                         cudaFuncAttributeMaxDynamicSharedMemorySize, BG_SMEM);
    cudaFuncSetAttribute(bgemm2_kernel<3, true>,
                         cudaFuncAttributeMaxDynamicSharedMemorySize, BG_SMEM);
    cudaFuncSetAttribute(bgemm2_kernel<4, false>,
                         cudaFuncAttributeMaxDynamicSharedMemorySize, BG_SMEM);

    dim3 blk(256);

    // 0. operand conversions
    cvt_kernel<<<(FFD * NQD) / 1024, blk>>>(W1, W1b);
    cvt_kernel<<<(EMB * FFD) / 1024, blk>>>(W2, W2b);
    cvt_tf32_kernel<<<(NTOK * EMB) / 1024, blk>>>(x, xr);
    cvt_tf32_kernel<<<(EMB * EMB) / 1024, blk>>>(Wp, Wpr);

    // 1. qa = tf32r(cos(xr @ Wpr^T + theta_rx))  [16384,768]  (TF32 v2)
    tgemm2_kernel<1, false><<<dim3(EMB / 256, NTOK / 128, 1), blk, BG_SMEM>>>(
        xr, Wpr, qa, NTOK, EMB, EMB, 0, 0, 0, th_rx, 0.0f);

    // 1b. qaTb[b][e][t] = bf16(qa[b][t][e])
    transpose_kernel<<<dim3(SEQ / 32, EMB / 32, BATCH), blk>>>(qa, qaTb);

    // 2. scores = qa @ qa^T / sqrt(8), batched; SYMMETRIC: 72 tiles + mirrors
    tgemm2_kernel<2, true><<<dim3(72, 1, BATCH), blk, BG_SMEM>>>(
        qa, qa, sc, SEQ, SEQ, EMB,
        (size_t)SEQ * EMB, (size_t)SEQ * EMB, (size_t)SEQ * SEQ,
        nullptr, 0.35355339059327373f);

    // 3. softmax rows -> bf16 P
    softmax2048_kernel<<<NTOK, blk>>>(sc, Pb);

    // 4. attn_out = P @ qa (bf16 pipeline), batched
    bgemm2_kernel<0, false><<<dim3(EMB / 256, SEQ / 128, BATCH), blk, BG_SMEM>>>(
        Pb, qaTb, tmp, SEQ, EMB, SEQ,
        (size_t)SEQ * SEQ, (size_t)EMB * SEQ, (size_t)SEQ * EMB,
        nullptr, 0.0f);

    // 5. x1 = LN(x + attn_out), fused qf = bf16(cos(x1[:, :128] + theta_ry))
    add_ln_kernel<true><<<NTOK, blk>>>(x, tmp, ln1g, ln1b, x1, th_ry, qfb);

    // 7. h = relu(qf @ W1^T + b1) -> bf16  [16384,3072], K=128
    bgemm2_kernel<3, true><<<dim3(FFD / 256, NTOK / 128, 1), blk, BG_SMEM>>>(
        qfb, W1b, hb, NTOK, FFD, NQD, 0, 0, 0, b1, 0.0f);

    // 8. ffn_out = h @ W2^T + b2  [16384,768], K=3072
    bgemm2_kernel<4, false><<<dim3(EMB / 256, NTOK / 128, 1), blk, BG_SMEM>>>(
        hb, W2b, tmp, NTOK, EMB, FFD, 0, 0, 0, b2, 0.0f);

    // 9. out = LN(x1 + ffn_out)
    add_ln_kernel<false><<<NTOK, blk>>>(x1, tmp, ln2g, ln2b, out, nullptr, nullptr);
}

// round 12
// speedup vs baseline: 5.8475x; 1.0066x over previous
#include <cuda_runtime.h>
#include <cuda_bf16.h>
#include <cstdint>
#include <math.h>

// Problem constants
#define NTOK 16384      // B*S
#define BATCH 8
#define SEQ 2048
#define EMB 768
#define FFD 3072
#define NQD 128

// ---------------------------------------------------------------------------
// Scratch (device globals; no allocation allowed)
// ---------------------------------------------------------------------------
__device__ float g_qa[(size_t)NTOK * EMB];
__device__ float g_scores[(size_t)BATCH * SEQ * SEQ];
__device__ float g_x1[(size_t)NTOK * EMB];
__device__ float g_tmp[(size_t)NTOK * EMB];
__device__ float g_xr[(size_t)NTOK * EMB];            // tf32-rounded x
__device__ float g_Wpr[(size_t)EMB * EMB];            // tf32-rounded Wp
__device__ __nv_bfloat16 g_Pb[(size_t)BATCH * SEQ * SEQ];
__device__ __nv_bfloat16 g_qaTb[(size_t)NTOK * EMB];
__device__ __nv_bfloat16 g_qfb[(size_t)NTOK * NQD];
__device__ __nv_bfloat16 g_hb[(size_t)NTOK * FFD];
__device__ __nv_bfloat16 g_W1b[(size_t)FFD * NQD];
__device__ __nv_bfloat16 g_W2b[(size_t)EMB * FFD];

// ---------------------------------------------------------------------------
// Helpers
// ---------------------------------------------------------------------------
__device__ __forceinline__ uint32_t smem_u32(const void* p) {
    uint32_t a;
    asm("{ .reg .u64 t; cvta.to.shared.u64 t, %1; cvt.u32.u64 %0, t; }"
        : "=r"(a) : "l"(p));
    return a;
}

__device__ __forceinline__ float tf32r(float f) {
    unsigned r;
    asm("cvt.rna.tf32.f32 %0, %1;" : "=r"(r) : "f"(f));
    return __uint_as_float(r);
}

__device__ __forceinline__ void mma8(float* c, const unsigned* a, const unsigned* b) {
    asm volatile(
        "mma.sync.aligned.m16n8k8.row.col.f32.tf32.tf32.f32 "
        "{%0,%1,%2,%3},{%4,%5,%6,%7},{%8,%9},{%0,%1,%2,%3};"
        : "+f"(c[0]), "+f"(c[1]), "+f"(c[2]), "+f"(c[3])
        : "r"(a[0]), "r"(a[1]), "r"(a[2]), "r"(a[3]), "r"(b[0]), "r"(b[1]));
}

__device__ __forceinline__ void mma16(float* c, const unsigned* a, const unsigned* b) {
    asm volatile(
        "mma.sync.aligned.m16n8k16.row.col.f32.bf16.bf16.f32 "
        "{%0,%1,%2,%3},{%4,%5,%6,%7},{%8,%9},{%0,%1,%2,%3};"
        : "+f"(c[0]), "+f"(c[1]), "+f"(c[2]), "+f"(c[3])
        : "r"(a[0]), "r"(a[1]), "r"(a[2]), "r"(a[3]), "r"(b[0]), "r"(b[1]));
}

__device__ __forceinline__ void cp16(uint32_t dst, const void* src) {
    asm volatile("cp.async.cg.shared.global [%0], [%1], 16;" :: "r"(dst), "l"(src));
}
#define CP_COMMIT() asm volatile("cp.async.commit_group;" ::: "memory")
#define CP_WAIT2()  asm volatile("cp.async.wait_group 2;" ::: "memory")

#define LDMX4(r, a) \
    asm volatile("ldmatrix.sync.aligned.m8n8.x4.shared.b16 {%0,%1,%2,%3}, [%4];" \
                 : "=r"((r)[0]), "=r"((r)[1]), "=r"((r)[2]), "=r"((r)[3]) : "r"(a))

// Epilogues: 0=none, 1=tf32r(cos(v+bias)), 2=v*scale, 3=relu(v+bias), 4=v+bias
template <int EPI>
__device__ __forceinline__ float epi_f(float v, const float* __restrict__ bias,
                                       int col, float scale) {
    if (EPI == 1) return tf32r(__cosf(v + bias[col]));
    if (EPI == 2) return v * scale;
    if (EPI == 3) return fmaxf(v + bias[col], 0.0f);
    if (EPI == 4) return v + bias[col];
    return v;
}

// Shared swizzle: 64B rows of 4x16B chunks, gray-code chunk rotation.
__device__ __forceinline__ uint32_t swz_off(int r, int c) {
    return (uint32_t)(r * 64 + ((c ^ ((r ^ (r >> 1)) & 3)) << 4));
}

#define BG_STAGE 24576
#define NSTAGE 4
#define BG_SMEM  (NSTAGE * BG_STAGE)

// ---------------------------------------------------------------------------
// TF32 GEMM v2: cp.async + ldmatrix(b16 view), fp32 K-major operands.
// C = A @ B^T. CTA 128x256, BK=16, 4-stage, 8 warps 2x4, warp tile 64x64.
// Operands MUST be pre-rounded to tf32 (mma truncates raw fp32).
// SYM: C symmetric (A==B); 72 lower tiles/batch, below-diag mirror scatter.
// ---------------------------------------------------------------------------
template <int EPI, bool SYM>
__global__ void __launch_bounds__(256, 1) tgemm2_kernel(
    const float* __restrict__ A, const float* __restrict__ B,
    float* __restrict__ C, int M, int N, int K,
    size_t sA, size_t sB, size_t sC,
    const float* __restrict__ bias, float scale) {
    extern __shared__ char smem[];
    const uint32_t sb = smem_u32(smem);

    A += (size_t)blockIdx.z * sA;
    B += (size_t)blockIdx.z * sB;
    C += (size_t)blockIdx.z * sC;

    int bm, bn, tt = 0;
    if (SYM) {
        int t = blockIdx.x, nx = 0;
        while (t >= 16 - 2 * nx) { t -= 16 - 2 * nx; nx++; }
        tt = t;
        bm = (2 * nx + t) * 128;
        bn = nx * 256;
    } else {
        bm = blockIdx.y * 128;
        bn = blockIdx.x * 256;
    }

    const int tid = threadIdx.x;
    const int lane = tid & 31;
    const int wid = tid >> 5;
    const int wm = wid >> 2;
    const int wn = wid & 3;
    const int niter = K >> 4;

    float acc[4][8][4] = {};

    auto load_stage = [&](int it, int st) {
        uint32_t base = sb + st * BG_STAGE;
        const float* Ag = A + (size_t)bm * K + it * 16;
#pragma unroll
        for (int u = 0; u < 2; u++) {
            int q = u * 256 + tid;
            int r = q >> 2, c = q & 3;
            cp16(base + swz_off(r, c), Ag + (size_t)r * K + c * 4);
        }
        const float* Bg = B + (size_t)bn * K + it * 16;
#pragma unroll
        for (int u = 0; u < 4; u++) {
            int q = u * 256 + tid;
            int r = q >> 2, c = q & 3;
            cp16(base + 8192 + swz_off(r, c), Bg + (size_t)r * K + c * 4);
        }
        CP_COMMIT();
    };

    auto compute = [&](int st) {
        uint32_t Ab = sb + st * BG_STAGE;
        uint32_t Bb = Ab + 8192;
#pragma unroll
        for (int s = 0; s < 2; s++) {
            unsigned af[4][4], bf[8][2];
#pragma unroll
            for (int mi = 0; mi < 4; mi++) {
                int row = wm * 64 + mi * 16 + ((lane >> 3) & 1) * 8 + (lane & 7);
                int c = s * 2 + (lane >> 4);
                LDMX4(af[mi], Ab + swz_off(row, c));
            }
#pragma unroll
            for (int p = 0; p < 4; p++) {
                int row = wn * 64 + p * 16 + ((lane >> 4) << 3) + (lane & 7);
                int c = s * 2 + ((lane >> 3) & 1);
                unsigned t[4];
                LDMX4(t, Bb + swz_off(row, c));
                bf[2 * p][0] = t[0];
                bf[2 * p][1] = t[1];
                bf[2 * p + 1][0] = t[2];
                bf[2 * p + 1][1] = t[3];
            }
#pragma unroll
            for (int mi = 0; mi < 4; mi++)
#pragma unroll
                for (int ni = 0; ni < 8; ni++)
                    mma8(acc[mi][ni], af[mi], bf[ni]);
        }
    };

#pragma unroll
    for (int i = 0; i < NSTAGE - 1; i++) {
        if (i < niter) load_stage(i, i);
        else CP_COMMIT();
    }

    int cur = 0;
    for (int it = 0; it < niter; it++) {
        CP_WAIT2();
        __syncthreads();
        compute(cur);
        if (it + NSTAGE - 1 < niter) {
            int nst = cur + NSTAGE - 1;
            if (nst >= NSTAGE) nst -= NSTAGE;
            load_stage(it + NSTAGE - 1, nst);
        } else {
            CP_COMMIT();
        }
        cur = (cur == NSTAGE - 1) ? 0 : cur + 1;
    }

    const int g = lane >> 2;
    const int tg = lane & 3;
#pragma unroll
    for (int mi = 0; mi < 4; ++mi) {
        int row = bm + wm * 64 + mi * 16 + g;
#pragma unroll
        for (int ni = 0; ni < 8; ++ni) {
            int col = bn + wn * 64 + ni * 8 + tg * 2;
            const float* a = acc[mi][ni];
            float e0 = epi_f<EPI>(a[0], bias, col + 0, scale);
            float e1 = epi_f<EPI>(a[1], bias, col + 1, scale);
            float e2 = epi_f<EPI>(a[2], bias, col + 0, scale);
            float e3 = epi_f<EPI>(a[3], bias, col + 1, scale);
            *(float2*)(C + (size_t)row * N + col) = make_float2(e0, e1);
            *(float2*)(C + (size_t)(row + 8) * N + col) = make_float2(e2, e3);
            if (SYM && tt >= 2) {
                C[(size_t)(col + 0) * N + row] = e0;
                C[(size_t)(col + 1) * N + row] = e1;
                C[(size_t)(col + 0) * N + row + 8] = e2;
                C[(size_t)(col + 1) * N + row + 8] = e3;
            }
        }
    }
}

// ---------------------------------------------------------------------------
// BF16 GEMM v3: cp.async + ldmatrix, bf16 gmem operands (K-major both).
// CTA 128x256, BK=32, 4-stage pipeline, 512 threads (16 warps, 2x8),
// warp tile 64x32 -> 4 warps/SMSP for latency hiding. acc 64 regs/thread.
// ---------------------------------------------------------------------------
template <int EPI, bool OUTBF>
__global__ void __launch_bounds__(512, 1) bgemm3_kernel(
    const __nv_bfloat16* __restrict__ A, const __nv_bfloat16* __restrict__ B,
    void* __restrict__ Cv, int M, int N, int K,
    size_t sA, size_t sB, size_t sC,
    const float* __restrict__ bias, float scale) {
    extern __shared__ char smem[];
    const uint32_t sb = smem_u32(smem);

    A += (size_t)blockIdx.z * sA;
    B += (size_t)blockIdx.z * sB;

    const int bm = blockIdx.y * 128;
    const int bn = blockIdx.x * 256;
    const int tid = threadIdx.x;
    const int lane = tid & 31;
    const int wid = tid >> 5;       // 0..15
    const int wm = wid >> 3;        // 0..1 (64 rows)
    const int wn = wid & 7;         // 0..7 (32 cols)
    const int niter = K >> 5;

    float acc[4][4][4] = {};

    auto load_stage = [&](int it, int st) {
        uint32_t base = sb + st * BG_STAGE;
        const __nv_bfloat16* Ag = A + (size_t)bm * K + it * 32;
        {
            int r = tid >> 2, c = tid & 3;   // 512 = 128 rows x 4 chunks
            cp16(base + swz_off(r, c), Ag + (size_t)r * K + c * 8);
        }
        const __nv_bfloat16* Bg = B + (size_t)bn * K + it * 32;
#pragma unroll
        for (int u = 0; u < 2; u++) {
            int q = u * 512 + tid;
            int r = q >> 2, c = q & 3;
            cp16(base + 8192 + swz_off(r, c), Bg + (size_t)r * K + c * 8);
        }
        CP_COMMIT();
    };

    auto compute = [&](int st) {
        uint32_t Ab = sb + st * BG_STAGE;
        uint32_t Bb = Ab + 8192;
#pragma unroll
        for (int s = 0; s < 2; s++) {
            unsigned af[4][4], bf[4][2];
#pragma unroll
            for (int mi = 0; mi < 4; mi++) {
                int row = wm * 64 + mi * 16 + ((lane >> 3) & 1) * 8 + (lane & 7);
                int c = s * 2 + (lane >> 4);
                LDMX4(af[mi], Ab + swz_off(row, c));
            }
#pragma unroll
            for (int p = 0; p < 2; p++) {
                int row = wn * 32 + p * 16 + ((lane >> 4) << 3) + (lane & 7);
                int c = s * 2 + ((lane >> 3) & 1);
                unsigned t[4];
                LDMX4(t, Bb + swz_off(row, c));
                bf[2 * p][0] = t[0];
                bf[2 * p][1] = t[1];
                bf[2 * p + 1][0] = t[2];
                bf[2 * p + 1][1] = t[3];
            }
#pragma unroll
            for (int mi = 0; mi < 4; mi++)
#pragma unroll
                for (int ni = 0; ni < 4; ni++)
                    mma16(acc[mi][ni], af[mi], bf[ni]);
        }
    };

#pragma unroll
    for (int i = 0; i < NSTAGE - 1; i++) {
        if (i < niter) load_stage(i, i);
        else CP_COMMIT();
    }

    int cur = 0;
    for (int it = 0; it < niter; it++) {
        CP_WAIT2();
        __syncthreads();
        compute(cur);
        if (it + NSTAGE - 1 < niter) {
            int nst = cur + NSTAGE - 1;
            if (nst >= NSTAGE) nst -= NSTAGE;
            load_stage(it + NSTAGE - 1, nst);
        } else {
            CP_COMMIT();
        }
        cur = (cur == NSTAGE - 1) ? 0 : cur + 1;
    }

    const int g = lane >> 2;
    const int tg = lane & 3;
#pragma unroll
    for (int mi = 0; mi < 4; ++mi) {
        int row = bm + wm * 64 + mi * 16 + g;
#pragma unroll
        for (int ni = 0; ni < 4; ++ni) {
            int col = bn + wn * 32 + ni * 8 + tg * 2;
            const float* a = acc[mi][ni];
            float e0 = epi_f<EPI>(a[0], bias, col + 0, scale);
            float e1 = epi_f<EPI>(a[1], bias, col + 1, scale);
            float e2 = epi_f<EPI>(a[2], bias, col + 0, scale);
            float e3 = epi_f<EPI>(a[3], bias, col + 1, scale);
            if (OUTBF) {
                __nv_bfloat16* C = (__nv_bfloat16*)Cv + (size_t)blockIdx.z * sC;
                *(__nv_bfloat162*)(C + (size_t)row * N + col) =
                    __float22bfloat162_rn(make_float2(e0, e1));
                *(__nv_bfloat162*)(C + (size_t)(row + 8) * N + col) =
                    __float22bfloat162_rn(make_float2(e2, e3));
            } else {
                float* C = (float*)Cv + (size_t)blockIdx.z * sC;
                *(float2*)(C + (size_t)row * N + col) = make_float2(e0, e1);
                *(float2*)(C + (size_t)(row + 8) * N + col) = make_float2(e2, e3);
            }
        }
    }
}

// ---------------------------------------------------------------------------
// 32x32 tiled transpose per batch, bf16 out: out[b][e][t] = bf16(in[b][t][e])
// ---------------------------------------------------------------------------
__global__ void __launch_bounds__(256) transpose_kernel(
    const float* __restrict__ in, __nv_bfloat16* __restrict__ out) {
    __shared__ float t[32][33];
    const int b = blockIdx.z;
    const int t0 = blockIdx.x * 32;
    const int e0 = blockIdx.y * 32;
    const int lx = threadIdx.x & 31, ly = threadIdx.x >> 5;
#pragma unroll
    for (int r = 0; r < 32; r += 8)
        t[ly + r][lx] = in[((size_t)b * SEQ + t0 + ly + r) * EMB + e0 + lx];
    __syncthreads();
#pragma unroll
    for (int r = 0; r < 32; r += 8)
        out[((size_t)b * EMB + e0 + ly + r) * SEQ + t0 + lx] =
            __float2bfloat16(t[lx][ly + r]);
}

// ---------------------------------------------------------------------------
// Row softmax (reads fp32 scores, writes bf16 P), row length 2048.
// ---------------------------------------------------------------------------
__global__ void __launch_bounds__(256) softmax2048_kernel(
    const float* __restrict__ S, __nv_bfloat16* __restrict__ P) {
    const float* p = S + (size_t)blockIdx.x * SEQ;
    __nv_bfloat16* o = P + (size_t)blockIdx.x * SEQ;
    const int tid = threadIdx.x;
    __shared__ float sh[8];

    float v[8];
    float m = -1e30f;
#pragma unroll
    for (int i = 0; i < 8; i++) {
        v[i] = p[tid + i * 256];
        m = fmaxf(m, v[i]);
    }
#pragma unroll
    for (int o2 = 16; o2 > 0; o2 >>= 1) m = fmaxf(m, __shfl_xor_sync(~0u, m, o2));
    if ((tid & 31) == 0) sh[tid >> 5] = m;
    __syncthreads();
    m = sh[0];
#pragma unroll
    for (int w = 1; w < 8; w++) m = fmaxf(m, sh[w]);

    float s = 0.0f;
#pragma unroll
    for (int i = 0; i < 8; i++) {
        v[i] = __expf(v[i] - m);
        s += v[i];
    }
    __syncthreads();
#pragma unroll
    for (int o2 = 16; o2 > 0; o2 >>= 1) s += __shfl_xor_sync(~0u, s, o2);
    if ((tid & 31) == 0) sh[tid >> 5] = s;
    __syncthreads();
    s = 0.0f;
#pragma unroll
    for (int w = 0; w < 8; w++) s += sh[w];
    float inv = 1.0f / s;
#pragma unroll
    for (int i = 0; i < 8; i++) o[tid + i * 256] = __float2bfloat16(v[i] * inv);
}

// ---------------------------------------------------------------------------
// out = LayerNorm(X + Y) * g + b, row length 768; optionally fused qf output.
// ---------------------------------------------------------------------------
template <bool QF>
__global__ void __launch_bounds__(256) add_ln_kernel(
    const float* __restrict__ X, const float* __restrict__ Y,
    const float* __restrict__ g, const float* __restrict__ b,
    float* __restrict__ out, const float* __restrict__ th,
    __nv_bfloat16* __restrict__ qf) {
    const size_t row = blockIdx.x;
    const float* xp = X + row * EMB;
    const float* yp = Y + row * EMB;
    float* op = out + row * EMB;
    const int tid = threadIdx.x;
    __shared__ float sh[8];

    float v[3];
    float s = 0.0f;
#pragma unroll
    for (int i = 0; i < 3; i++) {
        int c = tid + i * 256;
        v[i] = xp[c] + yp[c];
        s += v[i];
    }
#pragma unroll
    for (int o = 16; o > 0; o >>= 1) s += __shfl_xor_sync(~0u, s, o);
    if ((tid & 31) == 0) sh[tid >> 5] = s;
    __syncthreads();
    s = 0.0f;
#pragma unroll
    for (int w = 0; w < 8; w++) s += sh[w];
    const float mean = s * (1.0f / EMB);

    float q = 0.0f;
#pragma unroll
    for (int i = 0; i < 3; i++) {
        float d = v[i] - mean;
        q += d * d;
    }
    __syncthreads();
#pragma unroll
    for (int o = 16; o > 0; o >>= 1) q += __shfl_xor_sync(~0u, q, o);
    if ((tid & 31) == 0) sh[tid >> 5] = q;
    __syncthreads();
    q = 0.0f;
#pragma unroll
    for (int w = 0; w < 8; w++) q += sh[w];
    const float rs = rsqrtf(q * (1.0f / EMB) + 1e-5f);

#pragma unroll
    for (int i = 0; i < 3; i++) {
        int c = tid + i * 256;
        float r = (v[i] - mean) * rs * g[c] + b[c];
        op[c] = r;
        if (QF && i == 0 && c < NQD)
            qf[row * NQD + c] = __float2bfloat16(__cosf(r + th[c]));
    }
}

// ---------------------------------------------------------------------------
// Merged converts. cvt_w_kernel: W1,W2 fp32->bf16. cvt_x_kernel: x,Wp ->tf32.
// ---------------------------------------------------------------------------
#define W1_BLKS ((FFD * NQD) / 1024)
#define W2_BLKS ((EMB * FFD) / 1024)
__global__ void __launch_bounds__(256) cvt_w_kernel(
    const float* __restrict__ w1, __nv_bfloat16* __restrict__ w1o,
    const float* __restrict__ w2, __nv_bfloat16* __restrict__ w2o) {
    const float* in;
    __nv_bfloat16* out;
    size_t i;
    if (blockIdx.x < W1_BLKS) {
        in = w1; out = w1o;
        i = (size_t)blockIdx.x * 256 + threadIdx.x;
    } else {
        in = w2; out = w2o;
        i = (size_t)(blockIdx.x - W1_BLKS) * 256 + threadIdx.x;
    }
    float4 v = *(const float4*)(in + i * 4);
    *(__nv_bfloat162*)(out + i * 4) = __float22bfloat162_rn(make_float2(v.x, v.y));
    *(__nv_bfloat162*)(out + i * 4 + 2) = __float22bfloat162_rn(make_float2(v.z, v.w));
}

#define X_BLKS ((NTOK * EMB) / 1024)
__global__ void __launch_bounds__(256) cvt_x_kernel(
    const float* __restrict__ x, float* __restrict__ xo,
    const float* __restrict__ wp, float* __restrict__ wpo) {
    const float* in;
    float* out;
    size_t i;
    if (blockIdx.x < X_BLKS) {
        in = x; out = xo;
        i = (size_t)blockIdx.x * 256 + threadIdx.x;
    } else {
        in = wp; out = wpo;
        i = (size_t)(blockIdx.x - X_BLKS) * 256 + threadIdx.x;
    }
    float4 v = *(const float4*)(in + i * 4);
    v.x = tf32r(v.x);
    v.y = tf32r(v.y);
    v.z = tf32r(v.z);
    v.w = tf32r(v.w);
    *(float4*)(out + i * 4) = v;
}

// ---------------------------------------------------------------------------
// Launch
// ---------------------------------------------------------------------------
extern "C" void kernel_launch(void* const* d_in, const int* in_sizes, int n_in,
                              void* d_out, int out_size) {
    const float* x     = (const float*)d_in[0];
    const float* Wp    = (const float*)d_in[1];
    const float* th_rx = (const float*)d_in[2];
    const float* th_ry = (const float*)d_in[3];
    const float* W1    = (const float*)d_in[4];
    const float* b1    = (const float*)d_in[5];
    const float* W2    = (const float*)d_in[6];
    const float* b2    = (const float*)d_in[7];
    const float* ln1g  = (const float*)d_in[8];
    const float* ln1b  = (const float*)d_in[9];
    const float* ln2g  = (const float*)d_in[10];
    const float* ln2b  = (const float*)d_in[11];
    float* out = (float*)d_out;

    float *qa, *sc, *x1, *tmp, *xr, *Wpr;
    __nv_bfloat16 *Pb, *qaTb, *qfb, *hb, *W1b, *W2b;
    cudaGetSymbolAddress((void**)&qa, g_qa);
    cudaGetSymbolAddress((void**)&sc, g_scores);
    cudaGetSymbolAddress((void**)&x1, g_x1);
    cudaGetSymbolAddress((void**)&tmp, g_tmp);
    cudaGetSymbolAddress((void**)&xr, g_xr);
    cudaGetSymbolAddress((void**)&Wpr, g_Wpr);
    cudaGetSymbolAddress((void**)&Pb, g_Pb);
    cudaGetSymbolAddress((void**)&qaTb, g_qaTb);
    cudaGetSymbolAddress((void**)&qfb, g_qfb);
    cudaGetSymbolAddress((void**)&hb, g_hb);
    cudaGetSymbolAddress((void**)&W1b, g_W1b);
    cudaGetSymbolAddress((void**)&W2b, g_W2b);

    cudaFuncSetAttribute(tgemm2_kernel<1, false>,
                         cudaFuncAttributeMaxDynamicSharedMemorySize, BG_SMEM);
    cudaFuncSetAttribute(tgemm2_kernel<2, true>,
                         cudaFuncAttributeMaxDynamicSharedMemorySize, BG_SMEM);
    cudaFuncSetAttribute(bgemm3_kernel<0, false>,
                         cudaFuncAttributeMaxDynamicSharedMemorySize, BG_SMEM);
    cudaFuncSetAttribute(bgemm3_kernel<3, true>,
                         cudaFuncAttributeMaxDynamicSharedMemorySize, BG_SMEM);
    cudaFuncSetAttribute(bgemm3_kernel<4, false>,
                         cudaFuncAttributeMaxDynamicSharedMemorySize, BG_SMEM);

    dim3 blk(256);
    dim3 blk512(512);

    // [0] x,Wp -> tf32-rounded
    cvt_x_kernel<<<X_BLKS + (EMB * EMB) / 1024, blk>>>(x, xr, Wp, Wpr);
    // [1] W1,W2 -> bf16
    cvt_w_kernel<<<W1_BLKS + W2_BLKS, blk>>>(W1, W1b, W2, W2b);

    // [2] qa = tf32r(cos(xr @ Wpr^T + theta_rx))
    tgemm2_kernel<1, false><<<dim3(EMB / 256, NTOK / 128, 1), blk, BG_SMEM>>>(
        xr, Wpr, qa, NTOK, EMB, EMB, 0, 0, 0, th_rx, 0.0f);

    // [3] scores = qa @ qa^T / sqrt(8), SYMMETRIC (profiled slot)
    tgemm2_kernel<2, true><<<dim3(72, 1, BATCH), blk, BG_SMEM>>>(
        qa, qa, sc, SEQ, SEQ, EMB,
        (size_t)SEQ * EMB, (size_t)SEQ * EMB, (size_t)SEQ * SEQ,
        nullptr, 0.35355339059327373f);

    // [4] qaTb[b][e][t] = bf16(qa[b][t][e])
    transpose_kernel<<<dim3(SEQ / 32, EMB / 32, BATCH), blk>>>(qa, qaTb);

    // [5] softmax rows -> bf16 P
    softmax2048_kernel<<<NTOK, blk>>>(sc, Pb);

    // [6] attn_out = P @ qa (bf16 v3), batched
    bgemm3_kernel<0, false><<<dim3(EMB / 256, SEQ / 128, BATCH), blk512, BG_SMEM>>>(
        Pb, qaTb, tmp, SEQ, EMB, SEQ,
        (size_t)SEQ * SEQ, (size_t)EMB * SEQ, (size_t)SEQ * EMB,
        nullptr, 0.0f);

    // [7] x1 = LN(x + attn_out), fused qf
    add_ln_kernel<true><<<NTOK, blk>>>(x, tmp, ln1g, ln1b, x1, th_ry, qfb);

    // [8] h = relu(qf @ W1^T + b1) -> bf16
    bgemm3_kernel<3, true><<<dim3(FFD / 256, NTOK / 128, 1), blk512, BG_SMEM>>>(
        qfb, W1b, hb, NTOK, FFD, NQD, 0, 0, 0, b1, 0.0f);

    // [9] ffn_out = h @ W2^T + b2
    bgemm3_kernel<4, false><<<dim3(EMB / 256, NTOK / 128, 1), blk512, BG_SMEM>>>(
        hb, W2b, tmp, NTOK, EMB, FFD, 0, 0, 0, b2, 0.0f);

    // [10] out = LN(x1 + ffn_out)
    add_ln_kernel<false><<<NTOK, blk>>>(x1, tmp, ln2g, ln2b, out, nullptr, nullptr);
}

// round 16
// speedup vs baseline: 5.8989x; 1.0088x over previous
#include <cuda_runtime.h>
#include <cuda_bf16.h>
#include <cstdint>
#include <math.h>

// Problem constants
#define NTOK 16384      // B*S
#define BATCH 8
#define SEQ 2048
#define EMB 768
#define FFD 3072
#define NQD 128

// ---------------------------------------------------------------------------
// Scratch (device globals; no allocation allowed)
// ---------------------------------------------------------------------------
__device__ float g_qa[(size_t)NTOK * EMB];
__device__ float g_scores[(size_t)BATCH * SEQ * SEQ];
__device__ float g_x1[(size_t)NTOK * EMB];
__device__ float g_tmp[(size_t)NTOK * EMB];
__device__ float g_xr[(size_t)NTOK * EMB];            // tf32-rounded x
__device__ float g_Wpr[(size_t)EMB * EMB];            // tf32-rounded Wp
__device__ __nv_bfloat16 g_Pb[(size_t)BATCH * SEQ * SEQ];
__device__ __nv_bfloat16 g_qaTb[(size_t)NTOK * EMB];
__device__ __nv_bfloat16 g_qfb[(size_t)NTOK * NQD];
__device__ __nv_bfloat16 g_hb[(size_t)NTOK * FFD];
__device__ __nv_bfloat16 g_W1b[(size_t)FFD * NQD];
__device__ __nv_bfloat16 g_W2b[(size_t)EMB * FFD];

// ---------------------------------------------------------------------------
// Helpers
// ---------------------------------------------------------------------------
__device__ __forceinline__ uint32_t smem_u32(const void* p) {
    uint32_t a;
    asm("{ .reg .u64 t; cvta.to.shared.u64 t, %1; cvt.u32.u64 %0, t; }"
        : "=r"(a) : "l"(p));
    return a;
}

__device__ __forceinline__ float tf32r(float f) {
    unsigned r;
    asm("cvt.rna.tf32.f32 %0, %1;" : "=r"(r) : "f"(f));
    return __uint_as_float(r);
}

__device__ __forceinline__ void mma8(float* c, const unsigned* a, const unsigned* b) {
    asm volatile(
        "mma.sync.aligned.m16n8k8.row.col.f32.tf32.tf32.f32 "
        "{%0,%1,%2,%3},{%4,%5,%6,%7},{%8,%9},{%0,%1,%2,%3};"
        : "+f"(c[0]), "+f"(c[1]), "+f"(c[2]), "+f"(c[3])
        : "r"(a[0]), "r"(a[1]), "r"(a[2]), "r"(a[3]), "r"(b[0]), "r"(b[1]));
}

__device__ __forceinline__ void mma16(float* c, const unsigned* a, const unsigned* b) {
    asm volatile(
        "mma.sync.aligned.m16n8k16.row.col.f32.bf16.bf16.f32 "
        "{%0,%1,%2,%3},{%4,%5,%6,%7},{%8,%9},{%0,%1,%2,%3};"
        : "+f"(c[0]), "+f"(c[1]), "+f"(c[2]), "+f"(c[3])
        : "r"(a[0]), "r"(a[1]), "r"(a[2]), "r"(a[3]), "r"(b[0]), "r"(b[1]));
}

__device__ __forceinline__ void cp16(uint32_t dst, const void* src) {
    asm volatile("cp.async.cg.shared.global [%0], [%1], 16;" :: "r"(dst), "l"(src));
}
#define CP_COMMIT() asm volatile("cp.async.commit_group;" ::: "memory")
#define CP_WAIT2()  asm volatile("cp.async.wait_group 2;" ::: "memory")

#define LDMX4(r, a) \
    asm volatile("ldmatrix.sync.aligned.m8n8.x4.shared.b16 {%0,%1,%2,%3}, [%4];" \
                 : "=r"((r)[0]), "=r"((r)[1]), "=r"((r)[2]), "=r"((r)[3]) : "r"(a))

// Epilogues: 0=none, 1=tf32r(cos(v+bias)), 2=v*scale, 3=relu(v+bias), 4=v+bias
template <int EPI>
__device__ __forceinline__ float epi_f(float v, const float* __restrict__ bias,
                                       int col, float scale) {
    if (EPI == 1) return tf32r(__cosf(v + bias[col]));
    if (EPI == 2) return v * scale;
    if (EPI == 3) return fmaxf(v + bias[col], 0.0f);
    if (EPI == 4) return v + bias[col];
    return v;
}

// Shared swizzle: 64B rows of 4x16B chunks, gray-code chunk rotation.
__device__ __forceinline__ uint32_t swz_off(int r, int c) {
    return (uint32_t)(r * 64 + ((c ^ ((r ^ (r >> 1)) & 3)) << 4));
}

#define BG_STAGE 24576
#define NSTAGE 4
#define BG_SMEM  (NSTAGE * BG_STAGE)

// ---------------------------------------------------------------------------
// TF32 GEMM v3: cp.async + ldmatrix(b16 view), fp32 K-major operands.
// C = A @ B^T. CTA 128x256, BK=16, 4-stage, 512 threads (16 warps 2x8),
// warp tile 64x32 -> 4 warps/SMSP. Operands pre-rounded to tf32.
// SYM: C symmetric (A==B); 72 lower tiles/batch, below-diag mirror scatter.
// ---------------------------------------------------------------------------
template <int EPI, bool SYM>
__global__ void __launch_bounds__(512, 1) tgemm3_kernel(
    const float* __restrict__ A, const float* __restrict__ B,
    float* __restrict__ C, int M, int N, int K,
    size_t sA, size_t sB, size_t sC,
    const float* __restrict__ bias, float scale) {
    extern __shared__ char smem[];
    const uint32_t sb = smem_u32(smem);

    A += (size_t)blockIdx.z * sA;
    B += (size_t)blockIdx.z * sB;
    C += (size_t)blockIdx.z * sC;

    int bm, bn, tt = 0;
    if (SYM) {
        int t = blockIdx.x, nx = 0;
        while (t >= 16 - 2 * nx) { t -= 16 - 2 * nx; nx++; }
        tt = t;
        bm = (2 * nx + t) * 128;
        bn = nx * 256;
    } else {
        bm = blockIdx.y * 128;
        bn = blockIdx.x * 256;
    }

    const int tid = threadIdx.x;
    const int lane = tid & 31;
    const int wid = tid >> 5;       // 0..15
    const int wm = wid >> 3;        // 0..1 (64 rows)
    const int wn = wid & 7;         // 0..7 (32 cols)
    const int niter = K >> 4;

    float acc[4][4][4] = {};

    auto load_stage = [&](int it, int st) {
        uint32_t base = sb + st * BG_STAGE;
        const float* Ag = A + (size_t)bm * K + it * 16;
        {
            int r = tid >> 2, c = tid & 3;   // 512 = 128 rows x 4 chunks
            cp16(base + swz_off(r, c), Ag + (size_t)r * K + c * 4);
        }
        const float* Bg = B + (size_t)bn * K + it * 16;
#pragma unroll
        for (int u = 0; u < 2; u++) {
            int q = u * 512 + tid;
            int r = q >> 2, c = q & 3;
            cp16(base + 8192 + swz_off(r, c), Bg + (size_t)r * K + c * 4);
        }
        CP_COMMIT();
    };

    auto compute = [&](int st) {
        uint32_t Ab = sb + st * BG_STAGE;
        uint32_t Bb = Ab + 8192;
#pragma unroll
        for (int s = 0; s < 2; s++) {  // two k8 blocks per BK=16
            unsigned af[4][4], bf[4][2];
#pragma unroll
            for (int mi = 0; mi < 4; mi++) {
                int row = wm * 64 + mi * 16 + ((lane >> 3) & 1) * 8 + (lane & 7);
                int c = s * 2 + (lane >> 4);
                LDMX4(af[mi], Ab + swz_off(row, c));
            }
#pragma unroll
            for (int p = 0; p < 2; p++) {
                int row = wn * 32 + p * 16 + ((lane >> 4) << 3) + (lane & 7);
                int c = s * 2 + ((lane >> 3) & 1);
                unsigned t[4];
                LDMX4(t, Bb + swz_off(row, c));
                bf[2 * p][0] = t[0];
                bf[2 * p][1] = t[1];
                bf[2 * p + 1][0] = t[2];
                bf[2 * p + 1][1] = t[3];
            }
#pragma unroll
            for (int mi = 0; mi < 4; mi++)
#pragma unroll
                for (int ni = 0; ni < 4; ni++)
                    mma8(acc[mi][ni], af[mi], bf[ni]);
        }
    };

#pragma unroll
    for (int i = 0; i < NSTAGE - 1; i++) {
        if (i < niter) load_stage(i, i);
        else CP_COMMIT();
    }

    int cur = 0;
    for (int it = 0; it < niter; it++) {
        CP_WAIT2();
        __syncthreads();
        compute(cur);
        if (it + NSTAGE - 1 < niter) {
            int nst = cur + NSTAGE - 1;
            if (nst >= NSTAGE) nst -= NSTAGE;
            load_stage(it + NSTAGE - 1, nst);
        } else {
            CP_COMMIT();
        }
        cur = (cur == NSTAGE - 1) ? 0 : cur + 1;
    }

    const int g = lane >> 2;
    const int tg = lane & 3;
#pragma unroll
    for (int mi = 0; mi < 4; ++mi) {
        int row = bm + wm * 64 + mi * 16 + g;
#pragma unroll
        for (int ni = 0; ni < 4; ++ni) {
            int col = bn + wn * 32 + ni * 8 + tg * 2;
            const float* a = acc[mi][ni];
            float e0 = epi_f<EPI>(a[0], bias, col + 0, scale);
            float e1 = epi_f<EPI>(a[1], bias, col + 1, scale);
            float e2 = epi_f<EPI>(a[2], bias, col + 0, scale);
            float e3 = epi_f<EPI>(a[3], bias, col + 1, scale);
            *(float2*)(C + (size_t)row * N + col) = make_float2(e0, e1);
            *(float2*)(C + (size_t)(row + 8) * N + col) = make_float2(e2, e3);
            if (SYM && tt >= 2) {
                C[(size_t)(col + 0) * N + row] = e0;
                C[(size_t)(col + 1) * N + row] = e1;
                C[(size_t)(col + 0) * N + row + 8] = e2;
                C[(size_t)(col + 1) * N + row + 8] = e3;
            }
        }
    }
}

// ---------------------------------------------------------------------------
// BF16 GEMM v3: cp.async + ldmatrix, bf16 gmem operands (K-major both).
// CTA 128x256, BK=32, 4-stage pipeline, 512 threads (16 warps, 2x8),
// warp tile 64x32. acc 64 regs/thread.
// ---------------------------------------------------------------------------
template <int EPI, bool OUTBF>
__global__ void __launch_bounds__(512, 1) bgemm3_kernel(
    const __nv_bfloat16* __restrict__ A, const __nv_bfloat16* __restrict__ B,
    void* __restrict__ Cv, int M, int N, int K,
    size_t sA, size_t sB, size_t sC,
    const float* __restrict__ bias, float scale) {
    extern __shared__ char smem[];
    const uint32_t sb = smem_u32(smem);

    A += (size_t)blockIdx.z * sA;
    B += (size_t)blockIdx.z * sB;

    const int bm = blockIdx.y * 128;
    const int bn = blockIdx.x * 256;
    const int tid = threadIdx.x;
    const int lane = tid & 31;
    const int wid = tid >> 5;       // 0..15
    const int wm = wid >> 3;        // 0..1 (64 rows)
    const int wn = wid & 7;         // 0..7 (32 cols)
    const int niter = K >> 5;

    float acc[4][4][4] = {};

    auto load_stage = [&](int it, int st) {
        uint32_t base = sb + st * BG_STAGE;
        const __nv_bfloat16* Ag = A + (size_t)bm * K + it * 32;
        {
            int r = tid >> 2, c = tid & 3;
            cp16(base + swz_off(r, c), Ag + (size_t)r * K + c * 8);
        }
        const __nv_bfloat16* Bg = B + (size_t)bn * K + it * 32;
#pragma unroll
        for (int u = 0; u < 2; u++) {
            int q = u * 512 + tid;
            int r = q >> 2, c = q & 3;
            cp16(base + 8192 + swz_off(r, c), Bg + (size_t)r * K + c * 8);
        }
        CP_COMMIT();
    };

    auto compute = [&](int st) {
        uint32_t Ab = sb + st * BG_STAGE;
        uint32_t Bb = Ab + 8192;
#pragma unroll
        for (int s = 0; s < 2; s++) {
            unsigned af[4][4], bf[4][2];
#pragma unroll
            for (int mi = 0; mi < 4; mi++) {
                int row = wm * 64 + mi * 16 + ((lane >> 3) & 1) * 8 + (lane & 7);
                int c = s * 2 + (lane >> 4);
                LDMX4(af[mi], Ab + swz_off(row, c));
            }
#pragma unroll
            for (int p = 0; p < 2; p++) {
                int row = wn * 32 + p * 16 + ((lane >> 4) << 3) + (lane & 7);
                int c = s * 2 + ((lane >> 3) & 1);
                unsigned t[4];
                LDMX4(t, Bb + swz_off(row, c));
                bf[2 * p][0] = t[0];
                bf[2 * p][1] = t[1];
                bf[2 * p + 1][0] = t[2];
                bf[2 * p + 1][1] = t[3];
            }
#pragma unroll
            for (int mi = 0; mi < 4; mi++)
#pragma unroll
                for (int ni = 0; ni < 4; ni++)
                    mma16(acc[mi][ni], af[mi], bf[ni]);
        }
    };

#pragma unroll
    for (int i = 0; i < NSTAGE - 1; i++) {
        if (i < niter) load_stage(i, i);
        else CP_COMMIT();
    }

    int cur = 0;
    for (int it = 0; it < niter; it++) {
        CP_WAIT2();
        __syncthreads();
        compute(cur);
        if (it + NSTAGE - 1 < niter) {
            int nst = cur + NSTAGE - 1;
            if (nst >= NSTAGE) nst -= NSTAGE;
            load_stage(it + NSTAGE - 1, nst);
        } else {
            CP_COMMIT();
        }
        cur = (cur == NSTAGE - 1) ? 0 : cur + 1;
    }

    const int g = lane >> 2;
    const int tg = lane & 3;
#pragma unroll
    for (int mi = 0; mi < 4; ++mi) {
        int row = bm + wm * 64 + mi * 16 + g;
#pragma unroll
        for (int ni = 0; ni < 4; ++ni) {
            int col = bn + wn * 32 + ni * 8 + tg * 2;
            const float* a = acc[mi][ni];
            float e0 = epi_f<EPI>(a[0], bias, col + 0, scale);
            float e1 = epi_f<EPI>(a[1], bias, col + 1, scale);
            float e2 = epi_f<EPI>(a[2], bias, col + 0, scale);
            float e3 = epi_f<EPI>(a[3], bias, col + 1, scale);
            if (OUTBF) {
                __nv_bfloat16* C = (__nv_bfloat16*)Cv + (size_t)blockIdx.z * sC;
                *(__nv_bfloat162*)(C + (size_t)row * N + col) =
                    __float22bfloat162_rn(make_float2(e0, e1));
                *(__nv_bfloat162*)(C + (size_t)(row + 8) * N + col) =
                    __float22bfloat162_rn(make_float2(e2, e3));
            } else {
                float* C = (float*)Cv + (size_t)blockIdx.z * sC;
                *(float2*)(C + (size_t)row * N + col) = make_float2(e0, e1);
                *(float2*)(C + (size_t)(row + 8) * N + col) = make_float2(e2, e3);
            }
        }
    }
}

// ---------------------------------------------------------------------------
// 32x32 tiled transpose per batch, bf16 out: out[b][e][t] = bf16(in[b][t][e])
// ---------------------------------------------------------------------------
__global__ void __launch_bounds__(256) transpose_kernel(
    const float* __restrict__ in, __nv_bfloat16* __restrict__ out) {
    __shared__ float t[32][33];
    const int b = blockIdx.z;
    const int t0 = blockIdx.x * 32;
    const int e0 = blockIdx.y * 32;
    const int lx = threadIdx.x & 31, ly = threadIdx.x >> 5;
#pragma unroll
    for (int r = 0; r < 32; r += 8)
        t[ly + r][lx] = in[((size_t)b * SEQ + t0 + ly + r) * EMB + e0 + lx];
    __syncthreads();
#pragma unroll
    for (int r = 0; r < 32; r += 8)
        out[((size_t)b * EMB + e0 + ly + r) * SEQ + t0 + lx] =
            __float2bfloat16(t[lx][ly + r]);
}

// ---------------------------------------------------------------------------
// Row softmax (reads fp32 scores, writes bf16 P), row length 2048.
// ---------------------------------------------------------------------------
__global__ void __launch_bounds__(256) softmax2048_kernel(
    const float* __restrict__ S, __nv_bfloat16* __restrict__ P) {
    const float* p = S + (size_t)blockIdx.x * SEQ;
    __nv_bfloat16* o = P + (size_t)blockIdx.x * SEQ;
    const int tid = threadIdx.x;
    __shared__ float sh[8];

    float v[8];
    float m = -1e30f;
#pragma unroll
    for (int i = 0; i < 8; i++) {
        v[i] = p[tid + i * 256];
        m = fmaxf(m, v[i]);
    }
#pragma unroll
    for (int o2 = 16; o2 > 0; o2 >>= 1) m = fmaxf(m, __shfl_xor_sync(~0u, m, o2));
    if ((tid & 31) == 0) sh[tid >> 5] = m;
    __syncthreads();
    m = sh[0];
#pragma unroll
    for (int w = 1; w < 8; w++) m = fmaxf(m, sh[w]);

    float s = 0.0f;
#pragma unroll
    for (int i = 0; i < 8; i++) {
        v[i] = __expf(v[i] - m);
        s += v[i];
    }
    __syncthreads();
#pragma unroll
    for (int o2 = 16; o2 > 0; o2 >>= 1) s += __shfl_xor_sync(~0u, s, o2);
    if ((tid & 31) == 0) sh[tid >> 5] = s;
    __syncthreads();
    s = 0.0f;
#pragma unroll
    for (int w = 0; w < 8; w++) s += sh[w];
    float inv = 1.0f / s;
#pragma unroll
    for (int i = 0; i < 8; i++) o[tid + i * 256] = __float2bfloat16(v[i] * inv);
}

// ---------------------------------------------------------------------------
// out = LayerNorm(X + Y) * g + b, row length 768; optionally fused qf output.
// ---------------------------------------------------------------------------
template <bool QF>
__global__ void __launch_bounds__(256) add_ln_kernel(
    const float* __restrict__ X, const float* __restrict__ Y,
    const float* __restrict__ g, const float* __restrict__ b,
    float* __restrict__ out, const float* __restrict__ th,
    __nv_bfloat16* __restrict__ qf) {
    const size_t row = blockIdx.x;
    const float* xp = X + row * EMB;
    const float* yp = Y + row * EMB;
    float* op = out + row * EMB;
    const int tid = threadIdx.x;
    __shared__ float sh[8];

    float v[3];
    float s = 0.0f;
#pragma unroll
    for (int i = 0; i < 3; i++) {
        int c = tid + i * 256;
        v[i] = xp[c] + yp[c];
        s += v[i];
    }
#pragma unroll
    for (int o = 16; o > 0; o >>= 1) s += __shfl_xor_sync(~0u, s, o);
    if ((tid & 31) == 0) sh[tid >> 5] = s;
    __syncthreads();
    s = 0.0f;
#pragma unroll
    for (int w = 0; w < 8; w++) s += sh[w];
    const float mean = s * (1.0f / EMB);

    float q = 0.0f;
#pragma unroll
    for (int i = 0; i < 3; i++) {
        float d = v[i] - mean;
        q += d * d;
    }
    __syncthreads();
#pragma unroll
    for (int o = 16; o > 0; o >>= 1) q += __shfl_xor_sync(~0u, q, o);
    if ((tid & 31) == 0) sh[tid >> 5] = q;
    __syncthreads();
    q = 0.0f;
#pragma unroll
    for (int w = 0; w < 8; w++) q += sh[w];
    const float rs = rsqrtf(q * (1.0f / EMB) + 1e-5f);

#pragma unroll
    for (int i = 0; i < 3; i++) {
        int c = tid + i * 256;
        float r = (v[i] - mean) * rs * g[c] + b[c];
        op[c] = r;
        if (QF && i == 0 && c < NQD)
            qf[row * NQD + c] = __float2bfloat16(__cosf(r + th[c]));
    }
}

// ---------------------------------------------------------------------------
// Merged converts. cvt_w_kernel: W1,W2 fp32->bf16. cvt_x_kernel: x,Wp ->tf32.
// ---------------------------------------------------------------------------
#define W1_BLKS ((FFD * NQD) / 1024)
#define W2_BLKS ((EMB * FFD) / 1024)
__global__ void __launch_bounds__(256) cvt_w_kernel(
    const float* __restrict__ w1, __nv_bfloat16* __restrict__ w1o,
    const float* __restrict__ w2, __nv_bfloat16* __restrict__ w2o) {
    const float* in;
    __nv_bfloat16* out;
    size_t i;
    if (blockIdx.x < W1_BLKS) {
        in = w1; out = w1o;
        i = (size_t)blockIdx.x * 256 + threadIdx.x;
    } else {
        in = w2; out = w2o;
        i = (size_t)(blockIdx.x - W1_BLKS) * 256 + threadIdx.x;
    }
    float4 v = *(const float4*)(in + i * 4);
    *(__nv_bfloat162*)(out + i * 4) = __float22bfloat162_rn(make_float2(v.x, v.y));
    *(__nv_bfloat162*)(out + i * 4 + 2) = __float22bfloat162_rn(make_float2(v.z, v.w));
}

#define X_BLKS ((NTOK * EMB) / 1024)
__global__ void __launch_bounds__(256) cvt_x_kernel(
    const float* __restrict__ x, float* __restrict__ xo,
    const float* __restrict__ wp, float* __restrict__ wpo) {
    const float* in;
    float* out;
    size_t i;
    if (blockIdx.x < X_BLKS) {
        in = x; out = xo;
        i = (size_t)blockIdx.x * 256 + threadIdx.x;
    } else {
        in = wp; out = wpo;
        i = (size_t)(blockIdx.x - X_BLKS) * 256 + threadIdx.x;
    }
    float4 v = *(const float4*)(in + i * 4);
    v.x = tf32r(v.x);
    v.y = tf32r(v.y);
    v.z = tf32r(v.z);
    v.w = tf32r(v.w);
    *(float4*)(out + i * 4) = v;
}

// ---------------------------------------------------------------------------
// Launch
// ---------------------------------------------------------------------------
extern "C" void kernel_launch(void* const* d_in, const int* in_sizes, int n_in,
                              void* d_out, int out_size) {
    const float* x     = (const float*)d_in[0];
    const float* Wp    = (const float*)d_in[1];
    const float* th_rx = (const float*)d_in[2];
    const float* th_ry = (const float*)d_in[3];
    const float* W1    = (const float*)d_in[4];
    const float* b1    = (const float*)d_in[5];
    const float* W2    = (const float*)d_in[6];
    const float* b2    = (const float*)d_in[7];
    const float* ln1g  = (const float*)d_in[8];
    const float* ln1b  = (const float*)d_in[9];
    const float* ln2g  = (const float*)d_in[10];
    const float* ln2b  = (const float*)d_in[11];
    float* out = (float*)d_out;

    float *qa, *sc, *x1, *tmp, *xr, *Wpr;
    __nv_bfloat16 *Pb, *qaTb, *qfb, *hb, *W1b, *W2b;
    cudaGetSymbolAddress((void**)&qa, g_qa);
    cudaGetSymbolAddress((void**)&sc, g_scores);
    cudaGetSymbolAddress((void**)&x1, g_x1);
    cudaGetSymbolAddress((void**)&tmp, g_tmp);
    cudaGetSymbolAddress((void**)&xr, g_xr);
    cudaGetSymbolAddress((void**)&Wpr, g_Wpr);
    cudaGetSymbolAddress((void**)&Pb, g_Pb);
    cudaGetSymbolAddress((void**)&qaTb, g_qaTb);
    cudaGetSymbolAddress((void**)&qfb, g_qfb);
    cudaGetSymbolAddress((void**)&hb, g_hb);
    cudaGetSymbolAddress((void**)&W1b, g_W1b);
    cudaGetSymbolAddress((void**)&W2b, g_W2b);

    cudaFuncSetAttribute(tgemm3_kernel<1, false>,
                         cudaFuncAttributeMaxDynamicSharedMemorySize, BG_SMEM);
    cudaFuncSetAttribute(tgemm3_kernel<2, true>,
                         cudaFuncAttributeMaxDynamicSharedMemorySize, BG_SMEM);
    cudaFuncSetAttribute(bgemm3_kernel<0, false>,
                         cudaFuncAttributeMaxDynamicSharedMemorySize, BG_SMEM);
    cudaFuncSetAttribute(bgemm3_kernel<3, true>,
                         cudaFuncAttributeMaxDynamicSharedMemorySize, BG_SMEM);
    cudaFuncSetAttribute(bgemm3_kernel<4, false>,
                         cudaFuncAttributeMaxDynamicSharedMemorySize, BG_SMEM);

    dim3 blk(256);
    dim3 blk512(512);

    // [0] x,Wp -> tf32-rounded
    cvt_x_kernel<<<X_BLKS + (EMB * EMB) / 1024, blk>>>(x, xr, Wp, Wpr);
    // [1] W1,W2 -> bf16
    cvt_w_kernel<<<W1_BLKS + W2_BLKS, blk>>>(W1, W1b, W2, W2b);

    // [2] qa = tf32r(cos(xr @ Wpr^T + theta_rx))
    tgemm3_kernel<1, false><<<dim3(EMB / 256, NTOK / 128, 1), blk512, BG_SMEM>>>(
        xr, Wpr, qa, NTOK, EMB, EMB, 0, 0, 0, th_rx, 0.0f);

    // [3] scores = qa @ qa^T / sqrt(8), SYMMETRIC (profiled slot)
    tgemm3_kernel<2, true><<<dim3(72, 1, BATCH), blk512, BG_SMEM>>>(
        qa, qa, sc, SEQ, SEQ, EMB,
        (size_t)SEQ * EMB, (size_t)SEQ * EMB, (size_t)SEQ * SEQ,
        nullptr, 0.35355339059327373f);

    // [4] qaTb[b][e][t] = bf16(qa[b][t][e])
    transpose_kernel<<<dim3(SEQ / 32, EMB / 32, BATCH), blk>>>(qa, qaTb);

    // [5] softmax rows -> bf16 P
    softmax2048_kernel<<<NTOK, blk>>>(sc, Pb);

    // [6] attn_out = P @ qa (bf16 v3), batched
    bgemm3_kernel<0, false><<<dim3(EMB / 256, SEQ / 128, BATCH), blk512, BG_SMEM>>>(
        Pb, qaTb, tmp, SEQ, EMB, SEQ,
        (size_t)SEQ * SEQ, (size_t)EMB * SEQ, (size_t)SEQ * EMB,
        nullptr, 0.0f);

    // [7] x1 = LN(x + attn_out), fused qf
    add_ln_kernel<true><<<NTOK, blk>>>(x, tmp, ln1g, ln1b, x1, th_ry, qfb);

    // [8] h = relu(qf @ W1^T + b1) -> bf16
    bgemm3_kernel<3, true><<<dim3(FFD / 256, NTOK / 128, 1), blk512, BG_SMEM>>>(
        qfb, W1b, hb, NTOK, FFD, NQD, 0, 0, 0, b1, 0.0f);

    // [9] ffn_out = h @ W2^T + b2
    bgemm3_kernel<4, false><<<dim3(EMB / 256, NTOK / 128, 1), blk512, BG_SMEM>>>(
        hb, W2b, tmp, NTOK, EMB, FFD, 0, 0, 0, b2, 0.0f);

    // [10] out = LN(x1 + ffn_out)
    add_ln_kernel<false><<<NTOK, blk>>>(x1, tmp, ln2g, ln2b, out, nullptr, nullptr);
}

// round 17
// speedup vs baseline: 5.9117x; 1.0022x over previous
#include <cuda_runtime.h>
#include <cuda_bf16.h>
#include <cstdint>
#include <math.h>

// Problem constants
#define NTOK 16384      // B*S
#define BATCH 8
#define SEQ 2048
#define EMB 768
#define FFD 3072
#define NQD 128

// ---------------------------------------------------------------------------
// Scratch (device globals; no allocation allowed)
// ---------------------------------------------------------------------------
__device__ float g_qa[(size_t)NTOK * EMB];
__device__ float g_scores[(size_t)BATCH * SEQ * SEQ];
__device__ float g_x1[(size_t)NTOK * EMB];
__device__ float g_tmp[(size_t)NTOK * EMB];
__device__ float g_xr[(size_t)NTOK * EMB];            // tf32-rounded x
__device__ float g_Wpr[(size_t)EMB * EMB];            // tf32-rounded Wp
__device__ __nv_bfloat16 g_Pb[(size_t)BATCH * SEQ * SEQ];
__device__ __nv_bfloat16 g_qaTb[(size_t)NTOK * EMB];
__device__ __nv_bfloat16 g_qfb[(size_t)NTOK * NQD];
__device__ __nv_bfloat16 g_hb[(size_t)NTOK * FFD];
__device__ __nv_bfloat16 g_W1b[(size_t)FFD * NQD];
__device__ __nv_bfloat16 g_W2b[(size_t)EMB * FFD];

// ---------------------------------------------------------------------------
// Helpers
// ---------------------------------------------------------------------------
__device__ __forceinline__ uint32_t smem_u32(const void* p) {
    uint32_t a;
    asm("{ .reg .u64 t; cvta.to.shared.u64 t, %1; cvt.u32.u64 %0, t; }"
        : "=r"(a) : "l"(p));
    return a;
}

__device__ __forceinline__ float tf32r(float f) {
    unsigned r;
    asm("cvt.rna.tf32.f32 %0, %1;" : "=r"(r) : "f"(f));
    return __uint_as_float(r);
}

__device__ __forceinline__ void mma8(float* c, const unsigned* a, const unsigned* b) {
    asm volatile(
        "mma.sync.aligned.m16n8k8.row.col.f32.tf32.tf32.f32 "
        "{%0,%1,%2,%3},{%4,%5,%6,%7},{%8,%9},{%0,%1,%2,%3};"
        : "+f"(c[0]), "+f"(c[1]), "+f"(c[2]), "+f"(c[3])
        : "r"(a[0]), "r"(a[1]), "r"(a[2]), "r"(a[3]), "r"(b[0]), "r"(b[1]));
}

__device__ __forceinline__ void mma16(float* c, const unsigned* a, const unsigned* b) {
    asm volatile(
        "mma.sync.aligned.m16n8k16.row.col.f32.bf16.bf16.f32 "
        "{%0,%1,%2,%3},{%4,%5,%6,%7},{%8,%9},{%0,%1,%2,%3};"
        : "+f"(c[0]), "+f"(c[1]), "+f"(c[2]), "+f"(c[3])
        : "r"(a[0]), "r"(a[1]), "r"(a[2]), "r"(a[3]), "r"(b[0]), "r"(b[1]));
}

__device__ __forceinline__ void cp16(uint32_t dst, const void* src) {
    asm volatile("cp.async.cg.shared.global [%0], [%1], 16;" :: "r"(dst), "l"(src));
}
#define CP_COMMIT() asm volatile("cp.async.commit_group;" ::: "memory")
#define CP_WAIT2()  asm volatile("cp.async.wait_group 2;" ::: "memory")

#define LDMX4(r, a) \
    asm volatile("ldmatrix.sync.aligned.m8n8.x4.shared.b16 {%0,%1,%2,%3}, [%4];" \
                 : "=r"((r)[0]), "=r"((r)[1]), "=r"((r)[2]), "=r"((r)[3]) : "r"(a))

// Epilogues: 0=none, 1=tf32r(cos(v+bias)), 2=v*scale, 3=relu(v+bias), 4=v+bias
template <int EPI>
__device__ __forceinline__ float epi_f(float v, const float* __restrict__ bias,
                                       int col, float scale) {
    if (EPI == 1) return tf32r(__cosf(v + bias[col]));
    if (EPI == 2) return v * scale;
    if (EPI == 3) return fmaxf(v + bias[col], 0.0f);
    if (EPI == 4) return v + bias[col];
    return v;
}

// Shared swizzle: 64B rows of 4x16B chunks, gray-code chunk rotation.
__device__ __forceinline__ uint32_t swz_off(int r, int c) {
    return (uint32_t)(r * 64 + ((c ^ ((r ^ (r >> 1)) & 3)) << 4));
}

#define BG_STAGE 24576
#define NSTAGE 4
#define BG_SMEM  (NSTAGE * BG_STAGE)

// ---------------------------------------------------------------------------
// TF32 GEMM v3: cp.async + ldmatrix(b16 view), fp32 K-major operands.
// C = A @ B^T. CTA 128x256, BK=16, 4-stage, 512 threads (16 warps 2x8),
// warp tile 64x32 -> 4 warps/SMSP. Operands pre-rounded to tf32.
// SYM: C symmetric (A==B); 72 lower tiles/batch, below-diag mirror scatter.
// ---------------------------------------------------------------------------
template <int EPI, bool SYM>
__global__ void __launch_bounds__(512, 1) tgemm3_kernel(
    const float* __restrict__ A, const float* __restrict__ B,
    float* __restrict__ C, int M, int N, int K,
    size_t sA, size_t sB, size_t sC,
    const float* __restrict__ bias, float scale) {
    extern __shared__ char smem[];
    const uint32_t sb = smem_u32(smem);

    A += (size_t)blockIdx.z * sA;
    B += (size_t)blockIdx.z * sB;
    C += (size_t)blockIdx.z * sC;

    int bm, bn, tt = 0;
    if (SYM) {
        int t = blockIdx.x, nx = 0;
        while (t >= 16 - 2 * nx) { t -= 16 - 2 * nx; nx++; }
        tt = t;
        bm = (2 * nx + t) * 128;
        bn = nx * 256;
    } else {
        bm = blockIdx.y * 128;
        bn = blockIdx.x * 256;
    }

    const int tid = threadIdx.x;
    const int lane = tid & 31;
    const int wid = tid >> 5;       // 0..15
    const int wm = wid >> 3;        // 0..1 (64 rows)
    const int wn = wid & 7;         // 0..7 (32 cols)
    const int niter = K >> 4;

    float acc[4][4][4] = {};

    auto load_stage = [&](int it, int st) {
        uint32_t base = sb + st * BG_STAGE;
        const float* Ag = A + (size_t)bm * K + it * 16;
        {
            int r = tid >> 2, c = tid & 3;   // 512 = 128 rows x 4 chunks
            cp16(base + swz_off(r, c), Ag + (size_t)r * K + c * 4);
        }
        const float* Bg = B + (size_t)bn * K + it * 16;
#pragma unroll
        for (int u = 0; u < 2; u++) {
            int q = u * 512 + tid;
            int r = q >> 2, c = q & 3;
            cp16(base + 8192 + swz_off(r, c), Bg + (size_t)r * K + c * 4);
        }
        CP_COMMIT();
    };

    auto compute = [&](int st) {
        uint32_t Ab = sb + st * BG_STAGE;
        uint32_t Bb = Ab + 8192;
#pragma unroll
        for (int s = 0; s < 2; s++) {  // two k8 blocks per BK=16
            unsigned af[4][4], bf[4][2];
#pragma unroll
            for (int mi = 0; mi < 4; mi++) {
                int row = wm * 64 + mi * 16 + ((lane >> 3) & 1) * 8 + (lane & 7);
                int c = s * 2 + (lane >> 4);
                LDMX4(af[mi], Ab + swz_off(row, c));
            }
#pragma unroll
            for (int p = 0; p < 2; p++) {
                int row = wn * 32 + p * 16 + ((lane >> 4) << 3) + (lane & 7);
                int c = s * 2 + ((lane >> 3) & 1);
                unsigned t[4];
                LDMX4(t, Bb + swz_off(row, c));
                bf[2 * p][0] = t[0];
                bf[2 * p][1] = t[1];
                bf[2 * p + 1][0] = t[2];
                bf[2 * p + 1][1] = t[3];
            }
#pragma unroll
            for (int mi = 0; mi < 4; mi++)
#pragma unroll
                for (int ni = 0; ni < 4; ni++)
                    mma8(acc[mi][ni], af[mi], bf[ni]);
        }
    };

#pragma unroll
    for (int i = 0; i < NSTAGE - 1; i++) {
        if (i < niter) load_stage(i, i);
        else CP_COMMIT();
    }

    int cur = 0;
    for (int it = 0; it < niter; it++) {
        CP_WAIT2();
        __syncthreads();
        compute(cur);
        if (it + NSTAGE - 1 < niter) {
            int nst = cur + NSTAGE - 1;
            if (nst >= NSTAGE) nst -= NSTAGE;
            load_stage(it + NSTAGE - 1, nst);
        } else {
            CP_COMMIT();
        }
        cur = (cur == NSTAGE - 1) ? 0 : cur + 1;
    }

    const int g = lane >> 2;
    const int tg = lane & 3;
#pragma unroll
    for (int mi = 0; mi < 4; ++mi) {
        int row = bm + wm * 64 + mi * 16 + g;
#pragma unroll
        for (int ni = 0; ni < 4; ++ni) {
            int col = bn + wn * 32 + ni * 8 + tg * 2;
            const float* a = acc[mi][ni];
            float e0 = epi_f<EPI>(a[0], bias, col + 0, scale);
            float e1 = epi_f<EPI>(a[1], bias, col + 1, scale);
            float e2 = epi_f<EPI>(a[2], bias, col + 0, scale);
            float e3 = epi_f<EPI>(a[3], bias, col + 1, scale);
            *(float2*)(C + (size_t)row * N + col) = make_float2(e0, e1);
            *(float2*)(C + (size_t)(row + 8) * N + col) = make_float2(e2, e3);
            if (SYM && tt >= 2) {
                C[(size_t)(col + 0) * N + row] = e0;
                C[(size_t)(col + 1) * N + row] = e1;
                C[(size_t)(col + 0) * N + row + 8] = e2;
                C[(size_t)(col + 1) * N + row + 8] = e3;
            }
        }
    }
}

// ---------------------------------------------------------------------------
// BF16 GEMM v3: cp.async + ldmatrix, bf16 gmem operands (K-major both).
// CTA 128x256, BK=32, 4-stage pipeline, 512 threads (16 warps, 2x8),
// warp tile 64x32. acc 64 regs/thread.
// ---------------------------------------------------------------------------
template <int EPI, bool OUTBF>
__global__ void __launch_bounds__(512, 1) bgemm3_kernel(
    const __nv_bfloat16* __restrict__ A, const __nv_bfloat16* __restrict__ B,
    void* __restrict__ Cv, int M, int N, int K,
    size_t sA, size_t sB, size_t sC,
    const float* __restrict__ bias, float scale) {
    extern __shared__ char smem[];
    const uint32_t sb = smem_u32(smem);

    A += (size_t)blockIdx.z * sA;
    B += (size_t)blockIdx.z * sB;

    const int bm = blockIdx.y * 128;
    const int bn = blockIdx.x * 256;
    const int tid = threadIdx.x;
    const int lane = tid & 31;
    const int wid = tid >> 5;       // 0..15
    const int wm = wid >> 3;        // 0..1 (64 rows)
    const int wn = wid & 7;         // 0..7 (32 cols)
    const int niter = K >> 5;

    float acc[4][4][4] = {};

    auto load_stage = [&](int it, int st) {
        uint32_t base = sb + st * BG_STAGE;
        const __nv_bfloat16* Ag = A + (size_t)bm * K + it * 32;
        {
            int r = tid >> 2, c = tid & 3;
            cp16(base + swz_off(r, c), Ag + (size_t)r * K + c * 8);
        }
        const __nv_bfloat16* Bg = B + (size_t)bn * K + it * 32;
#pragma unroll
        for (int u = 0; u < 2; u++) {
            int q = u * 512 + tid;
            int r = q >> 2, c = q & 3;
            cp16(base + 8192 + swz_off(r, c), Bg + (size_t)r * K + c * 8);
        }
        CP_COMMIT();
    };

    auto compute = [&](int st) {
        uint32_t Ab = sb + st * BG_STAGE;
        uint32_t Bb = Ab + 8192;
#pragma unroll
        for (int s = 0; s < 2; s++) {
            unsigned af[4][4], bf[4][2];
#pragma unroll
            for (int mi = 0; mi < 4; mi++) {
                int row = wm * 64 + mi * 16 + ((lane >> 3) & 1) * 8 + (lane & 7);
                int c = s * 2 + (lane >> 4);
                LDMX4(af[mi], Ab + swz_off(row, c));
            }
#pragma unroll
            for (int p = 0; p < 2; p++) {
                int row = wn * 32 + p * 16 + ((lane >> 4) << 3) + (lane & 7);
                int c = s * 2 + ((lane >> 3) & 1);
                unsigned t[4];
                LDMX4(t, Bb + swz_off(row, c));
                bf[2 * p][0] = t[0];
                bf[2 * p][1] = t[1];
                bf[2 * p + 1][0] = t[2];
                bf[2 * p + 1][1] = t[3];
            }
#pragma unroll
            for (int mi = 0; mi < 4; mi++)
#pragma unroll
                for (int ni = 0; ni < 4; ni++)
                    mma16(acc[mi][ni], af[mi], bf[ni]);
        }
    };

#pragma unroll
    for (int i = 0; i < NSTAGE - 1; i++) {
        if (i < niter) load_stage(i, i);
        else CP_COMMIT();
    }

    int cur = 0;
    for (int it = 0; it < niter; it++) {
        CP_WAIT2();
        __syncthreads();
        compute(cur);
        if (it + NSTAGE - 1 < niter) {
            int nst = cur + NSTAGE - 1;
            if (nst >= NSTAGE) nst -= NSTAGE;
            load_stage(it + NSTAGE - 1, nst);
        } else {
            CP_COMMIT();
        }
        cur = (cur == NSTAGE - 1) ? 0 : cur + 1;
    }

    const int g = lane >> 2;
    const int tg = lane & 3;
#pragma unroll
    for (int mi = 0; mi < 4; ++mi) {
        int row = bm + wm * 64 + mi * 16 + g;
#pragma unroll
        for (int ni = 0; ni < 4; ++ni) {
            int col = bn + wn * 32 + ni * 8 + tg * 2;
            const float* a = acc[mi][ni];
            float e0 = epi_f<EPI>(a[0], bias, col + 0, scale);
            float e1 = epi_f<EPI>(a[1], bias, col + 1, scale);
            float e2 = epi_f<EPI>(a[2], bias, col + 0, scale);
            float e3 = epi_f<EPI>(a[3], bias, col + 1, scale);
            if (OUTBF) {
                __nv_bfloat16* C = (__nv_bfloat16*)Cv + (size_t)blockIdx.z * sC;
                *(__nv_bfloat162*)(C + (size_t)row * N + col) =
                    __float22bfloat162_rn(make_float2(e0, e1));
                *(__nv_bfloat162*)(C + (size_t)(row + 8) * N + col) =
                    __float22bfloat162_rn(make_float2(e2, e3));
            } else {
                float* C = (float*)Cv + (size_t)blockIdx.z * sC;
                *(float2*)(C + (size_t)row * N + col) = make_float2(e0, e1);
                *(float2*)(C + (size_t)(row + 8) * N + col) = make_float2(e2, e3);
            }
        }
    }
}

// ---------------------------------------------------------------------------
// 32x32 tiled transpose per batch, bf16 out: out[b][e][t] = bf16(in[b][t][e])
// ---------------------------------------------------------------------------
__global__ void __launch_bounds__(256) transpose_kernel(
    const float* __restrict__ in, __nv_bfloat16* __restrict__ out) {
    __shared__ float t[32][33];
    const int b = blockIdx.z;
    const int t0 = blockIdx.x * 32;
    const int e0 = blockIdx.y * 32;
    const int lx = threadIdx.x & 31, ly = threadIdx.x >> 5;
#pragma unroll
    for (int r = 0; r < 32; r += 8)
        t[ly + r][lx] = in[((size_t)b * SEQ + t0 + ly + r) * EMB + e0 + lx];
    __syncthreads();
#pragma unroll
    for (int r = 0; r < 32; r += 8)
        out[((size_t)b * EMB + e0 + ly + r) * SEQ + t0 + lx] =
            __float2bfloat16(t[lx][ly + r]);
}

// ---------------------------------------------------------------------------
// Row softmax (reads fp32 scores, writes bf16 P), row length 2048.
// ---------------------------------------------------------------------------
__global__ void __launch_bounds__(256) softmax2048_kernel(
    const float* __restrict__ S, __nv_bfloat16* __restrict__ P) {
    const float* p = S + (size_t)blockIdx.x * SEQ;
    __nv_bfloat16* o = P + (size_t)blockIdx.x * SEQ;
    const int tid = threadIdx.x;
    __shared__ float sh[8];

    float v[8];
    float m = -1e30f;
#pragma unroll
    for (int i = 0; i < 8; i++) {
        v[i] = p[tid + i * 256];
        m = fmaxf(m, v[i]);
    }
#pragma unroll
    for (int o2 = 16; o2 > 0; o2 >>= 1) m = fmaxf(m, __shfl_xor_sync(~0u, m, o2));
    if ((tid & 31) == 0) sh[tid >> 5] = m;
    __syncthreads();
    m = sh[0];
#pragma unroll
    for (int w = 1; w < 8; w++) m = fmaxf(m, sh[w]);

    float s = 0.0f;
#pragma unroll
    for (int i = 0; i < 8; i++) {
        v[i] = __expf(v[i] - m);
        s += v[i];
    }
    __syncthreads();
#pragma unroll
    for (int o2 = 16; o2 > 0; o2 >>= 1) s += __shfl_xor_sync(~0u, s, o2);
    if ((tid & 31) == 0) sh[tid >> 5] = s;
    __syncthreads();
    s = 0.0f;
#pragma unroll
    for (int w = 0; w < 8; w++) s += sh[w];
    float inv = 1.0f / s;
#pragma unroll
    for (int i = 0; i < 8; i++) o[tid + i * 256] = __float2bfloat16(v[i] * inv);
}

// ---------------------------------------------------------------------------
// out = LayerNorm(X + Y) * g + b, row length 768; optionally fused qf output.
// ---------------------------------------------------------------------------
template <bool QF>
__global__ void __launch_bounds__(256) add_ln_kernel(
    const float* __restrict__ X, const float* __restrict__ Y,
    const float* __restrict__ g, const float* __restrict__ b,
    float* __restrict__ out, const float* __restrict__ th,
    __nv_bfloat16* __restrict__ qf) {
    const size_t row = blockIdx.x;
    const float* xp = X + row * EMB;
    const float* yp = Y + row * EMB;
    float* op = out + row * EMB;
    const int tid = threadIdx.x;
    __shared__ float sh[8];

    float v[3];
    float s = 0.0f;
#pragma unroll
    for (int i = 0; i < 3; i++) {
        int c = tid + i * 256;
        v[i] = xp[c] + yp[c];
        s += v[i];
    }
#pragma unroll
    for (int o = 16; o > 0; o >>= 1) s += __shfl_xor_sync(~0u, s, o);
    if ((tid & 31) == 0) sh[tid >> 5] = s;
    __syncthreads();
    s = 0.0f;
#pragma unroll
    for (int w = 0; w < 8; w++) s += sh[w];
    const float mean = s * (1.0f / EMB);

    float q = 0.0f;
#pragma unroll
    for (int i = 0; i < 3; i++) {
        float d = v[i] - mean;
        q += d * d;
    }
    __syncthreads();
#pragma unroll
    for (int o = 16; o > 0; o >>= 1) q += __shfl_xor_sync(~0u, q, o);
    if ((tid & 31) == 0) sh[tid >> 5] = q;
    __syncthreads();
    q = 0.0f;
#pragma unroll
    for (int w = 0; w < 8; w++) q += sh[w];
    const float rs = rsqrtf(q * (1.0f / EMB) + 1e-5f);

#pragma unroll
    for (int i = 0; i < 3; i++) {
        int c = tid + i * 256;
        float r = (v[i] - mean) * rs * g[c] + b[c];
        op[c] = r;
        if (QF && i == 0 && c < NQD)
            qf[row * NQD + c] = __float2bfloat16(__cosf(r + th[c]));
    }
}

// ---------------------------------------------------------------------------
// Merged converts. cvt_w_kernel: W1,W2 fp32->bf16. cvt_x_kernel: x,Wp ->tf32.
// ---------------------------------------------------------------------------
#define W1_BLKS ((FFD * NQD) / 1024)
#define W2_BLKS ((EMB * FFD) / 1024)
__global__ void __launch_bounds__(256) cvt_w_kernel(
    const float* __restrict__ w1, __nv_bfloat16* __restrict__ w1o,
    const float* __restrict__ w2, __nv_bfloat16* __restrict__ w2o) {
    const float* in;
    __nv_bfloat16* out;
    size_t i;
    if (blockIdx.x < W1_BLKS) {
        in = w1; out = w1o;
        i = (size_t)blockIdx.x * 256 + threadIdx.x;
    } else {
        in = w2; out = w2o;
        i = (size_t)(blockIdx.x - W1_BLKS) * 256 + threadIdx.x;
    }
    float4 v = *(const float4*)(in + i * 4);
    *(__nv_bfloat162*)(out + i * 4) = __float22bfloat162_rn(make_float2(v.x, v.y));
    *(__nv_bfloat162*)(out + i * 4 + 2) = __float22bfloat162_rn(make_float2(v.z, v.w));
}

#define X_BLKS ((NTOK * EMB) / 1024)
__global__ void __launch_bounds__(256) cvt_x_kernel(
    const float* __restrict__ x, float* __restrict__ xo,
    const float* __restrict__ wp, float* __restrict__ wpo) {
    const float* in;
    float* out;
    size_t i;
    if (blockIdx.x < X_BLKS) {
        in = x; out = xo;
        i = (size_t)blockIdx.x * 256 + threadIdx.x;
    } else {
        in = wp; out = wpo;
        i = (size_t)(blockIdx.x - X_BLKS) * 256 + threadIdx.x;
    }
    float4 v = *(const float4*)(in + i * 4);
    v.x = tf32r(v.x);
    v.y = tf32r(v.y);
    v.z = tf32r(v.z);
    v.w = tf32r(v.w);
    *(float4*)(out + i * 4) = v;
}

// ---------------------------------------------------------------------------
// Launch
// ---------------------------------------------------------------------------
extern "C" void kernel_launch(void* const* d_in, const int* in_sizes, int n_in,
                              void* d_out, int out_size) {
    const float* x     = (const float*)d_in[0];
    const float* Wp    = (const float*)d_in[1];
    const float* th_rx = (const float*)d_in[2];
    const float* th_ry = (const float*)d_in[3];
    const float* W1    = (const float*)d_in[4];
    const float* b1    = (const float*)d_in[5];
    const float* W2    = (const float*)d_in[6];
    const float* b2    = (const float*)d_in[7];
    const float* ln1g  = (const float*)d_in[8];
    const float* ln1b  = (const float*)d_in[9];
    const float* ln2g  = (const float*)d_in[10];
    const float* ln2b  = (const float*)d_in[11];
    float* out = (float*)d_out;

    float *qa, *sc, *x1, *tmp, *xr, *Wpr;
    __nv_bfloat16 *Pb, *qaTb, *qfb, *hb, *W1b, *W2b;
    cudaGetSymbolAddress((void**)&qa, g_qa);
    cudaGetSymbolAddress((void**)&sc, g_scores);
    cudaGetSymbolAddress((void**)&x1, g_x1);
    cudaGetSymbolAddress((void**)&tmp, g_tmp);
    cudaGetSymbolAddress((void**)&xr, g_xr);
    cudaGetSymbolAddress((void**)&Wpr, g_Wpr);
    cudaGetSymbolAddress((void**)&Pb, g_Pb);
    cudaGetSymbolAddress((void**)&qaTb, g_qaTb);
    cudaGetSymbolAddress((void**)&qfb, g_qfb);
    cudaGetSymbolAddress((void**)&hb, g_hb);
    cudaGetSymbolAddress((void**)&W1b, g_W1b);
    cudaGetSymbolAddress((void**)&W2b, g_W2b);

    cudaFuncSetAttribute(tgemm3_kernel<1, false>,
                         cudaFuncAttributeMaxDynamicSharedMemorySize, BG_SMEM);
    cudaFuncSetAttribute(tgemm3_kernel<2, true>,
                         cudaFuncAttributeMaxDynamicSharedMemorySize, BG_SMEM);
    cudaFuncSetAttribute(bgemm3_kernel<0, false>,
                         cudaFuncAttributeMaxDynamicSharedMemorySize, BG_SMEM);
    cudaFuncSetAttribute(bgemm3_kernel<3, true>,
                         cudaFuncAttributeMaxDynamicSharedMemorySize, BG_SMEM);
    cudaFuncSetAttribute(bgemm3_kernel<4, false>,
                         cudaFuncAttributeMaxDynamicSharedMemorySize, BG_SMEM);

    dim3 blk(256);
    dim3 blk512(512);

    // [0] x,Wp -> tf32-rounded
    cvt_x_kernel<<<X_BLKS + (EMB * EMB) / 1024, blk>>>(x, xr, Wp, Wpr);
    // [1] W1,W2 -> bf16
    cvt_w_kernel<<<W1_BLKS + W2_BLKS, blk>>>(W1, W1b, W2, W2b);

    // [2] qa = tf32r(cos(xr @ Wpr^T + theta_rx))
    tgemm3_kernel<1, false><<<dim3(EMB / 256, NTOK / 128, 1), blk512, BG_SMEM>>>(
        xr, Wpr, qa, NTOK, EMB, EMB, 0, 0, 0, th_rx, 0.0f);

    // [3] scores = qa @ qa^T / sqrt(8), SYMMETRIC (profiled slot)
    tgemm3_kernel<2, true><<<dim3(72, 1, BATCH), blk512, BG_SMEM>>>(
        qa, qa, sc, SEQ, SEQ, EMB,
        (size_t)SEQ * EMB, (size_t)SEQ * EMB, (size_t)SEQ * SEQ,
        nullptr, 0.35355339059327373f);

    // [4] qaTb[b][e][t] = bf16(qa[b][t][e])
    transpose_kernel<<<dim3(SEQ / 32, EMB / 32, BATCH), blk>>>(qa, qaTb);

    // [5] softmax rows -> bf16 P
    softmax2048_kernel<<<NTOK, blk>>>(sc, Pb);

    // [6] attn_out = P @ qa (bf16 v3), batched
    bgemm3_kernel<0, false><<<dim3(EMB / 256, SEQ / 128, BATCH), blk512, BG_SMEM>>>(
        Pb, qaTb, tmp, SEQ, EMB, SEQ,
        (size_t)SEQ * SEQ, (size_t)EMB * SEQ, (size_t)SEQ * EMB,
        nullptr, 0.0f);

    // [7] x1 = LN(x + attn_out), fused qf
    add_ln_kernel<true><<<NTOK, blk>>>(x, tmp, ln1g, ln1b, x1, th_ry, qfb);

    // [8] h = relu(qf @ W1^T + b1) -> bf16
    bgemm3_kernel<3, true><<<dim3(FFD / 256, NTOK / 128, 1), blk512, BG_SMEM>>>(
        qfb, W1b, hb, NTOK, FFD, NQD, 0, 0, 0, b1, 0.0f);

    // [9] ffn_out = h @ W2^T + b2
    bgemm3_kernel<4, false><<<dim3(EMB / 256, NTOK / 128, 1), blk512, BG_SMEM>>>(
        hb, W2b, tmp, NTOK, EMB, FFD, 0, 0, 0, b2, 0.0f);

    // [10] out = LN(x1 + ffn_out)
    add_ln_kernel<false><<<NTOK, blk>>>(x1, tmp, ln2g, ln2b, out, nullptr, nullptr);
}